// round 4
// baseline (speedup 1.0000x reference)
#include <cuda_runtime.h>
#include <cuda_fp16.h>
#include <mma.h>

using namespace nvcuda;

// ---------------- problem constants ----------------
#define BB   16
#define SS   512
#define HH   768
#define NH_  12
#define DD   64
#define FF_  3072
#define LL   4
#define MR   (BB*SS)          // 8192 rows
#define SCALE_Q 0.125f        // D^-0.5
#define LN_EPS 1e-5f

#define HHxHH   (HH*HH)       // 589824
#define HHxFF   (HH*FF_)      // 2359296

// ---------------- scratch (__device__ globals; no cudaMalloc allowed) ----------------
__device__ __align__(16) float  g_h[(size_t)MR*HH];          // fp32 residual stream
__device__ __align__(16) __half g_y[(size_t)MR*HH];          // LN output (fp16)
__device__ __align__(16) __half g_q[(size_t)MR*HH];          // [B,NH,S,D]
__device__ __align__(16) __half g_k[(size_t)MR*HH];          // K^T: [B,NH,D,S]
__device__ __align__(16) __half g_v[(size_t)MR*HH];          // [B,NH,S,D]
__device__ __align__(16) __half g_attn[(size_t)MR*HH];       // attn out, [B,S,H]
__device__ __align__(16) float  g_scores[(size_t)BB*NH_*SS*SS];
__device__ __align__(16) __half g_probs [(size_t)BB*NH_*SS*SS];
__device__ __align__(16) __half g_ff[(size_t)MR*FF_];
__device__ __align__(16) __half g_w16[(size_t)LL*(4*HHxHH + 2*HHxFF)];

#define OFF_WQ  ((size_t)0)
#define OFF_WK  ((size_t)LL*HHxHH)
#define OFF_WV  ((size_t)2*LL*HHxHH)
#define OFF_WO  ((size_t)3*LL*HHxHH)
#define OFF_W1  ((size_t)4*LL*HHxHH)
#define OFF_W2  ((size_t)4*LL*HHxHH + (size_t)LL*HHxFF)

// ---------------- small utility kernels ----------------
__global__ void copy_f4_kernel(const float* __restrict__ src, float* __restrict__ dst, int n4) {
    int i = blockIdx.x * blockDim.x + threadIdx.x;
    if (i < n4) reinterpret_cast<float4*>(dst)[i] = reinterpret_cast<const float4*>(src)[i];
}

__global__ void conv_f2h_kernel(const float* __restrict__ src, __half* __restrict__ dst, int n2) {
    int i = blockIdx.x * blockDim.x + threadIdx.x;
    if (i < n2) {
        float2 f = reinterpret_cast<const float2*>(src)[i];
        reinterpret_cast<__half2*>(dst)[i] = __floats2half2_rn(f.x, f.y);
    }
}

// ---------------- LayerNorm ----------------
__global__ __launch_bounds__(256) void ln_kernel(
    const float* __restrict__ in, const float* __restrict__ g, const float* __restrict__ b,
    __half* __restrict__ outH, float* __restrict__ outF)
{
    const int row = blockIdx.x;
    const float* x = in + (size_t)row * HH;
    const int t = threadIdx.x;

    float v[3], s = 0.f, s2 = 0.f;
#pragma unroll
    for (int i = 0; i < 3; i++) {
        float xv = x[t + i * 256];
        v[i] = xv; s += xv; s2 += xv * xv;
    }
#pragma unroll
    for (int o = 16; o; o >>= 1) {
        s  += __shfl_xor_sync(0xffffffffu, s,  o);
        s2 += __shfl_xor_sync(0xffffffffu, s2, o);
    }
    __shared__ float r1[8], r2[8];
    __shared__ float mean_s, rstd_s;
    if ((t & 31) == 0) { r1[t >> 5] = s; r2[t >> 5] = s2; }
    __syncthreads();
    if (t == 0) {
        float ss = 0.f, ss2 = 0.f;
#pragma unroll
        for (int i = 0; i < 8; i++) { ss += r1[i]; ss2 += r2[i]; }
        float mean = ss * (1.f / HH);
        float var  = ss2 * (1.f / HH) - mean * mean;
        mean_s = mean;
        rstd_s = rsqrtf(var + LN_EPS);
    }
    __syncthreads();
    const float mean = mean_s, rstd = rstd_s;
#pragma unroll
    for (int i = 0; i < 3; i++) {
        int idx = t + i * 256;
        float o = (v[i] - mean) * rstd * g[idx] + b[idx];
        if (outH) outH[(size_t)row * HH + idx] = __float2half_rn(o);
        else      outF[(size_t)row * HH + idx] = o;
    }
}

// ---------------- softmax over rows of 512 ----------------
__global__ __launch_bounds__(256) void softmax_kernel(
    const float* __restrict__ sc, __half* __restrict__ pr)
{
    const size_t row = blockIdx.x;
    const float* x = sc + row * SS;
    __half* p = pr + row * SS;
    const int t = threadIdx.x;

    float a0 = x[t], a1 = x[t + 256];
    float m = fmaxf(a0, a1);
#pragma unroll
    for (int o = 16; o; o >>= 1) m = fmaxf(m, __shfl_xor_sync(0xffffffffu, m, o));
    __shared__ float rm[8];
    __shared__ float rowmax_s, rowsum_s;
    if ((t & 31) == 0) rm[t >> 5] = m;
    __syncthreads();
    if (t == 0) {
        float mm = rm[0];
#pragma unroll
        for (int i = 1; i < 8; i++) mm = fmaxf(mm, rm[i]);
        rowmax_s = mm;
    }
    __syncthreads();
    const float mx = rowmax_s;
    float e0 = __expf(a0 - mx), e1 = __expf(a1 - mx);
    float s = e0 + e1;
#pragma unroll
    for (int o = 16; o; o >>= 1) s += __shfl_xor_sync(0xffffffffu, s, o);
    __syncthreads();
    if ((t & 31) == 0) rm[t >> 5] = s;
    __syncthreads();
    if (t == 0) {
        float ssum = 0.f;
#pragma unroll
        for (int i = 0; i < 8; i++) ssum += rm[i];
        rowsum_s = ssum;
    }
    __syncthreads();
    const float inv = 1.f / rowsum_s;
    p[t]       = __float2half_rn(e0 * inv);
    p[t + 256] = __float2half_rn(e1 * inv);
}

// ---------------- cp.async helpers ----------------
__device__ __forceinline__ void cp16(void* smem, const void* gmem) {
    unsigned sa = (unsigned)__cvta_generic_to_shared(smem);
    asm volatile("cp.async.cg.shared.global [%0], [%1], 16;\n" :: "r"(sa), "l"(gmem));
}
__device__ __forceinline__ void cp_commit() { asm volatile("cp.async.commit_group;\n"); }

// ---------------- pipelined wmma GEMM: BM=128, BN in {128,64}, BK=32 ----------------
// All matrices fp16 row-major. A: [M,K] lda=K. B: [K,N] ldb given.
// Epilogues (per element acc at (gi,gj), batch z):
//  0 QKV : outH[((b*NH+h)*S+s)*D+d] = (acc + bias[gj]) * oscale     (gi->(b,s), gj->(h,d))
//  5 KT  : outH[((b*NH+h)*D+d)*S+s] = acc + bias[gj]
//  1 SCR : outF[z*S*S + gi*S + gj] = acc + bias[z*S*S+gi*S+gj]
//  2 PV  : outH[(b*S+gi)*H + h*D + gj] = acc ,  z=b*NH+h
//  3 RES : outF[gi*N + gj] += acc + bias[gj]
//  4 GEL : outH[gi*N + gj] = gelu(acc + bias[gj])
template<int BN, int EPI>
__global__ __launch_bounds__(256) void gemm2_kernel(
    const __half* __restrict__ Ag, const __half* __restrict__ Bg,
    const float* __restrict__ bias,
    float* __restrict__ outF, __half* __restrict__ outH,
    int N, int K, int ldb, long sA, long sB, float oscale)
{
    constexpr int SA  = 40;                 // A smem stride (halves), mult of 8
    constexpr int SB  = BN + 8;             // B smem stride, mult of 8
    constexpr int WGN = (BN == 128) ? 4 : 2;   // warps along N
    constexpr int WTM = (BN == 128) ? 64 : 32; // warp tile M
    constexpr int WTN = 32;                    // warp tile N
    constexpr int FM  = WTM / 16;
    constexpr int FN  = WTN / 16;

    __shared__ __align__(16) __half As[2][128 * SA];
    __shared__ __align__(16) __half Bs[2][32 * SB];
    __shared__ __align__(16) float  stg[8][16 * 20];

    const int z  = blockIdx.z;
    const __half* A  = Ag + (size_t)z * sA + (size_t)blockIdx.y * 128 * K;
    const __half* Bb = Bg + (size_t)z * sB;
    const int n0 = blockIdx.x * BN;

    const int t    = threadIdx.x;
    const int w    = t >> 5;
    const int lane = t & 31;
    const int wm   = w / WGN, wn = w % WGN;

    wmma::fragment<wmma::accumulator, 16, 16, 16, float> c[FM][FN];
#pragma unroll
    for (int i = 0; i < FM; i++)
#pragma unroll
        for (int j = 0; j < FN; j++) wmma::fill_fragment(c[i][j], 0.f);

    // tile loaders (all shapes divide evenly; no guards)
    auto load_tiles = [&](int s, int k0) {
#pragma unroll
        for (int i = 0; i < 2; i++) {               // A: 128x32 = 512 uint4
            int idx = t + i * 256;
            int row = idx >> 2, ch = (idx & 3) * 8;
            cp16(&As[s][row * SA + ch], A + (size_t)row * K + k0 + ch);
        }
        if (BN == 128) {
#pragma unroll
            for (int i = 0; i < 2; i++) {           // B: 32x128 = 512 uint4
                int idx = t + i * 256;
                int row = idx >> 4, ch = (idx & 15) * 8;
                cp16(&Bs[s][row * SB + ch], Bb + (size_t)(k0 + row) * ldb + n0 + ch);
            }
        } else {                                    // B: 32x64 = 256 uint4
            int row = t >> 3, ch = (t & 7) * 8;
            cp16(&Bs[s][row * SB + ch], Bb + (size_t)(k0 + row) * ldb + n0 + ch);
        }
    };

    const int nk = K >> 5;
    load_tiles(0, 0);
    cp_commit();

    int s = 0;
    for (int kt = 0; kt < nk; kt++) {
        if (kt + 1 < nk) {
            load_tiles(s ^ 1, (kt + 1) * 32);
            cp_commit();
            asm volatile("cp.async.wait_group 1;\n");
        } else {
            asm volatile("cp.async.wait_group 0;\n");
        }
        __syncthreads();

#pragma unroll
        for (int ks = 0; ks < 2; ks++) {
            wmma::fragment<wmma::matrix_b, 16, 16, 16, __half, wmma::row_major> bf[FN];
#pragma unroll
            for (int j = 0; j < FN; j++)
                wmma::load_matrix_sync(bf[j], &Bs[s][ks * 16 * SB + wn * WTN + j * 16], SB);
#pragma unroll
            for (int i = 0; i < FM; i++) {
                wmma::fragment<wmma::matrix_a, 16, 16, 16, __half, wmma::row_major> af;
                wmma::load_matrix_sync(af, &As[s][(wm * WTM + i * 16) * SA + ks * 16], SA);
#pragma unroll
                for (int j = 0; j < FN; j++)
                    wmma::mma_sync(c[i][j], af, bf[j], c[i][j]);
            }
        }
        __syncthreads();
        s ^= 1;
    }

    // ---- epilogue: per-warp 16x16 staging ----
    const int gi0 = blockIdx.y * 128 + wm * WTM;
    const int gj0 = n0 + wn * WTN;
    float* st = stg[w];
    const int r  = lane >> 1;
    const int c0 = (lane & 1) * 8;

#pragma unroll
    for (int i = 0; i < FM; i++) {
#pragma unroll
        for (int j = 0; j < FN; j++) {
            wmma::store_matrix_sync(st, c[i][j], 20, wmma::mem_row_major);
            __syncwarp();
            const int gi = gi0 + i * 16 + r;
#pragma unroll
            for (int cc = 0; cc < 8; cc++) {
                const int gj = gj0 + j * 16 + c0 + cc;
                float acc = st[r * 20 + c0 + cc];

                if (EPI == 0) {
                    float val = (acc + bias[gj]) * oscale;
                    int bb = gi >> 9, ss = gi & 511, hh = gj >> 6, dd = gj & 63;
                    outH[(((size_t)(bb * NH_ + hh) * SS + ss) << 6) + dd] = __float2half_rn(val);
                } else if (EPI == 5) {
                    float val = acc + bias[gj];
                    int bb = gi >> 9, ss = gi & 511, hh = gj >> 6, dd = gj & 63;
                    outH[((size_t)(bb * NH_ + hh) * DD + dd) * SS + ss] = __float2half_rn(val);
                } else if (EPI == 1) {
                    size_t idx = (size_t)z * SS * SS + (size_t)gi * SS + gj;
                    outF[idx] = acc + bias[idx];
                } else if (EPI == 2) {
                    int bb = z / NH_, hh = z - bb * NH_;
                    outH[((size_t)(bb * SS + gi)) * HH + hh * DD + gj] = __float2half_rn(acc);
                } else if (EPI == 3) {
                    size_t idx = (size_t)gi * N + gj;
                    outF[idx] += acc + bias[gj];
                } else { // EPI == 4 exact gelu
                    float xv = acc + bias[gj];
                    float gl = 0.5f * xv * (1.f + erff(xv * 0.70710678118654752f));
                    outH[(size_t)gi * N + gj] = __float2half_rn(gl);
                }
            }
            __syncwarp();
        }
    }
}

// ---------------- host ----------------
extern "C" void kernel_launch(void* const* d_in, const int* in_sizes, int n_in,
                              void* d_out, int out_size)
{
    const float* x         = (const float*)d_in[0];
    const float* attn_bias = (const float*)d_in[1];
    const float* ln1_g = (const float*)d_in[2];
    const float* ln1_b = (const float*)d_in[3];
    const float* wq = (const float*)d_in[4];
    const float* bq = (const float*)d_in[5];
    const float* wk = (const float*)d_in[6];
    const float* bk = (const float*)d_in[7];
    const float* wv = (const float*)d_in[8];
    const float* bv = (const float*)d_in[9];
    const float* wo = (const float*)d_in[10];
    const float* bo = (const float*)d_in[11];
    const float* ln2_g = (const float*)d_in[12];
    const float* ln2_b = (const float*)d_in[13];
    const float* w1 = (const float*)d_in[14];
    const float* b1 = (const float*)d_in[15];
    const float* w2 = (const float*)d_in[16];
    const float* b2 = (const float*)d_in[17];
    const float* fln_g = (const float*)d_in[18];
    const float* fln_b = (const float*)d_in[19];
    float* out = (float*)d_out;

    void* pv_ = nullptr;
    cudaGetSymbolAddress(&pv_, g_h);      float*  p_h    = (float*)pv_;
    cudaGetSymbolAddress(&pv_, g_y);      __half* p_y    = (__half*)pv_;
    cudaGetSymbolAddress(&pv_, g_q);      __half* p_q    = (__half*)pv_;
    cudaGetSymbolAddress(&pv_, g_k);      __half* p_kT   = (__half*)pv_;
    cudaGetSymbolAddress(&pv_, g_v);      __half* p_v    = (__half*)pv_;
    cudaGetSymbolAddress(&pv_, g_attn);   __half* p_attn = (__half*)pv_;
    cudaGetSymbolAddress(&pv_, g_scores); float*  p_sc   = (float*)pv_;
    cudaGetSymbolAddress(&pv_, g_probs);  __half* p_pr   = (__half*)pv_;
    cudaGetSymbolAddress(&pv_, g_ff);     __half* p_ff   = (__half*)pv_;
    cudaGetSymbolAddress(&pv_, g_w16);    __half* p_w16  = (__half*)pv_;

    __half* wq16 = p_w16 + OFF_WQ;
    __half* wk16 = p_w16 + OFF_WK;
    __half* wv16 = p_w16 + OFF_WV;
    __half* wo16 = p_w16 + OFF_WO;
    __half* w116 = p_w16 + OFF_W1;
    __half* w216 = p_w16 + OFF_W2;

    // h = x
    {
        int n4 = MR * HH / 4;
        copy_f4_kernel<<<(n4 + 255) / 256, 256>>>(x, p_h, n4);
    }
    // convert weights fp32 -> fp16
    {
        int n2;
        n2 = LL * HHxHH / 2;
        conv_f2h_kernel<<<(n2 + 255) / 256, 256>>>(wq, wq16, n2);
        conv_f2h_kernel<<<(n2 + 255) / 256, 256>>>(wk, wk16, n2);
        conv_f2h_kernel<<<(n2 + 255) / 256, 256>>>(wv, wv16, n2);
        conv_f2h_kernel<<<(n2 + 255) / 256, 256>>>(wo, wo16, n2);
        n2 = LL * HHxFF / 2;
        conv_f2h_kernel<<<(n2 + 255) / 256, 256>>>(w1, w116, n2);
        conv_f2h_kernel<<<(n2 + 255) / 256, 256>>>(w2, w216, n2);
    }

    const dim3 blk(256);
    const dim3 grid_proj(HH / 128, MR / 128, 1);        // 6 x 64
    const dim3 grid_scr(SS / 128, SS / 128, BB * NH_);  // 4 x 4 x 192
    const dim3 grid_pv(1, SS / 128, BB * NH_);          // 1 x 4 x 192
    const dim3 grid_ff1(FF_ / 128, MR / 128, 1);        // 24 x 64

    for (int l = 0; l < LL; l++) {
        // LN1 -> y (fp16)
        ln_kernel<<<MR, blk>>>(p_h, ln1_g + l * HH, ln1_b + l * HH, p_y, nullptr);
        // Q,K,V projections; K written transposed [B,NH,D,S]
        gemm2_kernel<128, 0><<<grid_proj, blk>>>(p_y, wq16 + (size_t)l * HHxHH, bq + l * HH,
                                                 nullptr, p_q, HH, HH, HH, 0, 0, SCALE_Q);
        gemm2_kernel<128, 5><<<grid_proj, blk>>>(p_y, wk16 + (size_t)l * HHxHH, bk + l * HH,
                                                 nullptr, p_kT, HH, HH, HH, 0, 0, 1.f);
        gemm2_kernel<128, 0><<<grid_proj, blk>>>(p_y, wv16 + (size_t)l * HHxHH, bv + l * HH,
                                                 nullptr, p_v, HH, HH, HH, 0, 0, 1.f);
        // scores = q @ kT + bias  (batched over B*NH; both operands row-major now)
        gemm2_kernel<128, 1><<<grid_scr, blk>>>(p_q, p_kT, attn_bias,
                                                p_sc, nullptr, SS, DD, SS,
                                                (long)SS * DD, (long)SS * DD, 1.f);
        // softmax
        softmax_kernel<<<(unsigned)(BB * NH_ * SS), blk>>>(p_sc, p_pr);
        // o = P @ V (batched), scatter to [B,S,H]
        gemm2_kernel<64, 2><<<grid_pv, blk>>>(p_pr, p_v, nullptr,
                                              nullptr, p_attn, DD, SS, DD,
                                              (long)SS * SS, (long)SS * DD, 1.f);
        // h += o @ Wo + bo
        gemm2_kernel<128, 3><<<grid_proj, blk>>>(p_attn, wo16 + (size_t)l * HHxHH, bo + l * HH,
                                                 p_h, nullptr, HH, HH, HH, 0, 0, 1.f);
        // LN2 -> y
        ln_kernel<<<MR, blk>>>(p_h, ln2_g + l * HH, ln2_b + l * HH, p_y, nullptr);
        // ff = gelu(y @ W1 + b1)
        gemm2_kernel<128, 4><<<grid_ff1, blk>>>(p_y, w116 + (size_t)l * HHxFF, b1 + l * FF_,
                                                nullptr, p_ff, FF_, HH, FF_, 0, 0, 1.f);
        // h += ff @ W2 + b2
        gemm2_kernel<128, 3><<<grid_proj, blk>>>(p_ff, w216 + (size_t)l * HHxFF, b2 + l * HH,
                                                 p_h, nullptr, HH, FF_, HH, 0, 0, 1.f);
    }
    // final LN -> fp32 output
    ln_kernel<<<MR, blk>>>(p_h, fln_g, fln_b, nullptr, out);
}

// round 5
// speedup vs baseline: 1.6957x; 1.6957x over previous
#include <cuda_runtime.h>
#include <cuda_fp16.h>
#include <mma.h>

using namespace nvcuda;

// ---------------- problem constants ----------------
#define BB   16
#define SS   512
#define HH   768
#define NH_  12
#define DD   64
#define FF_  3072
#define LL   4
#define MR   (BB*SS)          // 8192 rows
#define SCALE_Q 0.125f        // D^-0.5
#define LN_EPS 1e-5f

#define HHxHH   (HH*HH)       // 589824
#define HHxFF   (HH*FF_)      // 2359296

// ---------------- scratch (__device__ globals; no cudaMalloc allowed) ----------------
__device__ __align__(16) float  g_h[(size_t)MR*HH];          // fp32 residual stream
__device__ __align__(16) __half g_y[(size_t)MR*HH];          // LN output (fp16)
__device__ __align__(16) __half g_q[(size_t)MR*HH];          // [B,NH,S,D]
__device__ __align__(16) __half g_k[(size_t)MR*HH];          // K^T: [B,NH,D,S]
__device__ __align__(16) __half g_v[(size_t)MR*HH];          // [B,NH,S,D]
__device__ __align__(16) __half g_attn[(size_t)MR*HH];       // attn out, [B,S,H]
__device__ __align__(16) float  g_scores[(size_t)BB*NH_*SS*SS];
__device__ __align__(16) __half g_probs [(size_t)BB*NH_*SS*SS];
__device__ __align__(16) __half g_ff[(size_t)MR*FF_];
__device__ __align__(16) __half g_w16[(size_t)LL*(4*HHxHH + 2*HHxFF)];

#define OFF_WQ  ((size_t)0)
#define OFF_WK  ((size_t)LL*HHxHH)
#define OFF_WV  ((size_t)2*LL*HHxHH)
#define OFF_WO  ((size_t)3*LL*HHxHH)
#define OFF_W1  ((size_t)4*LL*HHxHH)
#define OFF_W2  ((size_t)4*LL*HHxHH + (size_t)LL*HHxFF)

// ---------------- utility kernels ----------------
__global__ void copy_f4_kernel(const float* __restrict__ src, float* __restrict__ dst, int n4) {
    int i = blockIdx.x * blockDim.x + threadIdx.x;
    if (i < n4) reinterpret_cast<float4*>(dst)[i] = reinterpret_cast<const float4*>(src)[i];
}

// single launch converting ALL weights fp32->fp16 into contiguous g_w16
__global__ void conv_all_kernel(
    const float* __restrict__ wq, const float* __restrict__ wk,
    const float* __restrict__ wv, const float* __restrict__ wo,
    const float* __restrict__ w1, const float* __restrict__ w2,
    __half* __restrict__ dst)
{
    const size_t NP = (size_t)LL * HHxHH / 2;   // float2-pairs per proj weight group
    const size_t NF = (size_t)LL * HHxFF / 2;   // pairs per ff weight group
    size_t i = (size_t)blockIdx.x * blockDim.x + threadIdx.x;   // pair index
    const float* src; size_t off;
    if (i < 4 * NP) {
        size_t g = i / NP; off = i - g * NP;
        src = (g == 0) ? wq : (g == 1) ? wk : (g == 2) ? wv : wo;
    } else {
        size_t j = i - 4 * NP;
        size_t g = j / NF; off = j - g * NF;
        src = g ? w2 : w1;
    }
    float2 f = reinterpret_cast<const float2*>(src)[off];
    reinterpret_cast<__half2*>(dst)[i] = __floats2half2_rn(f.x, f.y);
}

// ---------------- LayerNorm ----------------
__global__ __launch_bounds__(256) void ln_kernel(
    const float* __restrict__ in, const float* __restrict__ g, const float* __restrict__ b,
    __half* __restrict__ outH, float* __restrict__ outF)
{
    const int row = blockIdx.x;
    const float* x = in + (size_t)row * HH;
    const int t = threadIdx.x;

    float v[3], s = 0.f, s2 = 0.f;
#pragma unroll
    for (int i = 0; i < 3; i++) {
        float xv = x[t + i * 256];
        v[i] = xv; s += xv; s2 += xv * xv;
    }
#pragma unroll
    for (int o = 16; o; o >>= 1) {
        s  += __shfl_xor_sync(0xffffffffu, s,  o);
        s2 += __shfl_xor_sync(0xffffffffu, s2, o);
    }
    __shared__ float r1[8], r2[8];
    __shared__ float mean_s, rstd_s;
    if ((t & 31) == 0) { r1[t >> 5] = s; r2[t >> 5] = s2; }
    __syncthreads();
    if (t == 0) {
        float ss = 0.f, ss2 = 0.f;
#pragma unroll
        for (int i = 0; i < 8; i++) { ss += r1[i]; ss2 += r2[i]; }
        float mean = ss * (1.f / HH);
        float var  = ss2 * (1.f / HH) - mean * mean;
        mean_s = mean;
        rstd_s = rsqrtf(var + LN_EPS);
    }
    __syncthreads();
    const float mean = mean_s, rstd = rstd_s;
#pragma unroll
    for (int i = 0; i < 3; i++) {
        int idx = t + i * 256;
        float o = (v[i] - mean) * rstd * g[idx] + b[idx];
        if (outH) outH[(size_t)row * HH + idx] = __float2half_rn(o);
        else      outF[(size_t)row * HH + idx] = o;
    }
}

// ---------------- softmax: 4 rows / block, 2 warps / row ----------------
__global__ __launch_bounds__(256) void softmax4_kernel(
    const float* __restrict__ sc, __half* __restrict__ pr)
{
    const int w = threadIdx.x >> 5, lane = threadIdx.x & 31;
    const int rl = w >> 1, wr = w & 1;                 // row-in-block, warp-in-row
    const size_t row = (size_t)blockIdx.x * 4 + rl;
    const int col = (wr * 32 + lane) * 8;
    const float* x = sc + row * SS + col;
    __half* p = pr + row * SS + col;

    float4 a = reinterpret_cast<const float4*>(x)[0];
    float4 b = reinterpret_cast<const float4*>(x)[1];

    float m = fmaxf(fmaxf(fmaxf(a.x, a.y), fmaxf(a.z, a.w)),
                    fmaxf(fmaxf(b.x, b.y), fmaxf(b.z, b.w)));
#pragma unroll
    for (int o = 16; o; o >>= 1) m = fmaxf(m, __shfl_xor_sync(0xffffffffu, m, o));

    __shared__ float sm[4][2], ssum[4][2];
    if (lane == 0) sm[rl][wr] = m;
    __syncthreads();
    const float mx = fmaxf(sm[rl][0], sm[rl][1]);

    float e[8];
    e[0] = __expf(a.x - mx); e[1] = __expf(a.y - mx);
    e[2] = __expf(a.z - mx); e[3] = __expf(a.w - mx);
    e[4] = __expf(b.x - mx); e[5] = __expf(b.y - mx);
    e[6] = __expf(b.z - mx); e[7] = __expf(b.w - mx);
    float s = 0.f;
#pragma unroll
    for (int i = 0; i < 8; i++) s += e[i];
#pragma unroll
    for (int o = 16; o; o >>= 1) s += __shfl_xor_sync(0xffffffffu, s, o);
    if (lane == 0) ssum[rl][wr] = s;
    __syncthreads();
    const float inv = 1.f / (ssum[rl][0] + ssum[rl][1]);

    __half2 outv[4];
#pragma unroll
    for (int i = 0; i < 4; i++)
        outv[i] = __floats2half2_rn(e[2 * i] * inv, e[2 * i + 1] * inv);
    *reinterpret_cast<uint4*>(p) = *reinterpret_cast<uint4*>(outv);
}

// ---------------- cp.async helpers ----------------
__device__ __forceinline__ void cp16(void* smem, const void* gmem) {
    unsigned sa = (unsigned)__cvta_generic_to_shared(smem);
    asm volatile("cp.async.cg.shared.global [%0], [%1], 16;\n" :: "r"(sa), "l"(gmem));
}
__device__ __forceinline__ void cp_commit() { asm volatile("cp.async.commit_group;\n"); }

// ---------------- pipelined wmma GEMM: BM=128, BN in {128,64}, BK=32 ----------------
// Epilogues:
//  0 QKV : outH[((b*NH+h)*S+s)*D+d] = (acc + bias[gj]) * oscale
//  5 KT  : outH[((b*NH+h)*D+d)*S+s] = acc + bias[gj]   (coalesced transposed store)
//  1 SCR : outF[z*S*S + gi*S + gj] = acc + bias[z*S*S+gi*S+gj]
//  2 PV  : outH[(b*S+gi)*H + h*D + gj] = acc ,  z=b*NH+h
//  3 RES : outF[gi*N + gj] += acc + bias[gj]
//  4 GEL : outH[gi*N + gj] = gelu(acc + bias[gj])
template<int BN, int EPI>
__global__ __launch_bounds__(256, 2) void gemm2_kernel(
    const __half* __restrict__ Ag, const __half* __restrict__ Bg,
    const float* __restrict__ bias,
    float* __restrict__ outF, __half* __restrict__ outH,
    int N, int K, int ldb, long sA, long sB, float oscale)
{
    constexpr int SA  = 40;
    constexpr int SB  = BN + 8;
    constexpr int WGN = (BN == 128) ? 4 : 2;
    constexpr int WTM = (BN == 128) ? 64 : 32;
    constexpr int WTN = 32;
    constexpr int FM  = WTM / 16;
    constexpr int FN  = WTN / 16;

    __shared__ __align__(16) __half As[2][128 * SA];
    __shared__ __align__(16) __half Bs[2][32 * SB];
    __shared__ __align__(16) float  stg[8][16 * 20];

    const int z  = blockIdx.z;
    const __half* A  = Ag + (size_t)z * sA + (size_t)blockIdx.y * 128 * K;
    const __half* Bb = Bg + (size_t)z * sB;
    const int n0 = blockIdx.x * BN;

    const int t    = threadIdx.x;
    const int w    = t >> 5;
    const int lane = t & 31;
    const int wm   = w / WGN, wn = w % WGN;

    wmma::fragment<wmma::accumulator, 16, 16, 16, float> c[FM][FN];
#pragma unroll
    for (int i = 0; i < FM; i++)
#pragma unroll
        for (int j = 0; j < FN; j++) wmma::fill_fragment(c[i][j], 0.f);

    auto load_tiles = [&](int s, int k0) {
#pragma unroll
        for (int i = 0; i < 2; i++) {               // A: 128x32
            int idx = t + i * 256;
            int row = idx >> 2, ch = (idx & 3) * 8;
            cp16(&As[s][row * SA + ch], A + (size_t)row * K + k0 + ch);
        }
        if (BN == 128) {
#pragma unroll
            for (int i = 0; i < 2; i++) {           // B: 32x128
                int idx = t + i * 256;
                int row = idx >> 4, ch = (idx & 15) * 8;
                cp16(&Bs[s][row * SB + ch], Bb + (size_t)(k0 + row) * ldb + n0 + ch);
            }
        } else {                                    // B: 32x64
            int row = t >> 3, ch = (t & 7) * 8;
            cp16(&Bs[s][row * SB + ch], Bb + (size_t)(k0 + row) * ldb + n0 + ch);
        }
    };

    const int nk = K >> 5;
    load_tiles(0, 0);
    cp_commit();

    int s = 0;
    for (int kt = 0; kt < nk; kt++) {
        if (kt + 1 < nk) {
            load_tiles(s ^ 1, (kt + 1) * 32);
            cp_commit();
            asm volatile("cp.async.wait_group 1;\n");
        } else {
            asm volatile("cp.async.wait_group 0;\n");
        }
        __syncthreads();

#pragma unroll
        for (int ks = 0; ks < 2; ks++) {
            wmma::fragment<wmma::matrix_b, 16, 16, 16, __half, wmma::row_major> bf[FN];
#pragma unroll
            for (int j = 0; j < FN; j++)
                wmma::load_matrix_sync(bf[j], &Bs[s][ks * 16 * SB + wn * WTN + j * 16], SB);
#pragma unroll
            for (int i = 0; i < FM; i++) {
                wmma::fragment<wmma::matrix_a, 16, 16, 16, __half, wmma::row_major> af;
                wmma::load_matrix_sync(af, &As[s][(wm * WTM + i * 16) * SA + ks * 16], SA);
#pragma unroll
                for (int j = 0; j < FN; j++)
                    wmma::mma_sync(c[i][j], af, bf[j], c[i][j]);
            }
        }
        __syncthreads();
        s ^= 1;
    }

    // ---- epilogue: per-warp 16x16 staging ----
    const int gi0 = blockIdx.y * 128 + wm * WTM;
    const int gj0 = n0 + wn * WTN;
    float* st = stg[w];
    const int r  = lane >> 1;
    const int c0 = (lane & 1) * 8;

#pragma unroll
    for (int i = 0; i < FM; i++) {
#pragma unroll
        for (int j = 0; j < FN; j++) {
            wmma::store_matrix_sync(st, c[i][j], 20, wmma::mem_row_major);
            __syncwarp();

            if (EPI == 5) {
                // transposed, coalesced: lane covers 8 consecutive s for one (h,d)
                const int dr  = lane >> 1;              // local d index 0..15
                const int sc0 = (lane & 1) * 8;         // local s offset
                const int gjd = gj0 + j * 16 + dr;      // global col -> (hh,dd)
                const int hh = gjd >> 6, dd = gjd & 63;
                const int ssb = gi0 + i * 16 + sc0;     // global row -> s
                const int bb = ssb >> 9;
                const int sloc = ssb & 511;
                const float bv = bias[gjd];
                __half tmp[8];
#pragma unroll
                for (int k2 = 0; k2 < 8; k2++)
                    tmp[k2] = __float2half_rn(st[(sc0 + k2) * 20 + dr] + bv);
                *reinterpret_cast<uint4*>(
                    &outH[((size_t)(bb * NH_ + hh) * DD + dd) * SS + sloc]) =
                    *reinterpret_cast<uint4*>(tmp);
            } else {
                const int gi = gi0 + i * 16 + r;
#pragma unroll
                for (int cc = 0; cc < 8; cc++) {
                    const int gj = gj0 + j * 16 + c0 + cc;
                    float acc = st[r * 20 + c0 + cc];

                    if (EPI == 0) {
                        float val = (acc + bias[gj]) * oscale;
                        int bb = gi >> 9, ss2 = gi & 511, hh = gj >> 6, dd = gj & 63;
                        outH[(((size_t)(bb * NH_ + hh) * SS + ss2) << 6) + dd] = __float2half_rn(val);
                    } else if (EPI == 1) {
                        size_t idx = (size_t)z * SS * SS + (size_t)gi * SS + gj;
                        outF[idx] = acc + bias[idx];
                    } else if (EPI == 2) {
                        int bb = z / NH_, hh = z - bb * NH_;
                        outH[((size_t)(bb * SS + gi)) * HH + hh * DD + gj] = __float2half_rn(acc);
                    } else if (EPI == 3) {
                        size_t idx = (size_t)gi * N + gj;
                        outF[idx] += acc + bias[gj];
                    } else { // EPI == 4 exact gelu
                        float xv = acc + bias[gj];
                        float gl = 0.5f * xv * (1.f + erff(xv * 0.70710678118654752f));
                        outH[(size_t)gi * N + gj] = __float2half_rn(gl);
                    }
                }
            }
            __syncwarp();
        }
    }
}

// ---------------- host ----------------
extern "C" void kernel_launch(void* const* d_in, const int* in_sizes, int n_in,
                              void* d_out, int out_size)
{
    const float* x         = (const float*)d_in[0];
    const float* attn_bias = (const float*)d_in[1];
    const float* ln1_g = (const float*)d_in[2];
    const float* ln1_b = (const float*)d_in[3];
    const float* wq = (const float*)d_in[4];
    const float* bq = (const float*)d_in[5];
    const float* wk = (const float*)d_in[6];
    const float* bk = (const float*)d_in[7];
    const float* wv = (const float*)d_in[8];
    const float* bv = (const float*)d_in[9];
    const float* wo = (const float*)d_in[10];
    const float* bo = (const float*)d_in[11];
    const float* ln2_g = (const float*)d_in[12];
    const float* ln2_b = (const float*)d_in[13];
    const float* w1 = (const float*)d_in[14];
    const float* b1 = (const float*)d_in[15];
    const float* w2 = (const float*)d_in[16];
    const float* b2 = (const float*)d_in[17];
    const float* fln_g = (const float*)d_in[18];
    const float* fln_b = (const float*)d_in[19];
    float* out = (float*)d_out;

    void* pv_ = nullptr;
    cudaGetSymbolAddress(&pv_, g_h);      float*  p_h    = (float*)pv_;
    cudaGetSymbolAddress(&pv_, g_y);      __half* p_y    = (__half*)pv_;
    cudaGetSymbolAddress(&pv_, g_q);      __half* p_q    = (__half*)pv_;
    cudaGetSymbolAddress(&pv_, g_k);      __half* p_kT   = (__half*)pv_;
    cudaGetSymbolAddress(&pv_, g_v);      __half* p_v    = (__half*)pv_;
    cudaGetSymbolAddress(&pv_, g_attn);   __half* p_attn = (__half*)pv_;
    cudaGetSymbolAddress(&pv_, g_scores); float*  p_sc   = (float*)pv_;
    cudaGetSymbolAddress(&pv_, g_probs);  __half* p_pr   = (__half*)pv_;
    cudaGetSymbolAddress(&pv_, g_ff);     __half* p_ff   = (__half*)pv_;
    cudaGetSymbolAddress(&pv_, g_w16);    __half* p_w16  = (__half*)pv_;

    __half* wq16 = p_w16 + OFF_WQ;
    __half* wk16 = p_w16 + OFF_WK;
    __half* wv16 = p_w16 + OFF_WV;
    __half* wo16 = p_w16 + OFF_WO;
    __half* w116 = p_w16 + OFF_W1;
    __half* w216 = p_w16 + OFF_W2;

    // launch 0: h = x
    {
        int n4 = MR * HH / 4;
        copy_f4_kernel<<<(n4 + 255) / 256, 256>>>(x, p_h, n4);
    }
    // launch 1: convert ALL weights fp32 -> fp16 in one go
    {
        size_t npairs = (size_t)LL * (4 * HHxHH + 2 * HHxFF) / 2;   // 14155776
        conv_all_kernel<<<(unsigned)(npairs / 256), 256>>>(wq, wk, wv, wo, w1, w2, p_w16);
    }

    const dim3 blk(256);
    const dim3 grid_proj(HH / 128, MR / 128, 1);        // 6 x 64
    const dim3 grid_scr(SS / 128, SS / 128, BB * NH_);  // 4 x 4 x 192
    const dim3 grid_pv(1, SS / 128, BB * NH_);          // 1 x 4 x 192
    const dim3 grid_ff1(FF_ / 128, MR / 128, 1);        // 24 x 64

    for (int l = 0; l < LL; l++) {
        // launch 2: LN1 -> y (fp16)
        ln_kernel<<<MR, blk>>>(p_h, ln1_g + l * HH, ln1_b + l * HH, p_y, nullptr);
        // launches 3,4,5: Q,K,V projections (ncu -s 5 captures V: EPI 0)
        gemm2_kernel<128, 0><<<grid_proj, blk>>>(p_y, wq16 + (size_t)l * HHxHH, bq + l * HH,
                                                 nullptr, p_q, HH, HH, HH, 0, 0, SCALE_Q);
        gemm2_kernel<128, 5><<<grid_proj, blk>>>(p_y, wk16 + (size_t)l * HHxHH, bk + l * HH,
                                                 nullptr, p_kT, HH, HH, HH, 0, 0, 1.f);
        gemm2_kernel<128, 0><<<grid_proj, blk>>>(p_y, wv16 + (size_t)l * HHxHH, bv + l * HH,
                                                 nullptr, p_v, HH, HH, HH, 0, 0, 1.f);
        // scores = q @ kT + bias
        gemm2_kernel<128, 1><<<grid_scr, blk>>>(p_q, p_kT, attn_bias,
                                                p_sc, nullptr, SS, DD, SS,
                                                (long)SS * DD, (long)SS * DD, 1.f);
        // softmax (4 rows / block)
        softmax4_kernel<<<(unsigned)(BB * NH_ * SS / 4), blk>>>(p_sc, p_pr);
        // o = P @ V
        gemm2_kernel<64, 2><<<grid_pv, blk>>>(p_pr, p_v, nullptr,
                                              nullptr, p_attn, DD, SS, DD,
                                              (long)SS * SS, (long)SS * DD, 1.f);
        // h += o @ Wo + bo
        gemm2_kernel<128, 3><<<grid_proj, blk>>>(p_attn, wo16 + (size_t)l * HHxHH, bo + l * HH,
                                                 p_h, nullptr, HH, HH, HH, 0, 0, 1.f);
        // LN2 -> y
        ln_kernel<<<MR, blk>>>(p_h, ln2_g + l * HH, ln2_b + l * HH, p_y, nullptr);
        // ff = gelu(y @ W1 + b1)
        gemm2_kernel<128, 4><<<grid_ff1, blk>>>(p_y, w116 + (size_t)l * HHxFF, b1 + l * FF_,
                                                nullptr, p_ff, FF_, HH, FF_, 0, 0, 1.f);
        // h += ff @ W2 + b2
        gemm2_kernel<128, 3><<<grid_proj, blk>>>(p_ff, w216 + (size_t)l * HHxFF, b2 + l * HH,
                                                 p_h, nullptr, HH, FF_, HH, 0, 0, 1.f);
    }
    // final LN -> fp32 output
    ln_kernel<<<MR, blk>>>(p_h, fln_g, fln_b, nullptr, out);
}

// round 6
// speedup vs baseline: 1.7054x; 1.0057x over previous
#include <cuda_runtime.h>
#include <cuda_fp16.h>
#include <mma.h>

using namespace nvcuda;

// ---------------- problem constants ----------------
#define BB   16
#define SS   512
#define HH   768
#define NH_  12
#define DD   64
#define FF_  3072
#define LL   4
#define MR   (BB*SS)          // 8192 rows
#define SCALE_Q 0.125f        // D^-0.5
#define LN_EPS 1e-5f

#define HHxHH   (HH*HH)       // 589824
#define HHxFF   (HH*FF_)      // 2359296

// ---------------- scratch ----------------
__device__ __align__(16) float  g_h[(size_t)MR*HH];
__device__ __align__(16) __half g_y[(size_t)MR*HH];
__device__ __align__(16) __half g_q[(size_t)MR*HH];          // [B,NH,S,D]
__device__ __align__(16) __half g_k[(size_t)MR*HH];          // K^T: [B,NH,D,S]
__device__ __align__(16) __half g_v[(size_t)MR*HH];          // [B,NH,S,D]
__device__ __align__(16) __half g_attn[(size_t)MR*HH];
__device__ __align__(16) float  g_scores[(size_t)BB*NH_*SS*SS];
__device__ __align__(16) __half g_probs [(size_t)BB*NH_*SS*SS];
__device__ __align__(16) __half g_ff[(size_t)MR*FF_];
__device__ __align__(16) __half g_w16[(size_t)LL*(4*HHxHH + 2*HHxFF)];

#define OFF_WQ  ((size_t)0)
#define OFF_WK  ((size_t)LL*HHxHH)
#define OFF_WV  ((size_t)2*LL*HHxHH)
#define OFF_WO  ((size_t)3*LL*HHxHH)
#define OFF_W1  ((size_t)4*LL*HHxHH)
#define OFF_W2  ((size_t)4*LL*HHxHH + (size_t)LL*HHxFF)

// ---------------- utility kernels ----------------
__global__ void copy_f4_kernel(const float* __restrict__ src, float* __restrict__ dst, int n4) {
    int i = blockIdx.x * blockDim.x + threadIdx.x;
    if (i < n4) reinterpret_cast<float4*>(dst)[i] = reinterpret_cast<const float4*>(src)[i];
}

__global__ void conv_all_kernel(
    const float* __restrict__ wq, const float* __restrict__ wk,
    const float* __restrict__ wv, const float* __restrict__ wo,
    const float* __restrict__ w1, const float* __restrict__ w2,
    __half* __restrict__ dst)
{
    const size_t NP = (size_t)LL * HHxHH / 2;
    const size_t NF = (size_t)LL * HHxFF / 2;
    size_t i = (size_t)blockIdx.x * blockDim.x + threadIdx.x;
    const float* src; size_t off;
    if (i < 4 * NP) {
        size_t g = i / NP; off = i - g * NP;
        src = (g == 0) ? wq : (g == 1) ? wk : (g == 2) ? wv : wo;
    } else {
        size_t j = i - 4 * NP;
        size_t g = j / NF; off = j - g * NF;
        src = g ? w2 : w1;
    }
    float2 f = reinterpret_cast<const float2*>(src)[off];
    reinterpret_cast<__half2*>(dst)[i] = __floats2half2_rn(f.x, f.y);
}

// ---------------- LayerNorm ----------------
__global__ __launch_bounds__(256) void ln_kernel(
    const float* __restrict__ in, const float* __restrict__ g, const float* __restrict__ b,
    __half* __restrict__ outH, float* __restrict__ outF)
{
    const int row = blockIdx.x;
    const float* x = in + (size_t)row * HH;
    const int t = threadIdx.x;

    float v[3], s = 0.f, s2 = 0.f;
#pragma unroll
    for (int i = 0; i < 3; i++) {
        float xv = x[t + i * 256];
        v[i] = xv; s += xv; s2 += xv * xv;
    }
#pragma unroll
    for (int o = 16; o; o >>= 1) {
        s  += __shfl_xor_sync(0xffffffffu, s,  o);
        s2 += __shfl_xor_sync(0xffffffffu, s2, o);
    }
    __shared__ float r1[8], r2[8];
    __shared__ float mean_s, rstd_s;
    if ((t & 31) == 0) { r1[t >> 5] = s; r2[t >> 5] = s2; }
    __syncthreads();
    if (t == 0) {
        float ss = 0.f, ss2 = 0.f;
#pragma unroll
        for (int i = 0; i < 8; i++) { ss += r1[i]; ss2 += r2[i]; }
        float mean = ss * (1.f / HH);
        float var  = ss2 * (1.f / HH) - mean * mean;
        mean_s = mean;
        rstd_s = rsqrtf(var + LN_EPS);
    }
    __syncthreads();
    const float mean = mean_s, rstd = rstd_s;
#pragma unroll
    for (int i = 0; i < 3; i++) {
        int idx = t + i * 256;
        float o = (v[i] - mean) * rstd * g[idx] + b[idx];
        if (outH) outH[(size_t)row * HH + idx] = __float2half_rn(o);
        else      outF[(size_t)row * HH + idx] = o;
    }
}

// ---------------- softmax: 4 rows / block, 2 warps / row ----------------
__global__ __launch_bounds__(256) void softmax4_kernel(
    const float* __restrict__ sc, __half* __restrict__ pr)
{
    const int w = threadIdx.x >> 5, lane = threadIdx.x & 31;
    const int rl = w >> 1, wr = w & 1;
    const size_t row = (size_t)blockIdx.x * 4 + rl;
    const int col = (wr * 32 + lane) * 8;
    const float* x = sc + row * SS + col;
    __half* p = pr + row * SS + col;

    float4 a = reinterpret_cast<const float4*>(x)[0];
    float4 b = reinterpret_cast<const float4*>(x)[1];

    float m = fmaxf(fmaxf(fmaxf(a.x, a.y), fmaxf(a.z, a.w)),
                    fmaxf(fmaxf(b.x, b.y), fmaxf(b.z, b.w)));
#pragma unroll
    for (int o = 16; o; o >>= 1) m = fmaxf(m, __shfl_xor_sync(0xffffffffu, m, o));

    __shared__ float sm[4][2], ssum[4][2];
    if (lane == 0) sm[rl][wr] = m;
    __syncthreads();
    const float mx = fmaxf(sm[rl][0], sm[rl][1]);

    float e[8];
    e[0] = __expf(a.x - mx); e[1] = __expf(a.y - mx);
    e[2] = __expf(a.z - mx); e[3] = __expf(a.w - mx);
    e[4] = __expf(b.x - mx); e[5] = __expf(b.y - mx);
    e[6] = __expf(b.z - mx); e[7] = __expf(b.w - mx);
    float s = 0.f;
#pragma unroll
    for (int i = 0; i < 8; i++) s += e[i];
#pragma unroll
    for (int o = 16; o; o >>= 1) s += __shfl_xor_sync(0xffffffffu, s, o);
    if (lane == 0) ssum[rl][wr] = s;
    __syncthreads();
    const float inv = 1.f / (ssum[rl][0] + ssum[rl][1]);

    __half2 outv[4];
#pragma unroll
    for (int i = 0; i < 4; i++)
        outv[i] = __floats2half2_rn(e[2 * i] * inv, e[2 * i + 1] * inv);
    *reinterpret_cast<uint4*>(p) = *reinterpret_cast<uint4*>(outv);
}

// ---------------- cp.async helpers ----------------
__device__ __forceinline__ void cp16(void* smem, const void* gmem) {
    unsigned sa = (unsigned)__cvta_generic_to_shared(smem);
    asm volatile("cp.async.cg.shared.global [%0], [%1], 16;\n" :: "r"(sa), "l"(gmem));
}
__device__ __forceinline__ void cp_commit() { asm volatile("cp.async.commit_group;\n"); }

// ---------------- 4-stage pipelined wmma GEMM (dynamic smem) ----------------
// BM=128, BN in {128,64}, BK=32, 8 warps, one __syncthreads per K-iter.
#define STAGES 4
template<int BN, int EPI>
__global__ __launch_bounds__(256, 2) void gemm3_kernel(
    const __half* __restrict__ Ag, const __half* __restrict__ Bg,
    const float* __restrict__ bias,
    float* __restrict__ outF, __half* __restrict__ outH,
    int N, int K, int ldb, long sA, long sB, float oscale)
{
    constexpr int SA  = 40;
    constexpr int SB  = BN + 8;
    constexpr int WGN = (BN == 128) ? 4 : 2;
    constexpr int WTM = (BN == 128) ? 64 : 32;
    constexpr int WTN = 32;
    constexpr int FM  = WTM / 16;
    constexpr int FN  = WTN / 16;
    constexpr int ASZ = 128 * SA;      // halves per A stage
    constexpr int BSZ = 32 * SB;       // halves per B stage

    extern __shared__ __align__(16) char dyn[];
    __half* As  = reinterpret_cast<__half*>(dyn);
    __half* Bs  = As + (size_t)STAGES * ASZ;
    float*  stg = reinterpret_cast<float*>(Bs + (size_t)STAGES * BSZ);

    const int z  = blockIdx.z;
    const __half* A  = Ag + (size_t)z * sA + (size_t)blockIdx.y * 128 * K;
    const __half* Bb = Bg + (size_t)z * sB;
    const int n0 = blockIdx.x * BN;

    const int t    = threadIdx.x;
    const int w    = t >> 5;
    const int lane = t & 31;
    const int wm   = w / WGN, wn = w % WGN;

    wmma::fragment<wmma::accumulator, 16, 16, 16, float> c[FM][FN];
#pragma unroll
    for (int i = 0; i < FM; i++)
#pragma unroll
        for (int j = 0; j < FN; j++) wmma::fill_fragment(c[i][j], 0.f);

    auto load_tiles = [&](int s, int k0) {
        __half* as = As + s * ASZ;
        __half* bs = Bs + s * BSZ;
#pragma unroll
        for (int i = 0; i < 2; i++) {               // A: 128x32
            int idx = t + i * 256;
            int row = idx >> 2, ch = (idx & 3) * 8;
            cp16(&as[row * SA + ch], A + (size_t)row * K + k0 + ch);
        }
        if (BN == 128) {
#pragma unroll
            for (int i = 0; i < 2; i++) {           // B: 32x128
                int idx = t + i * 256;
                int row = idx >> 4, ch = (idx & 15) * 8;
                cp16(&bs[row * SB + ch], Bb + (size_t)(k0 + row) * ldb + n0 + ch);
            }
        } else {                                    // B: 32x64
            int row = t >> 3, ch = (t & 7) * 8;
            cp16(&bs[row * SB + ch], Bb + (size_t)(k0 + row) * ldb + n0 + ch);
        }
    };

    const int nk = K >> 5;
    // prologue: always commit STAGES-1 groups (empty groups beyond nk are legal)
#pragma unroll
    for (int i = 0; i < STAGES - 1; i++) {
        if (i < nk) load_tiles(i, i * 32);
        cp_commit();
    }

    for (int kt = 0; kt < nk; kt++) {
        asm volatile("cp.async.wait_group %0;\n" :: "n"(STAGES - 2));
        __syncthreads();
        // prefetch stage kt+3 (reuses buffer of stage kt-1; all warps passed the
        // barrier above => everyone finished computing stage kt-1)
        {
            int kn = kt + STAGES - 1;
            if (kn < nk) load_tiles(kn & (STAGES - 1), kn * 32);
            cp_commit();
        }
        const int s = kt & (STAGES - 1);
        const __half* as = As + s * ASZ;
        const __half* bs = Bs + s * BSZ;
#pragma unroll
        for (int ks = 0; ks < 2; ks++) {
            wmma::fragment<wmma::matrix_b, 16, 16, 16, __half, wmma::row_major> bf[FN];
#pragma unroll
            for (int j = 0; j < FN; j++)
                wmma::load_matrix_sync(bf[j], &bs[ks * 16 * SB + wn * WTN + j * 16], SB);
#pragma unroll
            for (int i = 0; i < FM; i++) {
                wmma::fragment<wmma::matrix_a, 16, 16, 16, __half, wmma::row_major> af;
                wmma::load_matrix_sync(af, &as[(wm * WTM + i * 16) * SA + ks * 16], SA);
#pragma unroll
                for (int j = 0; j < FN; j++)
                    wmma::mma_sync(c[i][j], af, bf[j], c[i][j]);
            }
        }
    }
    __syncthreads();

    // ---- epilogue: per-warp 16x16 staging ----
    const int gi0 = blockIdx.y * 128 + wm * WTM;
    const int gj0 = n0 + wn * WTN;
    float* st = stg + w * (16 * 20);
    const int r  = lane >> 1;
    const int c0 = (lane & 1) * 8;

#pragma unroll
    for (int i = 0; i < FM; i++) {
#pragma unroll
        for (int j = 0; j < FN; j++) {
            wmma::store_matrix_sync(st, c[i][j], 20, wmma::mem_row_major);
            __syncwarp();

            if (EPI == 5) {
                const int dr  = lane >> 1;
                const int sc0 = (lane & 1) * 8;
                const int gjd = gj0 + j * 16 + dr;
                const int hh = gjd >> 6, dd = gjd & 63;
                const int ssb = gi0 + i * 16 + sc0;
                const int bb = ssb >> 9;
                const int sloc = ssb & 511;
                const float bv = bias[gjd];
                __half tmp[8];
#pragma unroll
                for (int k2 = 0; k2 < 8; k2++)
                    tmp[k2] = __float2half_rn(st[(sc0 + k2) * 20 + dr] + bv);
                *reinterpret_cast<uint4*>(
                    &outH[((size_t)(bb * NH_ + hh) * DD + dd) * SS + sloc]) =
                    *reinterpret_cast<uint4*>(tmp);
            } else {
                const int gi = gi0 + i * 16 + r;
#pragma unroll
                for (int cc = 0; cc < 8; cc++) {
                    const int gj = gj0 + j * 16 + c0 + cc;
                    float acc = st[r * 20 + c0 + cc];

                    if (EPI == 0) {
                        float val = (acc + bias[gj]) * oscale;
                        int bb = gi >> 9, ss2 = gi & 511, hh = gj >> 6, dd = gj & 63;
                        outH[(((size_t)(bb * NH_ + hh) * SS + ss2) << 6) + dd] = __float2half_rn(val);
                    } else if (EPI == 1) {
                        size_t idx = (size_t)z * SS * SS + (size_t)gi * SS + gj;
                        outF[idx] = acc + bias[idx];
                    } else if (EPI == 2) {
                        int bb = z / NH_, hh = z - bb * NH_;
                        outH[((size_t)(bb * SS + gi)) * HH + hh * DD + gj] = __float2half_rn(acc);
                    } else if (EPI == 3) {
                        size_t idx = (size_t)gi * N + gj;
                        outF[idx] += acc + bias[gj];
                    } else { // EPI == 4 exact gelu
                        float xv = acc + bias[gj];
                        float gl = 0.5f * xv * (1.f + erff(xv * 0.70710678118654752f));
                        outH[(size_t)gi * N + gj] = __float2half_rn(gl);
                    }
                }
            }
            __syncwarp();
        }
    }
}

// dynamic smem sizes
static constexpr int SMEM_BN128 = (STAGES * (128*40 + 32*136)) * 2 + 8 * 16 * 20 * 4; // 86016
static constexpr int SMEM_BN64  = (STAGES * (128*40 + 32*72))  * 2 + 8 * 16 * 20 * 4; // 69632

// ---------------- host ----------------
extern "C" void kernel_launch(void* const* d_in, const int* in_sizes, int n_in,
                              void* d_out, int out_size)
{
    const float* x         = (const float*)d_in[0];
    const float* attn_bias = (const float*)d_in[1];
    const float* ln1_g = (const float*)d_in[2];
    const float* ln1_b = (const float*)d_in[3];
    const float* wq = (const float*)d_in[4];
    const float* bq = (const float*)d_in[5];
    const float* wk = (const float*)d_in[6];
    const float* bk = (const float*)d_in[7];
    const float* wv = (const float*)d_in[8];
    const float* bv = (const float*)d_in[9];
    const float* wo = (const float*)d_in[10];
    const float* bo = (const float*)d_in[11];
    const float* ln2_g = (const float*)d_in[12];
    const float* ln2_b = (const float*)d_in[13];
    const float* w1 = (const float*)d_in[14];
    const float* b1 = (const float*)d_in[15];
    const float* w2 = (const float*)d_in[16];
    const float* b2 = (const float*)d_in[17];
    const float* fln_g = (const float*)d_in[18];
    const float* fln_b = (const float*)d_in[19];
    float* out = (float*)d_out;

    void* pv_ = nullptr;
    cudaGetSymbolAddress(&pv_, g_h);      float*  p_h    = (float*)pv_;
    cudaGetSymbolAddress(&pv_, g_y);      __half* p_y    = (__half*)pv_;
    cudaGetSymbolAddress(&pv_, g_q);      __half* p_q    = (__half*)pv_;
    cudaGetSymbolAddress(&pv_, g_k);      __half* p_kT   = (__half*)pv_;
    cudaGetSymbolAddress(&pv_, g_v);      __half* p_v    = (__half*)pv_;
    cudaGetSymbolAddress(&pv_, g_attn);   __half* p_attn = (__half*)pv_;
    cudaGetSymbolAddress(&pv_, g_scores); float*  p_sc   = (float*)pv_;
    cudaGetSymbolAddress(&pv_, g_probs);  __half* p_pr   = (__half*)pv_;
    cudaGetSymbolAddress(&pv_, g_ff);     __half* p_ff   = (__half*)pv_;
    cudaGetSymbolAddress(&pv_, g_w16);    __half* p_w16  = (__half*)pv_;

    __half* wq16 = p_w16 + OFF_WQ;
    __half* wk16 = p_w16 + OFF_WK;
    __half* wv16 = p_w16 + OFF_WV;
    __half* wo16 = p_w16 + OFF_WO;
    __half* w116 = p_w16 + OFF_W1;
    __half* w216 = p_w16 + OFF_W2;

    // raise dynamic smem caps (host-side attribute; idempotent)
    cudaFuncSetAttribute(gemm3_kernel<128,0>, cudaFuncAttributeMaxDynamicSharedMemorySize, SMEM_BN128);
    cudaFuncSetAttribute(gemm3_kernel<128,1>, cudaFuncAttributeMaxDynamicSharedMemorySize, SMEM_BN128);
    cudaFuncSetAttribute(gemm3_kernel<128,3>, cudaFuncAttributeMaxDynamicSharedMemorySize, SMEM_BN128);
    cudaFuncSetAttribute(gemm3_kernel<128,4>, cudaFuncAttributeMaxDynamicSharedMemorySize, SMEM_BN128);
    cudaFuncSetAttribute(gemm3_kernel<128,5>, cudaFuncAttributeMaxDynamicSharedMemorySize, SMEM_BN128);
    cudaFuncSetAttribute(gemm3_kernel<64,2>,  cudaFuncAttributeMaxDynamicSharedMemorySize, SMEM_BN64);

    // launch 0: h = x
    {
        int n4 = MR * HH / 4;
        copy_f4_kernel<<<(n4 + 255) / 256, 256>>>(x, p_h, n4);
    }
    // launch 1: convert ALL weights
    {
        size_t npairs = (size_t)LL * (4 * HHxHH + 2 * HHxFF) / 2;
        conv_all_kernel<<<(unsigned)(npairs / 256), 256>>>(wq, wk, wv, wo, w1, w2, p_w16);
    }

    const dim3 blk(256);
    const dim3 grid_proj(HH / 128, MR / 128, 1);
    const dim3 grid_scr(SS / 128, SS / 128, BB * NH_);
    const dim3 grid_pv(1, SS / 128, BB * NH_);
    const dim3 grid_ff1(FF_ / 128, MR / 128, 1);

    for (int l = 0; l < LL; l++) {
        ln_kernel<<<MR, blk>>>(p_h, ln1_g + l * HH, ln1_b + l * HH, p_y, nullptr);
        gemm3_kernel<128, 0><<<grid_proj, blk, SMEM_BN128>>>(p_y, wq16 + (size_t)l * HHxHH, bq + l * HH,
                                                 nullptr, p_q, HH, HH, HH, 0, 0, SCALE_Q);
        gemm3_kernel<128, 5><<<grid_proj, blk, SMEM_BN128>>>(p_y, wk16 + (size_t)l * HHxHH, bk + l * HH,
                                                 nullptr, p_kT, HH, HH, HH, 0, 0, 1.f);
        gemm3_kernel<128, 0><<<grid_proj, blk, SMEM_BN128>>>(p_y, wv16 + (size_t)l * HHxHH, bv + l * HH,
                                                 nullptr, p_v, HH, HH, HH, 0, 0, 1.f);
        gemm3_kernel<128, 1><<<grid_scr, blk, SMEM_BN128>>>(p_q, p_kT, attn_bias,
                                                p_sc, nullptr, SS, DD, SS,
                                                (long)SS * DD, (long)SS * DD, 1.f);
        softmax4_kernel<<<(unsigned)(BB * NH_ * SS / 4), blk>>>(p_sc, p_pr);
        gemm3_kernel<64, 2><<<grid_pv, blk, SMEM_BN64>>>(p_pr, p_v, nullptr,
                                              nullptr, p_attn, DD, SS, DD,
                                              (long)SS * SS, (long)SS * DD, 1.f);
        gemm3_kernel<128, 3><<<grid_proj, blk, SMEM_BN128>>>(p_attn, wo16 + (size_t)l * HHxHH, bo + l * HH,
                                                 p_h, nullptr, HH, HH, HH, 0, 0, 1.f);
        ln_kernel<<<MR, blk>>>(p_h, ln2_g + l * HH, ln2_b + l * HH, p_y, nullptr);
        gemm3_kernel<128, 4><<<grid_ff1, blk, SMEM_BN128>>>(p_y, w116 + (size_t)l * HHxFF, b1 + l * FF_,
                                                nullptr, p_ff, FF_, HH, FF_, 0, 0, 1.f);
        gemm3_kernel<128, 3><<<grid_proj, blk, SMEM_BN128>>>(p_ff, w216 + (size_t)l * HHxFF, b2 + l * HH,
                                                 p_h, nullptr, HH, FF_, HH, 0, 0, 1.f);
    }
    ln_kernel<<<MR, blk>>>(p_h, fln_g, fln_b, nullptr, out);
}

// round 8
// speedup vs baseline: 2.1029x; 1.2331x over previous
#include <cuda_runtime.h>
#include <cuda_fp16.h>
#include <mma.h>
#include <cstdint>

using namespace nvcuda;

// ---------------- problem constants ----------------
#define BB   16
#define SS   512
#define HH   768
#define NH_  12
#define DD   64
#define FF_  3072
#define LL   4
#define MR   (BB*SS)
#define SCALE_Q 0.125f
#define LN_EPS 1e-5f

#define HHxHH   (HH*HH)
#define HHxFF   (HH*FF_)

// ---------------- scratch ----------------
__device__ __align__(16) float  g_h[(size_t)MR*HH];
__device__ __align__(16) __half g_y[(size_t)MR*HH];
__device__ __align__(16) __half g_q[(size_t)MR*HH];          // [B,NH,S,D]
__device__ __align__(16) __half g_k[(size_t)MR*HH];          // K^T: [B,NH,D,S]
__device__ __align__(16) __half g_v[(size_t)MR*HH];          // [B,NH,S,D]
__device__ __align__(16) __half g_attn[(size_t)MR*HH];
__device__ __align__(16) float  g_scores[(size_t)BB*NH_*SS*SS];
__device__ __align__(16) __half g_probs [(size_t)BB*NH_*SS*SS];
__device__ __align__(16) __half g_ff[(size_t)MR*FF_];
__device__ __align__(16) __half g_w16[(size_t)LL*(4*HHxHH + 2*HHxFF)];   // fp16 weights [K,N]

#define OFF_WQ  ((size_t)0)
#define OFF_WK  ((size_t)LL*HHxHH)
#define OFF_WV  ((size_t)2*LL*HHxHH)
#define OFF_WO  ((size_t)3*LL*HHxHH)
#define OFF_W1  ((size_t)4*LL*HHxHH)
#define OFF_W2  ((size_t)4*LL*HHxHH + (size_t)LL*HHxFF)

// ---------------- utility kernels ----------------
__global__ void copy_f4_kernel(const float* __restrict__ src, float* __restrict__ dst, int n4) {
    int i = blockIdx.x * blockDim.x + threadIdx.x;
    if (i < n4) reinterpret_cast<float4*>(dst)[i] = reinterpret_cast<const float4*>(src)[i];
}

__global__ void conv_all_kernel(
    const float* __restrict__ wq, const float* __restrict__ wk,
    const float* __restrict__ wv, const float* __restrict__ wo,
    const float* __restrict__ w1, const float* __restrict__ w2,
    __half* __restrict__ dst)
{
    const size_t NP = (size_t)LL * HHxHH / 2;
    const size_t NF = (size_t)LL * HHxFF / 2;
    size_t i = (size_t)blockIdx.x * blockDim.x + threadIdx.x;
    const float* src; size_t off;
    if (i < 4 * NP) {
        size_t g = i / NP; off = i - g * NP;
        src = (g == 0) ? wq : (g == 1) ? wk : (g == 2) ? wv : wo;
    } else {
        size_t j = i - 4 * NP;
        size_t g = j / NF; off = j - g * NF;
        src = g ? w2 : w1;
    }
    float2 f = reinterpret_cast<const float2*>(src)[off];
    reinterpret_cast<__half2*>(dst)[i] = __floats2half2_rn(f.x, f.y);
}

// ---------------- LayerNorm ----------------
__global__ __launch_bounds__(256) void ln_kernel(
    const float* __restrict__ in, const float* __restrict__ g, const float* __restrict__ b,
    __half* __restrict__ outH, float* __restrict__ outF)
{
    const int row = blockIdx.x;
    const float* x = in + (size_t)row * HH;
    const int t = threadIdx.x;

    float v[3], s = 0.f, s2 = 0.f;
#pragma unroll
    for (int i = 0; i < 3; i++) {
        float xv = x[t + i * 256];
        v[i] = xv; s += xv; s2 += xv * xv;
    }
#pragma unroll
    for (int o = 16; o; o >>= 1) {
        s  += __shfl_xor_sync(0xffffffffu, s,  o);
        s2 += __shfl_xor_sync(0xffffffffu, s2, o);
    }
    __shared__ float r1[8], r2[8];
    __shared__ float mean_s, rstd_s;
    if ((t & 31) == 0) { r1[t >> 5] = s; r2[t >> 5] = s2; }
    __syncthreads();
    if (t == 0) {
        float ss = 0.f, ss2 = 0.f;
#pragma unroll
        for (int i = 0; i < 8; i++) { ss += r1[i]; ss2 += r2[i]; }
        float mean = ss * (1.f / HH);
        float var  = ss2 * (1.f / HH) - mean * mean;
        mean_s = mean;
        rstd_s = rsqrtf(var + LN_EPS);
    }
    __syncthreads();
    const float mean = mean_s, rstd = rstd_s;
#pragma unroll
    for (int i = 0; i < 3; i++) {
        int idx = t + i * 256;
        float o = (v[i] - mean) * rstd * g[idx] + b[idx];
        if (outH) outH[(size_t)row * HH + idx] = __float2half_rn(o);
        else      outF[(size_t)row * HH + idx] = o;
    }
}

// ---------------- softmax: 4 rows / block ----------------
__global__ __launch_bounds__(256) void softmax4_kernel(
    const float* __restrict__ sc, __half* __restrict__ pr)
{
    const int w = threadIdx.x >> 5, lane = threadIdx.x & 31;
    const int rl = w >> 1, wr = w & 1;
    const size_t row = (size_t)blockIdx.x * 4 + rl;
    const int col = (wr * 32 + lane) * 8;
    const float* x = sc + row * SS + col;
    __half* p = pr + row * SS + col;

    float4 a = reinterpret_cast<const float4*>(x)[0];
    float4 b = reinterpret_cast<const float4*>(x)[1];

    float m = fmaxf(fmaxf(fmaxf(a.x, a.y), fmaxf(a.z, a.w)),
                    fmaxf(fmaxf(b.x, b.y), fmaxf(b.z, b.w)));
#pragma unroll
    for (int o = 16; o; o >>= 1) m = fmaxf(m, __shfl_xor_sync(0xffffffffu, m, o));

    __shared__ float sm[4][2], ssum[4][2];
    if (lane == 0) sm[rl][wr] = m;
    __syncthreads();
    const float mx = fmaxf(sm[rl][0], sm[rl][1]);

    float e[8];
    e[0] = __expf(a.x - mx); e[1] = __expf(a.y - mx);
    e[2] = __expf(a.z - mx); e[3] = __expf(a.w - mx);
    e[4] = __expf(b.x - mx); e[5] = __expf(b.y - mx);
    e[6] = __expf(b.z - mx); e[7] = __expf(b.w - mx);
    float s = 0.f;
#pragma unroll
    for (int i = 0; i < 8; i++) s += e[i];
#pragma unroll
    for (int o = 16; o; o >>= 1) s += __shfl_xor_sync(0xffffffffu, s, o);
    if (lane == 0) ssum[rl][wr] = s;
    __syncthreads();
    const float inv = 1.f / (ssum[rl][0] + ssum[rl][1]);

    __half2 outv[4];
#pragma unroll
    for (int i = 0; i < 4; i++)
        outv[i] = __floats2half2_rn(e[2 * i] * inv, e[2 * i + 1] * inv);
    *reinterpret_cast<uint4*>(p) = *reinterpret_cast<uint4*>(outv);
}

// ---------------- asm helpers ----------------
__device__ __forceinline__ void cp16(void* smem, const void* gmem) {
    unsigned sa = (unsigned)__cvta_generic_to_shared(smem);
    asm volatile("cp.async.cg.shared.global [%0], [%1], 16;\n" :: "r"(sa), "l"(gmem));
}
__device__ __forceinline__ void cp_commit() { asm volatile("cp.async.commit_group;\n"); }
__device__ __forceinline__ unsigned smem_u32(const void* p) {
    return (unsigned)__cvta_generic_to_shared(p);
}
__device__ __forceinline__ void ldsm4(uint32_t& r0, uint32_t& r1, uint32_t& r2, uint32_t& r3,
                                      unsigned addr) {
    asm volatile("ldmatrix.sync.aligned.m8n8.x4.shared.b16 {%0,%1,%2,%3}, [%4];"
                 : "=r"(r0), "=r"(r1), "=r"(r2), "=r"(r3) : "r"(addr));
}
__device__ __forceinline__ void ldsm4t(uint32_t& r0, uint32_t& r1, uint32_t& r2, uint32_t& r3,
                                       unsigned addr) {
    asm volatile("ldmatrix.sync.aligned.m8n8.x4.trans.shared.b16 {%0,%1,%2,%3}, [%4];"
                 : "=r"(r0), "=r"(r1), "=r"(r2), "=r"(r3) : "r"(addr));
}
__device__ __forceinline__ void mma16816(float& d0, float& d1, float& d2, float& d3,
                                         uint32_t a0, uint32_t a1, uint32_t a2, uint32_t a3,
                                         uint32_t b0, uint32_t b1) {
    asm volatile(
        "mma.sync.aligned.m16n8k16.row.col.f32.f16.f16.f32 "
        "{%0,%1,%2,%3}, {%4,%5,%6,%7}, {%8,%9}, {%0,%1,%2,%3};"
        : "+f"(d0), "+f"(d1), "+f"(d2), "+f"(d3)
        : "r"(a0), "r"(a1), "r"(a2), "r"(a3), "r"(b0), "r"(b1));
}

// ---------------- mma.sync GEMM: 128x128 tile, BK=32, 8 warps (2x4), 4-stage ----------------
// A [M,K] fp16 row-major; B [K,N] fp16 row-major. D = A@B.
// smem per stage: A 128 rows x 64B (XOR chunk^( (row>>1)&3 )); B 32 rows x 256B (chunk^(k&7)).
// Epilogues: 0 QKV-scatter(+scale), 5 K^T, 3 residual +=, 4 GELU.
#define MG_STAGES 4
#define MG_ASTG   8192
#define MG_BSTG   8192
#define MG_DSM    66560     // >= max(8*8192=65536, 128*129*4=66048)

template<int EPI>
__global__ __launch_bounds__(256, 2) void mgemm_kernel(
    const __half* __restrict__ Ag, const __half* __restrict__ Bg,
    const float* __restrict__ bias,
    float* __restrict__ outF, __half* __restrict__ outH,
    int K, int N, float oscale)
{
    extern __shared__ __align__(16) char dyn[];
    const unsigned sb = smem_u32(dyn);
    float* stg = reinterpret_cast<float*>(dyn);

    const int t = threadIdx.x, w = t >> 5, lane = t & 31;
    const int wm = w >> 2, wn = w & 3;          // 2 x 4 warps; warp tile 64(M) x 32(N)
    const __half* A = Ag + (size_t)blockIdx.y * 128 * K;
    const int n0 = blockIdx.x * 128;

    float d[4][4][4];
#pragma unroll
    for (int i = 0; i < 4; i++)
#pragma unroll
        for (int j = 0; j < 4; j++)
#pragma unroll
            for (int k = 0; k < 4; k++) d[i][j][k] = 0.f;

    // per-lane ldmatrix byte offsets within a stage
    unsigned aoff[2][4], boff[2][2];
#pragma unroll
    for (int ks = 0; ks < 2; ks++) {
#pragma unroll
        for (int mi = 0; mi < 4; mi++) {
            int row = wm * 64 + mi * 16 + (lane & 15);
            int kch = ks * 2 + (lane >> 4);
            aoff[ks][mi] = (unsigned)(row * 64 + ((kch ^ ((row >> 1) & 3)) << 4));
        }
#pragma unroll
        for (int pj = 0; pj < 2; pj++) {
            int kk = ks * 16 + (lane & 15);
            int nch = wn * 4 + pj * 2 + (lane >> 4);
            boff[ks][pj] = (unsigned)(kk * 256 + ((nch ^ (kk & 7)) << 4));
        }
    }

    auto load_tiles = [&](int s, int k0) {
        char* as = dyn + s * MG_ASTG;
        char* bs = dyn + MG_STAGES * MG_ASTG + s * MG_BSTG;
#pragma unroll
        for (int i = 0; i < 2; i++) {           // A: 128 x 32 halves = 512 chunks
            int idx = t + i * 256;
            int r = idx >> 2, c = idx & 3;
            cp16(as + r * 64 + ((c ^ ((r >> 1) & 3)) << 4), A + (size_t)r * K + k0 + c * 8);
        }
#pragma unroll
        for (int i = 0; i < 2; i++) {           // B: 32 x 128 halves = 512 chunks
            int idx = t + i * 256;
            int k = idx >> 4, c = idx & 15;
            cp16(bs + k * 256 + ((c ^ (k & 7)) << 4), Bg + (size_t)(k0 + k) * N + n0 + c * 8);
        }
    };

    const int nk = K >> 5;
#pragma unroll
    for (int i = 0; i < MG_STAGES - 1; i++) {
        if (i < nk) load_tiles(i, i * 32);
        cp_commit();
    }

    for (int kt = 0; kt < nk; kt++) {
        asm volatile("cp.async.wait_group %0;\n" :: "n"(MG_STAGES - 2));
        __syncthreads();
        {
            int kn = kt + MG_STAGES - 1;
            if (kn < nk) load_tiles(kn & (MG_STAGES - 1), kn * 32);
            cp_commit();
        }
        const int s = kt & (MG_STAGES - 1);
        const unsigned abase = sb + s * MG_ASTG;
        const unsigned bbase = sb + MG_STAGES * MG_ASTG + s * MG_BSTG;

#pragma unroll
        for (int ks = 0; ks < 2; ks++) {
            uint32_t a[4][4], b[2][4];
#pragma unroll
            for (int mi = 0; mi < 4; mi++)
                ldsm4(a[mi][0], a[mi][1], a[mi][2], a[mi][3], abase + aoff[ks][mi]);
#pragma unroll
            for (int pj = 0; pj < 2; pj++)
                ldsm4t(b[pj][0], b[pj][1], b[pj][2], b[pj][3], bbase + boff[ks][pj]);
#pragma unroll
            for (int mi = 0; mi < 4; mi++)
#pragma unroll
                for (int nj = 0; nj < 4; nj++)
                    mma16816(d[mi][nj][0], d[mi][nj][1], d[mi][nj][2], d[mi][nj][3],
                             a[mi][0], a[mi][1], a[mi][2], a[mi][3],
                             b[nj >> 1][(nj & 1) * 2], b[nj >> 1][(nj & 1) * 2 + 1]);
        }
    }
    __syncthreads();   // all warps done with mainloop; safe to overwrite buffers with staging

    // ---- store accumulators to smem staging (stride 129) ----
    const int qr = lane >> 2, qc = (lane & 3) * 2;
#pragma unroll
    for (int mi = 0; mi < 4; mi++) {
#pragma unroll
        for (int nj = 0; nj < 4; nj++) {
            int r0 = wm * 64 + mi * 16 + qr;
            int c0 = wn * 32 + nj * 8 + qc;
            stg[r0 * 129 + c0]           = d[mi][nj][0];
            stg[r0 * 129 + c0 + 1]       = d[mi][nj][1];
            stg[(r0 + 8) * 129 + c0]     = d[mi][nj][2];
            stg[(r0 + 8) * 129 + c0 + 1] = d[mi][nj][3];
        }
    }
    __syncthreads();

    // ---- epilogue from staging ----
    const int gi0 = blockIdx.y * 128;
    const int gj0 = blockIdx.x * 128;

    if (EPI == 5) {
        // K^T scatter: out[((b*NH+h)*D+d)*S + s], vectorized along s
#pragma unroll
        for (int it = 0; it < 8; it++) {
            int idx = t + it * 256;
            int col = idx >> 4;
            int rb  = (idx & 15) * 8;
            int gjd = gj0 + col;
            int hh = gjd >> 6, dd = gjd & 63;
            int srow0 = gi0 + rb;
            int bb = srow0 >> 9, s0 = srow0 & 511;
            float bv = bias[gjd];
            __half tmp[8];
#pragma unroll
            for (int k = 0; k < 8; k++)
                tmp[k] = __float2half_rn(stg[(rb + k) * 129 + col] + bv);
            *reinterpret_cast<uint4*>(
                &outH[((size_t)(bb * NH_ + hh) * DD + dd) * SS + s0]) =
                *reinterpret_cast<uint4*>(tmp);
        }
    } else {
#pragma unroll
        for (int it = 0; it < 32; it++) {
            int idx = t + it * 256;
            int rr = idx >> 6;
            int c2 = (idx & 63) * 2;
            int gi = gi0 + rr, gj = gj0 + c2;
            float a0 = stg[rr * 129 + c2];
            float a1 = stg[rr * 129 + c2 + 1];

            if (EPI == 0) {
                float v0 = (a0 + bias[gj]) * oscale;
                float v1 = (a1 + bias[gj + 1]) * oscale;
                int bb = gi >> 9, ss2 = gi & 511, hh = gj >> 6, dd = gj & 63;
                *reinterpret_cast<__half2*>(
                    &outH[(((size_t)(bb * NH_ + hh) * SS + ss2) << 6) + dd]) =
                    __floats2half2_rn(v0, v1);
            } else if (EPI == 3) {
                float* dst = &outF[(size_t)gi * N + gj];
                float2 old = *reinterpret_cast<float2*>(dst);
                old.x += a0 + bias[gj];
                old.y += a1 + bias[gj + 1];
                *reinterpret_cast<float2*>(dst) = old;
            } else { // EPI == 4
                float x0 = a0 + bias[gj];
                float x1 = a1 + bias[gj + 1];
                float g0 = 0.5f * x0 * (1.f + erff(x0 * 0.70710678118654752f));
                float g1 = 0.5f * x1 * (1.f + erff(x1 * 0.70710678118654752f));
                *reinterpret_cast<__half2*>(&outH[(size_t)gi * N + gj]) =
                    __floats2half2_rn(g0, g1);
            }
        }
    }
}

// ---------------- wmma GEMM for attention (EPI1 scores, EPI2 PV) ----------------
#define STAGES 4
template<int BN, int EPI>
__global__ __launch_bounds__(256, 2) void gemm3_kernel(
    const __half* __restrict__ Ag, const __half* __restrict__ Bg,
    const float* __restrict__ bias,
    float* __restrict__ outF, __half* __restrict__ outH,
    int N, int K, int ldb, long sA, long sB, float oscale)
{
    constexpr int SA  = 40;
    constexpr int SB  = BN + 8;
    constexpr int WGN = (BN == 128) ? 4 : 2;
    constexpr int WTM = (BN == 128) ? 64 : 32;
    constexpr int WTN = 32;
    constexpr int FM  = WTM / 16;
    constexpr int FN  = WTN / 16;
    constexpr int ASZ = 128 * SA;
    constexpr int BSZ = 32 * SB;

    extern __shared__ __align__(16) char dyn[];
    __half* As  = reinterpret_cast<__half*>(dyn);
    __half* Bs  = As + (size_t)STAGES * ASZ;
    float*  stg = reinterpret_cast<float*>(Bs + (size_t)STAGES * BSZ);

    const int z  = blockIdx.z;
    const __half* A  = Ag + (size_t)z * sA + (size_t)blockIdx.y * 128 * K;
    const __half* Bb = Bg + (size_t)z * sB;
    const int n0 = blockIdx.x * BN;

    const int t    = threadIdx.x;
    const int w    = t >> 5;
    const int lane = t & 31;
    const int wm   = w / WGN, wn = w % WGN;

    wmma::fragment<wmma::accumulator, 16, 16, 16, float> c[FM][FN];
#pragma unroll
    for (int i = 0; i < FM; i++)
#pragma unroll
        for (int j = 0; j < FN; j++) wmma::fill_fragment(c[i][j], 0.f);

    auto load_tiles = [&](int s, int k0) {
        __half* as = As + s * ASZ;
        __half* bs = Bs + s * BSZ;
#pragma unroll
        for (int i = 0; i < 2; i++) {
            int idx = t + i * 256;
            int row = idx >> 2, ch = (idx & 3) * 8;
            cp16(&as[row * SA + ch], A + (size_t)row * K + k0 + ch);
        }
        if (BN == 128) {
#pragma unroll
            for (int i = 0; i < 2; i++) {
                int idx = t + i * 256;
                int row = idx >> 4, ch = (idx & 15) * 8;
                cp16(&bs[row * SB + ch], Bb + (size_t)(k0 + row) * ldb + n0 + ch);
            }
        } else {
            int row = t >> 3, ch = (t & 7) * 8;
            cp16(&bs[row * SB + ch], Bb + (size_t)(k0 + row) * ldb + n0 + ch);
        }
    };

    const int nk = K >> 5;
#pragma unroll
    for (int i = 0; i < STAGES - 1; i++) {
        if (i < nk) load_tiles(i, i * 32);
        cp_commit();
    }

    for (int kt = 0; kt < nk; kt++) {
        asm volatile("cp.async.wait_group %0;\n" :: "n"(STAGES - 2));
        __syncthreads();
        {
            int kn = kt + STAGES - 1;
            if (kn < nk) load_tiles(kn & (STAGES - 1), kn * 32);
            cp_commit();
        }
        const int s = kt & (STAGES - 1);
        const __half* as = As + s * ASZ;
        const __half* bs = Bs + s * BSZ;
#pragma unroll
        for (int ks = 0; ks < 2; ks++) {
            wmma::fragment<wmma::matrix_b, 16, 16, 16, __half, wmma::row_major> bf[FN];
#pragma unroll
            for (int j = 0; j < FN; j++)
                wmma::load_matrix_sync(bf[j], &bs[ks * 16 * SB + wn * WTN + j * 16], SB);
#pragma unroll
            for (int i = 0; i < FM; i++) {
                wmma::fragment<wmma::matrix_a, 16, 16, 16, __half, wmma::row_major> af;
                wmma::load_matrix_sync(af, &as[(wm * WTM + i * 16) * SA + ks * 16], SA);
#pragma unroll
                for (int j = 0; j < FN; j++)
                    wmma::mma_sync(c[i][j], af, bf[j], c[i][j]);
            }
        }
    }
    __syncthreads();

    const int gi0 = blockIdx.y * 128 + wm * WTM;
    const int gj0 = n0 + wn * WTN;
    float* st = stg + w * (16 * 20);
    const int r  = lane >> 1;
    const int c0 = (lane & 1) * 8;

#pragma unroll
    for (int i = 0; i < FM; i++) {
#pragma unroll
        for (int j = 0; j < FN; j++) {
            wmma::store_matrix_sync(st, c[i][j], 20, wmma::mem_row_major);
            __syncwarp();
            const int gi = gi0 + i * 16 + r;
#pragma unroll
            for (int cc = 0; cc < 8; cc++) {
                const int gj = gj0 + j * 16 + c0 + cc;
                float acc = st[r * 20 + c0 + cc];
                if (EPI == 1) {
                    size_t idx = (size_t)z * SS * SS + (size_t)gi * SS + gj;
                    outF[idx] = acc + bias[idx];
                } else { // EPI == 2
                    int bb = z / NH_, hh = z - bb * NH_;
                    outH[((size_t)(bb * SS + gi)) * HH + hh * DD + gj] = __float2half_rn(acc);
                }
            }
            __syncwarp();
        }
    }
}

static constexpr int SMEM_BN128 = (STAGES * (128*40 + 32*136)) * 2 + 8 * 16 * 20 * 4;
static constexpr int SMEM_BN64  = (STAGES * (128*40 + 32*72))  * 2 + 8 * 16 * 20 * 4;

// ---------------- host ----------------
extern "C" void kernel_launch(void* const* d_in, const int* in_sizes, int n_in,
                              void* d_out, int out_size)
{
    const float* x         = (const float*)d_in[0];
    const float* attn_bias = (const float*)d_in[1];
    const float* ln1_g = (const float*)d_in[2];
    const float* ln1_b = (const float*)d_in[3];
    const float* wq = (const float*)d_in[4];
    const float* bq = (const float*)d_in[5];
    const float* wk = (const float*)d_in[6];
    const float* bk = (const float*)d_in[7];
    const float* wv = (const float*)d_in[8];
    const float* bv = (const float*)d_in[9];
    const float* wo = (const float*)d_in[10];
    const float* bo = (const float*)d_in[11];
    const float* ln2_g = (const float*)d_in[12];
    const float* ln2_b = (const float*)d_in[13];
    const float* w1 = (const float*)d_in[14];
    const float* b1 = (const float*)d_in[15];
    const float* w2 = (const float*)d_in[16];
    const float* b2 = (const float*)d_in[17];
    const float* fln_g = (const float*)d_in[18];
    const float* fln_b = (const float*)d_in[19];
    float* out = (float*)d_out;

    void* pv_ = nullptr;
    cudaGetSymbolAddress(&pv_, g_h);      float*  p_h    = (float*)pv_;
    cudaGetSymbolAddress(&pv_, g_y);      __half* p_y    = (__half*)pv_;
    cudaGetSymbolAddress(&pv_, g_q);      __half* p_q    = (__half*)pv_;
    cudaGetSymbolAddress(&pv_, g_k);      __half* p_kT   = (__half*)pv_;
    cudaGetSymbolAddress(&pv_, g_v);      __half* p_v    = (__half*)pv_;
    cudaGetSymbolAddress(&pv_, g_attn);   __half* p_attn = (__half*)pv_;
    cudaGetSymbolAddress(&pv_, g_scores); float*  p_sc   = (float*)pv_;
    cudaGetSymbolAddress(&pv_, g_probs);  __half* p_pr   = (__half*)pv_;
    cudaGetSymbolAddress(&pv_, g_ff);     __half* p_ff   = (__half*)pv_;
    cudaGetSymbolAddress(&pv_, g_w16);    __half* p_w16  = (__half*)pv_;

    __half* wq16 = p_w16 + OFF_WQ;
    __half* wk16 = p_w16 + OFF_WK;
    __half* wv16 = p_w16 + OFF_WV;
    __half* wo16 = p_w16 + OFF_WO;
    __half* w116 = p_w16 + OFF_W1;
    __half* w216 = p_w16 + OFF_W2;

    cudaFuncSetAttribute(mgemm_kernel<0>, cudaFuncAttributeMaxDynamicSharedMemorySize, MG_DSM);
    cudaFuncSetAttribute(mgemm_kernel<3>, cudaFuncAttributeMaxDynamicSharedMemorySize, MG_DSM);
    cudaFuncSetAttribute(mgemm_kernel<4>, cudaFuncAttributeMaxDynamicSharedMemorySize, MG_DSM);
    cudaFuncSetAttribute(mgemm_kernel<5>, cudaFuncAttributeMaxDynamicSharedMemorySize, MG_DSM);
    cudaFuncSetAttribute(gemm3_kernel<128,1>, cudaFuncAttributeMaxDynamicSharedMemorySize, SMEM_BN128);
    cudaFuncSetAttribute(gemm3_kernel<64,2>,  cudaFuncAttributeMaxDynamicSharedMemorySize, SMEM_BN64);

    // launch 0: h = x
    {
        int n4 = MR * HH / 4;
        copy_f4_kernel<<<(n4 + 255) / 256, 256>>>(x, p_h, n4);
    }
    // launch 1: convert all weights fp32 -> fp16 ([K,N] layout preserved)
    {
        size_t npairs = (size_t)LL * (4 * HHxHH + 2 * HHxFF) / 2;
        conv_all_kernel<<<(unsigned)(npairs / 256), 256>>>(wq, wk, wv, wo, w1, w2, p_w16);
    }

    const dim3 blk(256);
    const dim3 grid_proj(HH / 128, MR / 128);           // 6 x 64
    const dim3 grid_ff1(FF_ / 128, MR / 128);           // 24 x 64
    const dim3 grid_scr(SS / 128, SS / 128, BB * NH_);
    const dim3 grid_pv(1, SS / 128, BB * NH_);

    for (int l = 0; l < LL; l++) {
        // launch 2: LN1 ; launches 3,4,5: Q,K,V (ncu -s 5 -> V mgemm)
        ln_kernel<<<MR, blk>>>(p_h, ln1_g + l * HH, ln1_b + l * HH, p_y, nullptr);
        mgemm_kernel<0><<<grid_proj, blk, MG_DSM>>>(p_y, wq16 + (size_t)l * HHxHH, bq + l * HH,
                                                    nullptr, p_q, HH, HH, SCALE_Q);
        mgemm_kernel<5><<<grid_proj, blk, MG_DSM>>>(p_y, wk16 + (size_t)l * HHxHH, bk + l * HH,
                                                    nullptr, p_kT, HH, HH, 1.f);
        mgemm_kernel<0><<<grid_proj, blk, MG_DSM>>>(p_y, wv16 + (size_t)l * HHxHH, bv + l * HH,
                                                    nullptr, p_v, HH, HH, 1.f);
        gemm3_kernel<128, 1><<<grid_scr, blk, SMEM_BN128>>>(p_q, p_kT, attn_bias,
                                                p_sc, nullptr, SS, DD, SS,
                                                (long)SS * DD, (long)SS * DD, 1.f);
        softmax4_kernel<<<(unsigned)(BB * NH_ * SS / 4), blk>>>(p_sc, p_pr);
        gemm3_kernel<64, 2><<<grid_pv, blk, SMEM_BN64>>>(p_pr, p_v, nullptr,
                                              nullptr, p_attn, DD, SS, DD,
                                              (long)SS * SS, (long)SS * DD, 1.f);
        mgemm_kernel<3><<<grid_proj, blk, MG_DSM>>>(p_attn, wo16 + (size_t)l * HHxHH, bo + l * HH,
                                                    p_h, nullptr, HH, HH, 1.f);
        ln_kernel<<<MR, blk>>>(p_h, ln2_g + l * HH, ln2_b + l * HH, p_y, nullptr);
        mgemm_kernel<4><<<grid_ff1, blk, MG_DSM>>>(p_y, w116 + (size_t)l * HHxFF, b1 + l * FF_,
                                                   nullptr, p_ff, HH, FF_, 1.f);
        mgemm_kernel<3><<<grid_proj, blk, MG_DSM>>>(p_ff, w216 + (size_t)l * HHxFF, b2 + l * HH,
                                                    p_h, nullptr, FF_, HH, 1.f);
    }
    ln_kernel<<<MR, blk>>>(p_h, fln_g, fln_b, nullptr, out);
}

// round 10
// speedup vs baseline: 2.1694x; 1.0316x over previous
#include <cuda_runtime.h>
#include <cuda_fp16.h>
#include <cstdint>

// ---------------- problem constants ----------------
#define BB   16
#define SS   512
#define HH   768
#define NH_  12
#define DD   64
#define FF_  3072
#define LL   4
#define MR   (BB*SS)
#define SCALE_Q 0.125f
#define LN_EPS 1e-5f

#define HHxHH   (HH*HH)
#define HHxFF   (HH*FF_)

// ---------------- scratch ----------------
__device__ __align__(16) float  g_h[(size_t)MR*HH];
__device__ __align__(16) __half g_y[(size_t)MR*HH];
__device__ __align__(16) __half g_q[(size_t)MR*HH];          // [B,NH,S,D] (pre-scaled)
__device__ __align__(16) __half g_k[(size_t)MR*HH];          // [B,NH,S,D]
__device__ __align__(16) __half g_v[(size_t)MR*HH];          // [B,NH,S,D]
__device__ __align__(16) __half g_attn[(size_t)MR*HH];       // [B,S,H]
__device__ __align__(16) __half g_ff[(size_t)MR*FF_];
__device__ __align__(16) __half g_w16[(size_t)LL*(4*HHxHH + 2*HHxFF)];   // fp16 weights [K,N]

#define OFF_WQ  ((size_t)0)
#define OFF_WK  ((size_t)LL*HHxHH)
#define OFF_WV  ((size_t)2*LL*HHxHH)
#define OFF_WO  ((size_t)3*LL*HHxHH)
#define OFF_W1  ((size_t)4*LL*HHxHH)
#define OFF_W2  ((size_t)4*LL*HHxHH + (size_t)LL*HHxFF)

// ---------------- init: h=x copy + all-weight fp32->fp16 conversion, one launch ----------------
#define NPAIRS ((size_t)LL*(4*HHxHH + 2*HHxFF)/2)     // 14155776 half2 pairs
#define NCOPY4 ((size_t)MR*HH/4)                      // 1572864 float4s
__global__ void init_kernel(
    const float* __restrict__ x, float* __restrict__ h,
    const float* __restrict__ wq, const float* __restrict__ wk,
    const float* __restrict__ wv, const float* __restrict__ wo,
    const float* __restrict__ w1, const float* __restrict__ w2,
    __half* __restrict__ dst)
{
    size_t i = (size_t)blockIdx.x * blockDim.x + threadIdx.x;
    if (i < NPAIRS) {
        const size_t NP = (size_t)LL * HHxHH / 2;
        const size_t NF = (size_t)LL * HHxFF / 2;
        const float* src; size_t off;
        if (i < 4 * NP) {
            size_t g = i / NP; off = i - g * NP;
            src = (g == 0) ? wq : (g == 1) ? wk : (g == 2) ? wv : wo;
        } else {
            size_t j = i - 4 * NP;
            size_t g = j / NF; off = j - g * NF;
            src = g ? w2 : w1;
        }
        float2 f = reinterpret_cast<const float2*>(src)[off];
        reinterpret_cast<__half2*>(dst)[i] = __floats2half2_rn(f.x, f.y);
    } else {
        size_t j = i - NPAIRS;
        if (j < NCOPY4)
            reinterpret_cast<float4*>(h)[j] = reinterpret_cast<const float4*>(x)[j];
    }
}

// ---------------- LayerNorm ----------------
__global__ __launch_bounds__(256) void ln_kernel(
    const float* __restrict__ in, const float* __restrict__ g, const float* __restrict__ b,
    __half* __restrict__ outH, float* __restrict__ outF)
{
    const int row = blockIdx.x;
    const float* x = in + (size_t)row * HH;
    const int t = threadIdx.x;

    float v[3], s = 0.f, s2 = 0.f;
#pragma unroll
    for (int i = 0; i < 3; i++) {
        float xv = x[t + i * 256];
        v[i] = xv; s += xv; s2 += xv * xv;
    }
#pragma unroll
    for (int o = 16; o; o >>= 1) {
        s  += __shfl_xor_sync(0xffffffffu, s,  o);
        s2 += __shfl_xor_sync(0xffffffffu, s2, o);
    }
    __shared__ float r1[8], r2[8];
    __shared__ float mean_s, rstd_s;
    if ((t & 31) == 0) { r1[t >> 5] = s; r2[t >> 5] = s2; }
    __syncthreads();
    if (t == 0) {
        float ss = 0.f, ss2 = 0.f;
#pragma unroll
        for (int i = 0; i < 8; i++) { ss += r1[i]; ss2 += r2[i]; }
        float mean = ss * (1.f / HH);
        float var  = ss2 * (1.f / HH) - mean * mean;
        mean_s = mean;
        rstd_s = rsqrtf(var + LN_EPS);
    }
    __syncthreads();
    const float mean = mean_s, rstd = rstd_s;
#pragma unroll
    for (int i = 0; i < 3; i++) {
        int idx = t + i * 256;
        float o = (v[i] - mean) * rstd * g[idx] + b[idx];
        if (outH) outH[(size_t)row * HH + idx] = __float2half_rn(o);
        else      outF[(size_t)row * HH + idx] = o;
    }
}

// ---------------- asm helpers ----------------
__device__ __forceinline__ void cp16(void* smem, const void* gmem) {
    unsigned sa = (unsigned)__cvta_generic_to_shared(smem);
    asm volatile("cp.async.cg.shared.global [%0], [%1], 16;\n" :: "r"(sa), "l"(gmem));
}
__device__ __forceinline__ void cp_commit() { asm volatile("cp.async.commit_group;\n"); }
__device__ __forceinline__ unsigned smem_u32(const void* p) {
    return (unsigned)__cvta_generic_to_shared(p);
}
__device__ __forceinline__ uint32_t h2_as_u32(__half2 h) {
    return *reinterpret_cast<uint32_t*>(&h);
}
__device__ __forceinline__ void ldsm4(uint32_t& r0, uint32_t& r1, uint32_t& r2, uint32_t& r3,
                                      unsigned addr) {
    asm volatile("ldmatrix.sync.aligned.m8n8.x4.shared.b16 {%0,%1,%2,%3}, [%4];"
                 : "=r"(r0), "=r"(r1), "=r"(r2), "=r"(r3) : "r"(addr));
}
__device__ __forceinline__ void ldsm4t(uint32_t& r0, uint32_t& r1, uint32_t& r2, uint32_t& r3,
                                       unsigned addr) {
    asm volatile("ldmatrix.sync.aligned.m8n8.x4.trans.shared.b16 {%0,%1,%2,%3}, [%4];"
                 : "=r"(r0), "=r"(r1), "=r"(r2), "=r"(r3) : "r"(addr));
}
__device__ __forceinline__ void mma16816(float& d0, float& d1, float& d2, float& d3,
                                         uint32_t a0, uint32_t a1, uint32_t a2, uint32_t a3,
                                         uint32_t b0, uint32_t b1) {
    asm volatile(
        "mma.sync.aligned.m16n8k16.row.col.f32.f16.f16.f32 "
        "{%0,%1,%2,%3}, {%4,%5,%6,%7}, {%8,%9}, {%0,%1,%2,%3};"
        : "+f"(d0), "+f"(d1), "+f"(d2), "+f"(d3)
        : "r"(a0), "r"(a1), "r"(a2), "r"(a3), "r"(b0), "r"(b1));
}

// ---------------- flash attention: 1 CTA per (qtile=128, b*NH) ----------------
// q,k,v: [B,NH,S,D] fp16 (q pre-scaled). bias: [B,NH,S,S] fp32. out: [B,S,H] fp16.
// 8 warps; warp w owns q rows [w*16, w*16+16). KV chunks of 64, double-buffered.
__global__ __launch_bounds__(256) void flash_kernel(
    const __half* __restrict__ qg, const __half* __restrict__ kg,
    const __half* __restrict__ vg, const float* __restrict__ biasg,
    __half* __restrict__ outH)
{
    __shared__ __align__(16) __half Qs[128 * 64];
    __shared__ __align__(16) __half Ks[2][64 * 64];
    __shared__ __align__(16) __half Vs[2][64 * 64];

    const int t = threadIdx.x, w = t >> 5, lane = t & 31;
    const int z = blockIdx.y;                 // b*NH + h
    const int b = z / NH_, hh = z - b * NH_;
    const int q0 = blockIdx.x * 128;

    const __half* Qg = qg + (size_t)z * SS * DD + (size_t)q0 * DD;
    const __half* Kg = kg + (size_t)z * SS * DD;
    const __half* Vg = vg + (size_t)z * SS * DD;
    const float*  Bg = biasg + (size_t)z * SS * SS + (size_t)q0 * SS;

    const unsigned sQ = smem_u32(Qs);
    const unsigned sK[2] = { smem_u32(Ks[0]), smem_u32(Ks[1]) };
    const unsigned sV[2] = { smem_u32(Vs[0]), smem_u32(Vs[1]) };

    // ---- loaders (rows of 64 halves = 128B = 8 chunks of 16B; XOR c^(r&7)) ----
    auto loadQ = [&]() {
#pragma unroll
        for (int j = 0; j < 4; j++) {                 // 1024 chunks
            int idx = t + j * 256;
            int r = idx >> 3, c = idx & 7;
            cp16((char*)Qs + r * 128 + ((c ^ (r & 7)) << 4), Qg + (size_t)r * DD + c * 8);
        }
    };
    auto loadKV = [&](int s, int chunk) {
        const __half* kc = Kg + (size_t)chunk * 64 * DD;
        const __half* vc = Vg + (size_t)chunk * 64 * DD;
#pragma unroll
        for (int j = 0; j < 2; j++) {                 // K: 512 chunks
            int idx = t + j * 256;
            int r = idx >> 3, c = idx & 7;
            cp16((char*)Ks[s] + r * 128 + ((c ^ (r & 7)) << 4), kc + (size_t)r * DD + c * 8);
        }
#pragma unroll
        for (int j = 0; j < 2; j++) {                 // V: 512 chunks
            int idx = t + j * 256;
            int r = idx >> 3, c = idx & 7;
            cp16((char*)Vs[s] + r * 128 + ((c ^ (r & 7)) << 4), vc + (size_t)r * DD + c * 8);
        }
    };

    loadQ(); loadKV(0, 0); cp_commit();
    loadKV(1, 1); cp_commit();

    // softmax state (2 rows per thread) + output accum (16x64 per warp)
    float m0 = -1e30f, m1 = -1e30f, l0 = 0.f, l1 = 0.f;
    float o[8][4];
#pragma unroll
    for (int i = 0; i < 8; i++)
#pragma unroll
        for (int k = 0; k < 4; k++) o[i][k] = 0.f;

    uint32_t aq[4][4];            // Q frags: 4 k16-steps, register-resident
    const int qrow = w * 16 + (lane & 15);

    for (int ch = 0; ch < 8; ch++) {
        if (ch < 7) { asm volatile("cp.async.wait_group 1;\n"); }
        else        { asm volatile("cp.async.wait_group 0;\n"); }
        __syncthreads();
        const int s = ch & 1;

        if (ch == 0) {
#pragma unroll
            for (int ks = 0; ks < 4; ks++) {
                int kch = ks * 2 + (lane >> 4);
                ldsm4(aq[ks][0], aq[ks][1], aq[ks][2], aq[ks][3],
                      sQ + qrow * 128 + ((kch ^ (qrow & 7)) << 4));
            }
        }

        // ---- S = Q @ K^T (16 x 64 per warp) ----
        float sc[8][4];
#pragma unroll
        for (int i = 0; i < 8; i++)
#pragma unroll
            for (int k = 0; k < 4; k++) sc[i][k] = 0.f;
#pragma unroll
        for (int ks = 0; ks < 4; ks++) {
#pragma unroll
            for (int ng = 0; ng < 4; ng++) {
                int nrow = ng * 16 + (lane & 15);
                int kch = ks * 2 + (lane >> 4);
                uint32_t r0, r1, r2, r3;
                ldsm4(r0, r1, r2, r3, sK[s] + nrow * 128 + ((kch ^ (nrow & 7)) << 4));
                mma16816(sc[ng*2][0], sc[ng*2][1], sc[ng*2][2], sc[ng*2][3],
                         aq[ks][0], aq[ks][1], aq[ks][2], aq[ks][3], r0, r2);
                mma16816(sc[ng*2+1][0], sc[ng*2+1][1], sc[ng*2+1][2], sc[ng*2+1][3],
                         aq[ks][0], aq[ks][1], aq[ks][2], aq[ks][3], r1, r3);
            }
        }

        // ---- add bias ----
        const int r0g = w * 16 + (lane >> 2);          // q row (local)
        const int cbase = ch * 64 + (lane & 3) * 2;
        const float* bp0 = Bg + (size_t)r0g * SS + cbase;
        const float* bp1 = bp0 + 8 * SS;
#pragma unroll
        for (int nj = 0; nj < 8; nj++) {
            float2 bv0 = *reinterpret_cast<const float2*>(bp0 + nj * 8);
            float2 bv1 = *reinterpret_cast<const float2*>(bp1 + nj * 8);
            sc[nj][0] += bv0.x; sc[nj][1] += bv0.y;
            sc[nj][2] += bv1.x; sc[nj][3] += bv1.y;
        }

        // ---- online softmax ----
        float rm0 = -1e30f, rm1 = -1e30f;
#pragma unroll
        for (int nj = 0; nj < 8; nj++) {
            rm0 = fmaxf(rm0, fmaxf(sc[nj][0], sc[nj][1]));
            rm1 = fmaxf(rm1, fmaxf(sc[nj][2], sc[nj][3]));
        }
        rm0 = fmaxf(rm0, __shfl_xor_sync(0xffffffffu, rm0, 1));
        rm0 = fmaxf(rm0, __shfl_xor_sync(0xffffffffu, rm0, 2));
        rm1 = fmaxf(rm1, __shfl_xor_sync(0xffffffffu, rm1, 1));
        rm1 = fmaxf(rm1, __shfl_xor_sync(0xffffffffu, rm1, 2));

        float nm0 = fmaxf(m0, rm0), nm1 = fmaxf(m1, rm1);
        float al0 = __expf(m0 - nm0), al1 = __expf(m1 - nm1);
        m0 = nm0; m1 = nm1;

        uint32_t h0[8], h1[8];
        float rs0 = 0.f, rs1 = 0.f;
#pragma unroll
        for (int nj = 0; nj < 8; nj++) {
            float e0 = __expf(sc[nj][0] - nm0);
            float e1 = __expf(sc[nj][1] - nm0);
            float e2 = __expf(sc[nj][2] - nm1);
            float e3 = __expf(sc[nj][3] - nm1);
            rs0 += e0 + e1; rs1 += e2 + e3;
            h0[nj] = h2_as_u32(__floats2half2_rn(e0, e1));
            h1[nj] = h2_as_u32(__floats2half2_rn(e2, e3));
        }
        rs0 += __shfl_xor_sync(0xffffffffu, rs0, 1);
        rs0 += __shfl_xor_sync(0xffffffffu, rs0, 2);
        rs1 += __shfl_xor_sync(0xffffffffu, rs1, 1);
        rs1 += __shfl_xor_sync(0xffffffffu, rs1, 2);
        l0 = l0 * al0 + rs0;
        l1 = l1 * al1 + rs1;
#pragma unroll
        for (int i = 0; i < 8; i++) {
            o[i][0] *= al0; o[i][1] *= al0;
            o[i][2] *= al1; o[i][3] *= al1;
        }

        // ---- O += P @ V  (P frags from h0/h1, V via trans ldsm) ----
#pragma unroll
        for (int j = 0; j < 4; j++) {                 // k16-steps over kv
#pragma unroll
            for (int pr = 0; pr < 4; pr++) {          // d 16-col groups
                int kk = j * 16 + (lane & 15);
                int nch = pr * 2 + (lane >> 4);
                uint32_t r0, r1, r2, r3;
                ldsm4t(r0, r1, r2, r3, sV[s] + kk * 128 + ((nch ^ (kk & 7)) << 4));
                mma16816(o[pr*2][0], o[pr*2][1], o[pr*2][2], o[pr*2][3],
                         h0[2*j], h1[2*j], h0[2*j+1], h1[2*j+1], r0, r1);
                mma16816(o[pr*2+1][0], o[pr*2+1][1], o[pr*2+1][2], o[pr*2+1][3],
                         h0[2*j], h1[2*j], h0[2*j+1], h1[2*j+1], r2, r3);
            }
        }
        __syncthreads();
        if (ch + 2 < 8) { loadKV(s, ch + 2); cp_commit(); }
        else if (ch < 7) { cp_commit(); }   // keep group arithmetic uniform
    }

    // ---- epilogue: O/l -> g_attn[b, s, h*64+d] ----
    const float inv0 = 1.f / l0, inv1 = 1.f / l1;
    const int row0 = q0 + w * 16 + (lane >> 2);
    const int col0 = hh * DD + (lane & 3) * 2;
    __half* o0 = outH + ((size_t)(b * SS) + row0) * HH + col0;
    __half* o1 = o0 + 8 * HH;
#pragma unroll
    for (int pj = 0; pj < 8; pj++) {
        *reinterpret_cast<__half2*>(o0 + pj * 8) = __floats2half2_rn(o[pj][0] * inv0, o[pj][1] * inv0);
        *reinterpret_cast<__half2*>(o1 + pj * 8) = __floats2half2_rn(o[pj][2] * inv1, o[pj][3] * inv1);
    }
}

// ---------------- mma.sync GEMM: 128x128 tile, BK=32, 8 warps, 4-stage ----------------
// Epilogues: 0 QKV-scatter(+scale), 3 residual +=, 4 GELU.
#define MG_STAGES 4
#define MG_ASTG   8192
#define MG_BSTG   8192
#define MG_DSM    66560

template<int EPI>
__global__ __launch_bounds__(256, 2) void mgemm_kernel(
    const __half* __restrict__ Ag, const __half* __restrict__ Bg,
    const float* __restrict__ bias,
    float* __restrict__ outF, __half* __restrict__ outH,
    int K, int N, float oscale)
{
    extern __shared__ __align__(16) char dyn[];
    const unsigned sb = smem_u32(dyn);
    float* stg = reinterpret_cast<float*>(dyn);

    const int t = threadIdx.x, w = t >> 5, lane = t & 31;
    const int wm = w >> 2, wn = w & 3;
    const __half* A = Ag + (size_t)blockIdx.y * 128 * K;
    const int n0 = blockIdx.x * 128;

    float d[4][4][4];
#pragma unroll
    for (int i = 0; i < 4; i++)
#pragma unroll
        for (int j = 0; j < 4; j++)
#pragma unroll
            for (int k = 0; k < 4; k++) d[i][j][k] = 0.f;

    unsigned aoff[2][4], boff[2][2];
#pragma unroll
    for (int ks = 0; ks < 2; ks++) {
#pragma unroll
        for (int mi = 0; mi < 4; mi++) {
            int row = wm * 64 + mi * 16 + (lane & 15);
            int kch = ks * 2 + (lane >> 4);
            aoff[ks][mi] = (unsigned)(row * 64 + ((kch ^ ((row >> 1) & 3)) << 4));
        }
#pragma unroll
        for (int pj = 0; pj < 2; pj++) {
            int kk = ks * 16 + (lane & 15);
            int nch = wn * 4 + pj * 2 + (lane >> 4);
            boff[ks][pj] = (unsigned)(kk * 256 + ((nch ^ (kk & 7)) << 4));
        }
    }

    auto load_tiles = [&](int s, int k0) {
        char* as = dyn + s * MG_ASTG;
        char* bs = dyn + MG_STAGES * MG_ASTG + s * MG_BSTG;
#pragma unroll
        for (int i = 0; i < 2; i++) {
            int idx = t + i * 256;
            int r = idx >> 2, c = idx & 3;
            cp16(as + r * 64 + ((c ^ ((r >> 1) & 3)) << 4), A + (size_t)r * K + k0 + c * 8);
        }
#pragma unroll
        for (int i = 0; i < 2; i++) {
            int idx = t + i * 256;
            int k = idx >> 4, c = idx & 15;
            cp16(bs + k * 256 + ((c ^ (k & 7)) << 4), Bg + (size_t)(k0 + k) * N + n0 + c * 8);
        }
    };

    const int nk = K >> 5;
#pragma unroll
    for (int i = 0; i < MG_STAGES - 1; i++) {
        if (i < nk) load_tiles(i, i * 32);
        cp_commit();
    }

    for (int kt = 0; kt < nk; kt++) {
        asm volatile("cp.async.wait_group %0;\n" :: "n"(MG_STAGES - 2));
        __syncthreads();
        {
            int kn = kt + MG_STAGES - 1;
            if (kn < nk) load_tiles(kn & (MG_STAGES - 1), kn * 32);
            cp_commit();
        }
        const int s = kt & (MG_STAGES - 1);
        const unsigned abase = sb + s * MG_ASTG;
        const unsigned bbase = sb + MG_STAGES * MG_ASTG + s * MG_BSTG;

#pragma unroll
        for (int ks = 0; ks < 2; ks++) {
            uint32_t a[4][4], b[2][4];
#pragma unroll
            for (int mi = 0; mi < 4; mi++)
                ldsm4(a[mi][0], a[mi][1], a[mi][2], a[mi][3], abase + aoff[ks][mi]);
#pragma unroll
            for (int pj = 0; pj < 2; pj++)
                ldsm4t(b[pj][0], b[pj][1], b[pj][2], b[pj][3], bbase + boff[ks][pj]);
#pragma unroll
            for (int mi = 0; mi < 4; mi++)
#pragma unroll
                for (int nj = 0; nj < 4; nj++)
                    mma16816(d[mi][nj][0], d[mi][nj][1], d[mi][nj][2], d[mi][nj][3],
                             a[mi][0], a[mi][1], a[mi][2], a[mi][3],
                             b[nj >> 1][(nj & 1) * 2], b[nj >> 1][(nj & 1) * 2 + 1]);
        }
    }
    __syncthreads();

    // ---- staging (stride 129) ----
    const int qr = lane >> 2, qc = (lane & 3) * 2;
#pragma unroll
    for (int mi = 0; mi < 4; mi++) {
#pragma unroll
        for (int nj = 0; nj < 4; nj++) {
            int r0 = wm * 64 + mi * 16 + qr;
            int c0 = wn * 32 + nj * 8 + qc;
            stg[r0 * 129 + c0]           = d[mi][nj][0];
            stg[r0 * 129 + c0 + 1]       = d[mi][nj][1];
            stg[(r0 + 8) * 129 + c0]     = d[mi][nj][2];
            stg[(r0 + 8) * 129 + c0 + 1] = d[mi][nj][3];
        }
    }
    __syncthreads();

    const int gi0 = blockIdx.y * 128;
    const int gj0 = blockIdx.x * 128;

#pragma unroll
    for (int it = 0; it < 32; it++) {
        int idx = t + it * 256;
        int rr = idx >> 6;
        int c2 = (idx & 63) * 2;
        int gi = gi0 + rr, gj = gj0 + c2;
        float a0 = stg[rr * 129 + c2];
        float a1 = stg[rr * 129 + c2 + 1];

        if (EPI == 0) {
            float v0 = (a0 + bias[gj]) * oscale;
            float v1 = (a1 + bias[gj + 1]) * oscale;
            int bb = gi >> 9, ss2 = gi & 511, hh = gj >> 6, dd = gj & 63;
            *reinterpret_cast<__half2*>(
                &outH[(((size_t)(bb * NH_ + hh) * SS + ss2) << 6) + dd]) =
                __floats2half2_rn(v0, v1);
        } else if (EPI == 3) {
            float* dst = &outF[(size_t)gi * N + gj];
            float2 old = *reinterpret_cast<float2*>(dst);
            old.x += a0 + bias[gj];
            old.y += a1 + bias[gj + 1];
            *reinterpret_cast<float2*>(dst) = old;
        } else { // EPI == 4
            float x0 = a0 + bias[gj];
            float x1 = a1 + bias[gj + 1];
            float g0 = 0.5f * x0 * (1.f + erff(x0 * 0.70710678118654752f));
            float g1 = 0.5f * x1 * (1.f + erff(x1 * 0.70710678118654752f));
            *reinterpret_cast<__half2*>(&outH[(size_t)gi * N + gj]) =
                __floats2half2_rn(g0, g1);
        }
    }
}

// ---------------- host ----------------
extern "C" void kernel_launch(void* const* d_in, const int* in_sizes, int n_in,
                              void* d_out, int out_size)
{
    const float* x         = (const float*)d_in[0];
    const float* attn_bias = (const float*)d_in[1];
    const float* ln1_g = (const float*)d_in[2];
    const float* ln1_b = (const float*)d_in[3];
    const float* wq = (const float*)d_in[4];
    const float* bq = (const float*)d_in[5];
    const float* wk = (const float*)d_in[6];
    const float* bk = (const float*)d_in[7];
    const float* wv = (const float*)d_in[8];
    const float* bv = (const float*)d_in[9];
    const float* wo = (const float*)d_in[10];
    const float* bo = (const float*)d_in[11];
    const float* ln2_g = (const float*)d_in[12];
    const float* ln2_b = (const float*)d_in[13];
    const float* w1 = (const float*)d_in[14];
    const float* b1 = (const float*)d_in[15];
    const float* w2 = (const float*)d_in[16];
    const float* b2 = (const float*)d_in[17];
    const float* fln_g = (const float*)d_in[18];
    const float* fln_b = (const float*)d_in[19];
    float* out = (float*)d_out;

    void* pv_ = nullptr;
    cudaGetSymbolAddress(&pv_, g_h);      float*  p_h    = (float*)pv_;
    cudaGetSymbolAddress(&pv_, g_y);      __half* p_y    = (__half*)pv_;
    cudaGetSymbolAddress(&pv_, g_q);      __half* p_q    = (__half*)pv_;
    cudaGetSymbolAddress(&pv_, g_k);      __half* p_k    = (__half*)pv_;
    cudaGetSymbolAddress(&pv_, g_v);      __half* p_v    = (__half*)pv_;
    cudaGetSymbolAddress(&pv_, g_attn);   __half* p_attn = (__half*)pv_;
    cudaGetSymbolAddress(&pv_, g_ff);     __half* p_ff   = (__half*)pv_;
    cudaGetSymbolAddress(&pv_, g_w16);    __half* p_w16  = (__half*)pv_;

    __half* wq16 = p_w16 + OFF_WQ;
    __half* wk16 = p_w16 + OFF_WK;
    __half* wv16 = p_w16 + OFF_WV;
    __half* wo16 = p_w16 + OFF_WO;
    __half* w116 = p_w16 + OFF_W1;
    __half* w216 = p_w16 + OFF_W2;

    cudaFuncSetAttribute(mgemm_kernel<0>, cudaFuncAttributeMaxDynamicSharedMemorySize, MG_DSM);
    cudaFuncSetAttribute(mgemm_kernel<3>, cudaFuncAttributeMaxDynamicSharedMemorySize, MG_DSM);
    cudaFuncSetAttribute(mgemm_kernel<4>, cudaFuncAttributeMaxDynamicSharedMemorySize, MG_DSM);

    // launch 0: init (h=x copy + weight conversion)
    {
        size_t total = NPAIRS + NCOPY4;
        init_kernel<<<(unsigned)((total + 255) / 256), 256>>>(
            x, p_h, wq, wk, wv, wo, w1, w2, p_w16);
    }

    const dim3 blk(256);
    const dim3 grid_proj(HH / 128, MR / 128);
    const dim3 grid_ff1(FF_ / 128, MR / 128);
    const dim3 grid_fa(SS / 128, BB * NH_);

    for (int l = 0; l < LL; l++) {
        // launches per layer: ln(1), Q(2), K(3), V(4), flash(5) on first layer
        ln_kernel<<<MR, blk>>>(p_h, ln1_g + l * HH, ln1_b + l * HH, p_y, nullptr);
        mgemm_kernel<0><<<grid_proj, blk, MG_DSM>>>(p_y, wq16 + (size_t)l * HHxHH, bq + l * HH,
                                                    nullptr, p_q, HH, HH, SCALE_Q);
        mgemm_kernel<0><<<grid_proj, blk, MG_DSM>>>(p_y, wk16 + (size_t)l * HHxHH, bk + l * HH,
                                                    nullptr, p_k, HH, HH, 1.f);
        mgemm_kernel<0><<<grid_proj, blk, MG_DSM>>>(p_y, wv16 + (size_t)l * HHxHH, bv + l * HH,
                                                    nullptr, p_v, HH, HH, 1.f);
        flash_kernel<<<grid_fa, blk>>>(p_q, p_k, p_v, attn_bias, p_attn);
        mgemm_kernel<3><<<grid_proj, blk, MG_DSM>>>(p_attn, wo16 + (size_t)l * HHxHH, bo + l * HH,
                                                    p_h, nullptr, HH, HH, 1.f);
        ln_kernel<<<MR, blk>>>(p_h, ln2_g + l * HH, ln2_b + l * HH, p_y, nullptr);
        mgemm_kernel<4><<<grid_ff1, blk, MG_DSM>>>(p_y, w116 + (size_t)l * HHxFF, b1 + l * FF_,
                                                   nullptr, p_ff, HH, FF_, 1.f);
        mgemm_kernel<3><<<grid_proj, blk, MG_DSM>>>(p_ff, w216 + (size_t)l * HHxFF, b2 + l * HH,
                                                    p_h, nullptr, FF_, HH, 1.f);
    }
    ln_kernel<<<MR, blk>>>(p_h, fln_g, fln_b, nullptr, out);
}

// round 11
// speedup vs baseline: 2.2404x; 1.0327x over previous
#include <cuda_runtime.h>
#include <cuda_fp16.h>
#include <cstdint>

// ---------------- problem constants ----------------
#define BB   16
#define SS   512
#define HH   768
#define NH_  12
#define DD   64
#define FF_  3072
#define LL   4
#define MR   (BB*SS)
#define SCALE_Q 0.125f
#define LN_EPS 1e-5f

#define HHxHH   (HH*HH)
#define HHxFF   (HH*FF_)
#define NQKV    (3*HH)                 // 2304
#define QKV_STRIDE ((size_t)MR*HH)

// ---------------- scratch ----------------
__device__ __align__(16) float  g_h[(size_t)MR*HH];
__device__ __align__(16) __half g_y[(size_t)MR*HH];
__device__ __align__(16) __half g_qkv[(size_t)3*MR*HH];      // q|k|v each [B,NH,S,D]
__device__ __align__(16) __half g_attn[(size_t)MR*HH];       // [B,S,H]
__device__ __align__(16) __half g_ff[(size_t)MR*FF_];
// weights fp16: [ wqkv (L x 768 x 2304) | wo | w1 | w2 ]
__device__ __align__(16) __half g_w16[(size_t)LL*(4*HHxHH + 2*HHxFF)];
__device__ __align__(16) float  g_bqkv[(size_t)LL*NQKV];

#define OFF_QKV ((size_t)0)                                  // 3L*HHxHH halves
#define OFF_WO  ((size_t)3*LL*HHxHH)
#define OFF_W1  ((size_t)4*LL*HHxHH)
#define OFF_W2  ((size_t)4*LL*HHxHH + (size_t)LL*HHxFF)

// ---------------- init kernels ----------------
#define NPAIRS ((size_t)LL*(4*HHxHH + 2*HHxFF)/2)
#define NCOPY4 ((size_t)MR*HH/4)

// weights fp32 -> fp16; wq/wk/wv interleaved into [l][k][2304] layout
__global__ void initw_kernel(
    const float* __restrict__ wq, const float* __restrict__ wk,
    const float* __restrict__ wv, const float* __restrict__ wo,
    const float* __restrict__ w1, const float* __restrict__ w2,
    __half* __restrict__ dst)
{
    const size_t NP = (size_t)LL * HHxHH / 2;
    const size_t NF = (size_t)LL * HHxFF / 2;
    size_t i = (size_t)blockIdx.x * blockDim.x + threadIdx.x;
    if (i >= NPAIRS) return;
    const float* src; size_t off, dpi;
    if (i < 3 * NP) {                  // wq/wk/wv -> concatenated qkv layout
        size_t g = i / NP; off = i - g * NP;
        src = (g == 0) ? wq : (g == 1) ? wk : wv;
        size_t l  = off / (HHxHH / 2);
        size_t r  = off - l * (HHxHH / 2);
        size_t k  = r / (HH / 2);
        size_t nc = r - k * (HH / 2);
        dpi = l * ((size_t)HH * NQKV / 2) + k * (NQKV / 2) + g * (HH / 2) + nc;
    } else {                           // wo/w1/w2: linear (same offsets as before)
        dpi = i;
        if (i < 4 * NP) { src = wo; off = i - 3 * NP; }
        else {
            size_t j = i - 4 * NP;
            size_t g = j / NF; off = j - g * NF;
            src = g ? w2 : w1;
        }
    }
    float2 f = reinterpret_cast<const float2*>(src)[off];
    reinterpret_cast<__half2*>(dst)[dpi] = __floats2half2_rn(f.x, f.y);
}

__global__ void inith_kernel(const float* __restrict__ x, float* __restrict__ h) {
    size_t i = (size_t)blockIdx.x * blockDim.x + threadIdx.x;
    if (i < NCOPY4)
        reinterpret_cast<float4*>(h)[i] = reinterpret_cast<const float4*>(x)[i];
}

__global__ void initb_kernel(const float* __restrict__ bq, const float* __restrict__ bk,
                             const float* __restrict__ bv, float* __restrict__ dst) {
    int i = blockIdx.x * blockDim.x + threadIdx.x;
    if (i >= LL * NQKV) return;
    int l = i / NQKV, n = i - l * NQKV;
    float v = (n < HH) ? bq[l * HH + n]
            : (n < 2 * HH) ? bk[l * HH + n - HH]
            : bv[l * HH + n - 2 * HH];
    dst[i] = v;
}

// ---------------- LayerNorm ----------------
__global__ __launch_bounds__(256) void ln_kernel(
    const float* __restrict__ in, const float* __restrict__ g, const float* __restrict__ b,
    __half* __restrict__ outH, float* __restrict__ outF)
{
    const int row = blockIdx.x;
    const float* x = in + (size_t)row * HH;
    const int t = threadIdx.x;

    float v[3], s = 0.f, s2 = 0.f;
#pragma unroll
    for (int i = 0; i < 3; i++) {
        float xv = x[t + i * 256];
        v[i] = xv; s += xv; s2 += xv * xv;
    }
#pragma unroll
    for (int o = 16; o; o >>= 1) {
        s  += __shfl_xor_sync(0xffffffffu, s,  o);
        s2 += __shfl_xor_sync(0xffffffffu, s2, o);
    }
    __shared__ float r1[8], r2[8];
    __shared__ float mean_s, rstd_s;
    if ((t & 31) == 0) { r1[t >> 5] = s; r2[t >> 5] = s2; }
    __syncthreads();
    if (t == 0) {
        float ss = 0.f, ss2 = 0.f;
#pragma unroll
        for (int i = 0; i < 8; i++) { ss += r1[i]; ss2 += r2[i]; }
        float mean = ss * (1.f / HH);
        float var  = ss2 * (1.f / HH) - mean * mean;
        mean_s = mean;
        rstd_s = rsqrtf(var + LN_EPS);
    }
    __syncthreads();
    const float mean = mean_s, rstd = rstd_s;
#pragma unroll
    for (int i = 0; i < 3; i++) {
        int idx = t + i * 256;
        float o = (v[i] - mean) * rstd * g[idx] + b[idx];
        if (outH) outH[(size_t)row * HH + idx] = __float2half_rn(o);
        else      outF[(size_t)row * HH + idx] = o;
    }
}

// ---------------- asm helpers ----------------
__device__ __forceinline__ void cp16(void* smem, const void* gmem) {
    unsigned sa = (unsigned)__cvta_generic_to_shared(smem);
    asm volatile("cp.async.cg.shared.global [%0], [%1], 16;\n" :: "r"(sa), "l"(gmem));
}
__device__ __forceinline__ void cp_commit() { asm volatile("cp.async.commit_group;\n"); }
__device__ __forceinline__ unsigned smem_u32(const void* p) {
    return (unsigned)__cvta_generic_to_shared(p);
}
__device__ __forceinline__ uint32_t h2_as_u32(__half2 h) {
    return *reinterpret_cast<uint32_t*>(&h);
}
__device__ __forceinline__ void ldsm4(uint32_t& r0, uint32_t& r1, uint32_t& r2, uint32_t& r3,
                                      unsigned addr) {
    asm volatile("ldmatrix.sync.aligned.m8n8.x4.shared.b16 {%0,%1,%2,%3}, [%4];"
                 : "=r"(r0), "=r"(r1), "=r"(r2), "=r"(r3) : "r"(addr));
}
__device__ __forceinline__ void ldsm4t(uint32_t& r0, uint32_t& r1, uint32_t& r2, uint32_t& r3,
                                       unsigned addr) {
    asm volatile("ldmatrix.sync.aligned.m8n8.x4.trans.shared.b16 {%0,%1,%2,%3}, [%4];"
                 : "=r"(r0), "=r"(r1), "=r"(r2), "=r"(r3) : "r"(addr));
}
__device__ __forceinline__ void mma16816(float& d0, float& d1, float& d2, float& d3,
                                         uint32_t a0, uint32_t a1, uint32_t a2, uint32_t a3,
                                         uint32_t b0, uint32_t b1) {
    asm volatile(
        "mma.sync.aligned.m16n8k16.row.col.f32.f16.f16.f32 "
        "{%0,%1,%2,%3}, {%4,%5,%6,%7}, {%8,%9}, {%0,%1,%2,%3};"
        : "+f"(d0), "+f"(d1), "+f"(d2), "+f"(d3)
        : "r"(a0), "r"(a1), "r"(a2), "r"(a3), "r"(b0), "r"(b1));
}

// ---------------- flash attention: 1 CTA per (qtile=128, b*NH) ----------------
__global__ __launch_bounds__(256) void flash_kernel(
    const __half* __restrict__ qg, const __half* __restrict__ kg,
    const __half* __restrict__ vg, const float* __restrict__ biasg,
    __half* __restrict__ outH)
{
    __shared__ __align__(16) __half Qs[128 * 64];
    __shared__ __align__(16) __half Ks[2][64 * 64];
    __shared__ __align__(16) __half Vs[2][64 * 64];

    const int t = threadIdx.x, w = t >> 5, lane = t & 31;
    const int z = blockIdx.y;
    const int b = z / NH_, hh = z - b * NH_;
    const int q0 = blockIdx.x * 128;

    const __half* Qg = qg + (size_t)z * SS * DD + (size_t)q0 * DD;
    const __half* Kg = kg + (size_t)z * SS * DD;
    const __half* Vg = vg + (size_t)z * SS * DD;
    const float*  Bg = biasg + (size_t)z * SS * SS + (size_t)q0 * SS;

    const unsigned sQ = smem_u32(Qs);
    const unsigned sK[2] = { smem_u32(Ks[0]), smem_u32(Ks[1]) };
    const unsigned sV[2] = { smem_u32(Vs[0]), smem_u32(Vs[1]) };

    auto loadQ = [&]() {
#pragma unroll
        for (int j = 0; j < 4; j++) {
            int idx = t + j * 256;
            int r = idx >> 3, c = idx & 7;
            cp16((char*)Qs + r * 128 + ((c ^ (r & 7)) << 4), Qg + (size_t)r * DD + c * 8);
        }
    };
    auto loadKV = [&](int s, int chunk) {
        const __half* kc = Kg + (size_t)chunk * 64 * DD;
        const __half* vc = Vg + (size_t)chunk * 64 * DD;
#pragma unroll
        for (int j = 0; j < 2; j++) {
            int idx = t + j * 256;
            int r = idx >> 3, c = idx & 7;
            cp16((char*)Ks[s] + r * 128 + ((c ^ (r & 7)) << 4), kc + (size_t)r * DD + c * 8);
        }
#pragma unroll
        for (int j = 0; j < 2; j++) {
            int idx = t + j * 256;
            int r = idx >> 3, c = idx & 7;
            cp16((char*)Vs[s] + r * 128 + ((c ^ (r & 7)) << 4), vc + (size_t)r * DD + c * 8);
        }
    };

    loadQ(); loadKV(0, 0); cp_commit();
    loadKV(1, 1); cp_commit();

    float m0 = -1e30f, m1 = -1e30f, l0 = 0.f, l1 = 0.f;
    float o[8][4];
#pragma unroll
    for (int i = 0; i < 8; i++)
#pragma unroll
        for (int k = 0; k < 4; k++) o[i][k] = 0.f;

    // wait group1 (Q+KV0) then preload Q frags once
    asm volatile("cp.async.wait_group 1;\n");
    __syncthreads();
    uint32_t aq[4][4];
    {
        const int qrow = w * 16 + (lane & 15);
#pragma unroll
        for (int ks = 0; ks < 4; ks++) {
            int kch = ks * 2 + (lane >> 4);
            ldsm4(aq[ks][0], aq[ks][1], aq[ks][2], aq[ks][3],
                  sQ + qrow * 128 + ((kch ^ (qrow & 7)) << 4));
        }
    }

    const int r0g = w * 16 + (lane >> 2);
    const int cb2 = (lane & 3) * 2;

    for (int ch = 0; ch < 8; ch++) {
        if (ch > 0) {
            if (ch < 7) { asm volatile("cp.async.wait_group 1;\n"); }
            else        { asm volatile("cp.async.wait_group 0;\n"); }
            __syncthreads();
        }
        const int s = ch & 1;

        // ---- S accumulator initialized with bias (loads issue before mma chain) ----
        float sc[8][4];
        {
            const float* bp0 = Bg + (size_t)r0g * SS + ch * 64 + cb2;
            const float* bp1 = bp0 + 8 * SS;
#pragma unroll
            for (int nj = 0; nj < 8; nj++) {
                float2 bv0 = *reinterpret_cast<const float2*>(bp0 + nj * 8);
                float2 bv1 = *reinterpret_cast<const float2*>(bp1 + nj * 8);
                sc[nj][0] = bv0.x; sc[nj][1] = bv0.y;
                sc[nj][2] = bv1.x; sc[nj][3] = bv1.y;
            }
        }

        // ---- S += Q @ K^T ----
#pragma unroll
        for (int ks = 0; ks < 4; ks++) {
#pragma unroll
            for (int ng = 0; ng < 4; ng++) {
                int nrow = ng * 16 + (lane & 15);
                int kch = ks * 2 + (lane >> 4);
                uint32_t r0, r1, r2, r3;
                ldsm4(r0, r1, r2, r3, sK[s] + nrow * 128 + ((kch ^ (nrow & 7)) << 4));
                mma16816(sc[ng*2][0], sc[ng*2][1], sc[ng*2][2], sc[ng*2][3],
                         aq[ks][0], aq[ks][1], aq[ks][2], aq[ks][3], r0, r2);
                mma16816(sc[ng*2+1][0], sc[ng*2+1][1], sc[ng*2+1][2], sc[ng*2+1][3],
                         aq[ks][0], aq[ks][1], aq[ks][2], aq[ks][3], r1, r3);
            }
        }

        // ---- online softmax ----
        float rm0 = -1e30f, rm1 = -1e30f;
#pragma unroll
        for (int nj = 0; nj < 8; nj++) {
            rm0 = fmaxf(rm0, fmaxf(sc[nj][0], sc[nj][1]));
            rm1 = fmaxf(rm1, fmaxf(sc[nj][2], sc[nj][3]));
        }
        rm0 = fmaxf(rm0, __shfl_xor_sync(0xffffffffu, rm0, 1));
        rm0 = fmaxf(rm0, __shfl_xor_sync(0xffffffffu, rm0, 2));
        rm1 = fmaxf(rm1, __shfl_xor_sync(0xffffffffu, rm1, 1));
        rm1 = fmaxf(rm1, __shfl_xor_sync(0xffffffffu, rm1, 2));

        float nm0 = fmaxf(m0, rm0), nm1 = fmaxf(m1, rm1);
        float al0 = __expf(m0 - nm0), al1 = __expf(m1 - nm1);
        m0 = nm0; m1 = nm1;

        uint32_t h0[8], h1[8];
        float rs0 = 0.f, rs1 = 0.f;
#pragma unroll
        for (int nj = 0; nj < 8; nj++) {
            float e0 = __expf(sc[nj][0] - nm0);
            float e1 = __expf(sc[nj][1] - nm0);
            float e2 = __expf(sc[nj][2] - nm1);
            float e3 = __expf(sc[nj][3] - nm1);
            rs0 += e0 + e1; rs1 += e2 + e3;
            h0[nj] = h2_as_u32(__floats2half2_rn(e0, e1));
            h1[nj] = h2_as_u32(__floats2half2_rn(e2, e3));
        }
        rs0 += __shfl_xor_sync(0xffffffffu, rs0, 1);
        rs0 += __shfl_xor_sync(0xffffffffu, rs0, 2);
        rs1 += __shfl_xor_sync(0xffffffffu, rs1, 1);
        rs1 += __shfl_xor_sync(0xffffffffu, rs1, 2);
        l0 = l0 * al0 + rs0;
        l1 = l1 * al1 + rs1;
#pragma unroll
        for (int i = 0; i < 8; i++) {
            o[i][0] *= al0; o[i][1] *= al0;
            o[i][2] *= al1; o[i][3] *= al1;
        }

        // ---- O += P @ V ----
#pragma unroll
        for (int j = 0; j < 4; j++) {
#pragma unroll
            for (int pr = 0; pr < 4; pr++) {
                int kk = j * 16 + (lane & 15);
                int nch = pr * 2 + (lane >> 4);
                uint32_t r0, r1, r2, r3;
                ldsm4t(r0, r1, r2, r3, sV[s] + kk * 128 + ((nch ^ (kk & 7)) << 4));
                mma16816(o[pr*2][0], o[pr*2][1], o[pr*2][2], o[pr*2][3],
                         h0[2*j], h1[2*j], h0[2*j+1], h1[2*j+1], r0, r1);
                mma16816(o[pr*2+1][0], o[pr*2+1][1], o[pr*2+1][2], o[pr*2+1][3],
                         h0[2*j], h1[2*j], h0[2*j+1], h1[2*j+1], r2, r3);
            }
        }
        __syncthreads();
        if (ch + 2 < 8) { loadKV(s, ch + 2); cp_commit(); }
        else if (ch < 7) { cp_commit(); }
    }

    // ---- epilogue ----
    const float inv0 = 1.f / l0, inv1 = 1.f / l1;
    const int row0 = q0 + r0g;
    const int col0 = hh * DD + cb2;
    __half* o0 = outH + ((size_t)(b * SS) + row0) * HH + col0;
    __half* o1 = o0 + 8 * HH;
#pragma unroll
    for (int pj = 0; pj < 8; pj++) {
        *reinterpret_cast<__half2*>(o0 + pj * 8) = __floats2half2_rn(o[pj][0] * inv0, o[pj][1] * inv0);
        *reinterpret_cast<__half2*>(o1 + pj * 8) = __floats2half2_rn(o[pj][2] * inv1, o[pj][3] * inv1);
    }
}

// ---------------- mma.sync GEMM: 128x128 tile, BK=32, 8 warps, 4-stage ----------------
// Epilogues: 6 QKV-fused scatter, 3 residual +=, 4 GELU.
#define MG_STAGES 4
#define MG_ASTG   8192
#define MG_BSTG   8192
#define MG_DSM    66560

template<int EPI>
__global__ __launch_bounds__(256, 2) void mgemm_kernel(
    const __half* __restrict__ Ag, const __half* __restrict__ Bg,
    const float* __restrict__ bias,
    float* __restrict__ outF, __half* __restrict__ outH,
    int K, int N, float oscale)
{
    extern __shared__ __align__(16) char dyn[];
    const unsigned sb = smem_u32(dyn);
    float* stg = reinterpret_cast<float*>(dyn);

    const int t = threadIdx.x, w = t >> 5, lane = t & 31;
    const int wm = w >> 2, wn = w & 3;
    const __half* A = Ag + (size_t)blockIdx.y * 128 * K;
    const int n0 = blockIdx.x * 128;

    float d[4][4][4];
#pragma unroll
    for (int i = 0; i < 4; i++)
#pragma unroll
        for (int j = 0; j < 4; j++)
#pragma unroll
            for (int k = 0; k < 4; k++) d[i][j][k] = 0.f;

    unsigned aoff[2][4], boff[2][2];
#pragma unroll
    for (int ks = 0; ks < 2; ks++) {
#pragma unroll
        for (int mi = 0; mi < 4; mi++) {
            int row = wm * 64 + mi * 16 + (lane & 15);
            int kch = ks * 2 + (lane >> 4);
            aoff[ks][mi] = (unsigned)(row * 64 + ((kch ^ ((row >> 1) & 3)) << 4));
        }
#pragma unroll
        for (int pj = 0; pj < 2; pj++) {
            int kk = ks * 16 + (lane & 15);
            int nch = wn * 4 + pj * 2 + (lane >> 4);
            boff[ks][pj] = (unsigned)(kk * 256 + ((nch ^ (kk & 7)) << 4));
        }
    }

    auto load_tiles = [&](int s, int k0) {
        char* as = dyn + s * MG_ASTG;
        char* bs = dyn + MG_STAGES * MG_ASTG + s * MG_BSTG;
#pragma unroll
        for (int i = 0; i < 2; i++) {
            int idx = t + i * 256;
            int r = idx >> 2, c = idx & 3;
            cp16(as + r * 64 + ((c ^ ((r >> 1) & 3)) << 4), A + (size_t)r * K + k0 + c * 8);
        }
#pragma unroll
        for (int i = 0; i < 2; i++) {
            int idx = t + i * 256;
            int k = idx >> 4, c = idx & 15;
            cp16(bs + k * 256 + ((c ^ (k & 7)) << 4), Bg + (size_t)(k0 + k) * N + n0 + c * 8);
        }
    };

    const int nk = K >> 5;
#pragma unroll
    for (int i = 0; i < MG_STAGES - 1; i++) {
        if (i < nk) load_tiles(i, i * 32);
        cp_commit();
    }

    for (int kt = 0; kt < nk; kt++) {
        asm volatile("cp.async.wait_group %0;\n" :: "n"(MG_STAGES - 2));
        __syncthreads();
        {
            int kn = kt + MG_STAGES - 1;
            if (kn < nk) load_tiles(kn & (MG_STAGES - 1), kn * 32);
            cp_commit();
        }
        const int s = kt & (MG_STAGES - 1);
        const unsigned abase = sb + s * MG_ASTG;
        const unsigned bbase = sb + MG_STAGES * MG_ASTG + s * MG_BSTG;

#pragma unroll
        for (int ks = 0; ks < 2; ks++) {
            uint32_t a[4][4], b[2][4];
#pragma unroll
            for (int mi = 0; mi < 4; mi++)
                ldsm4(a[mi][0], a[mi][1], a[mi][2], a[mi][3], abase + aoff[ks][mi]);
#pragma unroll
            for (int pj = 0; pj < 2; pj++)
                ldsm4t(b[pj][0], b[pj][1], b[pj][2], b[pj][3], bbase + boff[ks][pj]);
#pragma unroll
            for (int mi = 0; mi < 4; mi++)
#pragma unroll
                for (int nj = 0; nj < 4; nj++)
                    mma16816(d[mi][nj][0], d[mi][nj][1], d[mi][nj][2], d[mi][nj][3],
                             a[mi][0], a[mi][1], a[mi][2], a[mi][3],
                             b[nj >> 1][(nj & 1) * 2], b[nj >> 1][(nj & 1) * 2 + 1]);
        }
    }
    __syncthreads();

    // ---- staging (stride 129) ----
    const int qr = lane >> 2, qc = (lane & 3) * 2;
#pragma unroll
    for (int mi = 0; mi < 4; mi++) {
#pragma unroll
        for (int nj = 0; nj < 4; nj++) {
            int r0 = wm * 64 + mi * 16 + qr;
            int c0 = wn * 32 + nj * 8 + qc;
            stg[r0 * 129 + c0]           = d[mi][nj][0];
            stg[r0 * 129 + c0 + 1]       = d[mi][nj][1];
            stg[(r0 + 8) * 129 + c0]     = d[mi][nj][2];
            stg[(r0 + 8) * 129 + c0 + 1] = d[mi][nj][3];
        }
    }
    __syncthreads();

    const int gi0 = blockIdx.y * 128;
    const int gj0 = blockIdx.x * 128;

#pragma unroll
    for (int it = 0; it < 32; it++) {
        int idx = t + it * 256;
        int rr = idx >> 6;
        int c2 = (idx & 63) * 2;
        int gi = gi0 + rr, gj = gj0 + c2;
        float a0 = stg[rr * 129 + c2];
        float a1 = stg[rr * 129 + c2 + 1];

        if (EPI == 6) {
            int which = gj / HH;              // 0=q 1=k 2=v (tile never spans: 128 | 768)
            int col = gj - which * HH;
            float f = (which == 0) ? oscale : 1.f;
            float v0 = (a0 + bias[gj]) * f;
            float v1 = (a1 + bias[gj + 1]) * f;
            int bb = gi >> 9, ss2 = gi & 511, hhh = col >> 6, dd = col & 63;
            *reinterpret_cast<__half2*>(
                &outH[(size_t)which * QKV_STRIDE +
                      (((size_t)(bb * NH_ + hhh) * SS + ss2) << 6) + dd]) =
                __floats2half2_rn(v0, v1);
        } else if (EPI == 3) {
            float* dst = &outF[(size_t)gi * N + gj];
            float2 old = *reinterpret_cast<float2*>(dst);
            old.x += a0 + bias[gj];
            old.y += a1 + bias[gj + 1];
            *reinterpret_cast<float2*>(dst) = old;
        } else { // EPI == 4
            float x0 = a0 + bias[gj];
            float x1 = a1 + bias[gj + 1];
            float g0 = 0.5f * x0 * (1.f + erff(x0 * 0.70710678118654752f));
            float g1 = 0.5f * x1 * (1.f + erff(x1 * 0.70710678118654752f));
            *reinterpret_cast<__half2*>(&outH[(size_t)gi * N + gj]) =
                __floats2half2_rn(g0, g1);
        }
    }
}

// ---------------- host ----------------
extern "C" void kernel_launch(void* const* d_in, const int* in_sizes, int n_in,
                              void* d_out, int out_size)
{
    const float* x         = (const float*)d_in[0];
    const float* attn_bias = (const float*)d_in[1];
    const float* ln1_g = (const float*)d_in[2];
    const float* ln1_b = (const float*)d_in[3];
    const float* wq = (const float*)d_in[4];
    const float* bq = (const float*)d_in[5];
    const float* wk = (const float*)d_in[6];
    const float* bk = (const float*)d_in[7];
    const float* wv = (const float*)d_in[8];
    const float* bv = (const float*)d_in[9];
    const float* wo = (const float*)d_in[10];
    const float* bo = (const float*)d_in[11];
    const float* ln2_g = (const float*)d_in[12];
    const float* ln2_b = (const float*)d_in[13];
    const float* w1 = (const float*)d_in[14];
    const float* b1 = (const float*)d_in[15];
    const float* w2 = (const float*)d_in[16];
    const float* b2 = (const float*)d_in[17];
    const float* fln_g = (const float*)d_in[18];
    const float* fln_b = (const float*)d_in[19];
    float* out = (float*)d_out;

    void* pv_ = nullptr;
    cudaGetSymbolAddress(&pv_, g_h);      float*  p_h    = (float*)pv_;
    cudaGetSymbolAddress(&pv_, g_y);      __half* p_y    = (__half*)pv_;
    cudaGetSymbolAddress(&pv_, g_qkv);    __half* p_qkv  = (__half*)pv_;
    cudaGetSymbolAddress(&pv_, g_attn);   __half* p_attn = (__half*)pv_;
    cudaGetSymbolAddress(&pv_, g_ff);     __half* p_ff   = (__half*)pv_;
    cudaGetSymbolAddress(&pv_, g_w16);    __half* p_w16  = (__half*)pv_;
    cudaGetSymbolAddress(&pv_, g_bqkv);   float*  p_bqkv = (float*)pv_;

    __half* wqkv16 = p_w16 + OFF_QKV;
    __half* wo16   = p_w16 + OFF_WO;
    __half* w116   = p_w16 + OFF_W1;
    __half* w216   = p_w16 + OFF_W2;

    cudaFuncSetAttribute(mgemm_kernel<6>, cudaFuncAttributeMaxDynamicSharedMemorySize, MG_DSM);
    cudaFuncSetAttribute(mgemm_kernel<3>, cudaFuncAttributeMaxDynamicSharedMemorySize, MG_DSM);
    cudaFuncSetAttribute(mgemm_kernel<4>, cudaFuncAttributeMaxDynamicSharedMemorySize, MG_DSM);

    // launches 0,1,2: init
    initw_kernel<<<(unsigned)((NPAIRS + 255) / 256), 256>>>(wq, wk, wv, wo, w1, w2, p_w16);
    inith_kernel<<<(unsigned)((NCOPY4 + 255) / 256), 256>>>(x, p_h);
    initb_kernel<<<(LL * NQKV + 255) / 256, 256>>>(bq, bk, bv, p_bqkv);

    const dim3 blk(256);
    const dim3 grid_qkv(NQKV / 128, MR / 128);          // 18 x 64
    const dim3 grid_proj(HH / 128, MR / 128);           // 6 x 64
    const dim3 grid_ff1(FF_ / 128, MR / 128);           // 24 x 64
    const dim3 grid_fa(SS / 128, BB * NH_);

    for (int l = 0; l < LL; l++) {
        // layer launches: ln(3), qkv(4), flash(5 on first layer) ...
        ln_kernel<<<MR, blk>>>(p_h, ln1_g + l * HH, ln1_b + l * HH, p_y, nullptr);
        mgemm_kernel<6><<<grid_qkv, blk, MG_DSM>>>(p_y, wqkv16 + (size_t)l * HH * NQKV,
                                                   p_bqkv + (size_t)l * NQKV,
                                                   nullptr, p_qkv, HH, NQKV, SCALE_Q);
        flash_kernel<<<grid_fa, blk>>>(p_qkv, p_qkv + QKV_STRIDE, p_qkv + 2 * QKV_STRIDE,
                                       attn_bias, p_attn);
        mgemm_kernel<3><<<grid_proj, blk, MG_DSM>>>(p_attn, wo16 + (size_t)l * HHxHH, bo + l * HH,
                                                    p_h, nullptr, HH, HH, 1.f);
        ln_kernel<<<MR, blk>>>(p_h, ln2_g + l * HH, ln2_b + l * HH, p_y, nullptr);
        mgemm_kernel<4><<<grid_ff1, blk, MG_DSM>>>(p_y, w116 + (size_t)l * HHxFF, b1 + l * FF_,
                                                   nullptr, p_ff, HH, FF_, 1.f);
        mgemm_kernel<3><<<grid_proj, blk, MG_DSM>>>(p_ff, w216 + (size_t)l * HHxFF, b2 + l * HH,
                                                    p_h, nullptr, FF_, HH, 1.f);
    }
    ln_kernel<<<MR, blk>>>(p_h, fln_g, fln_b, nullptr, out);
}

// round 12
// speedup vs baseline: 3.2977x; 1.4719x over previous
#include <cuda_runtime.h>
#include <cuda_fp16.h>
#include <cstdint>

// ---------------- problem constants ----------------
#define BB   16
#define SS   512
#define HH   768
#define NH_  12
#define DD   64
#define FF_  3072
#define LL   4
#define MR   (BB*SS)
#define SCALE_Q 0.125f
#define LN_EPS 1e-5f

#define HHxHH   (HH*HH)
#define HHxFF   (HH*FF_)
#define NQKV    (3*HH)                 // 2304
#define QKV_STRIDE ((size_t)MR*HH)
#define NBIAS   ((size_t)BB*NH_*SS*SS) // 50331648

// ---------------- scratch ----------------
__device__ __align__(16) float  g_h[(size_t)MR*HH];
__device__ __align__(16) __half g_y[(size_t)MR*HH];
__device__ __align__(16) __half g_qkv[(size_t)3*MR*HH];      // q|k|v each [B,NH,S,D]
__device__ __align__(16) __half g_attn[(size_t)MR*HH];       // [B,S,H]
__device__ __align__(16) __half g_ff[(size_t)MR*FF_];
__device__ __align__(16) __half g_bias16[NBIAS];             // fp16 attn_bias
// weights fp16: [ wqkv (L x 768 x 2304) | wo | w1 | w2 ]
__device__ __align__(16) __half g_w16[(size_t)LL*(4*HHxHH + 2*HHxFF)];
__device__ __align__(16) float  g_bqkv[(size_t)LL*NQKV];

#define OFF_QKV ((size_t)0)
#define OFF_WO  ((size_t)3*LL*HHxHH)
#define OFF_W1  ((size_t)4*LL*HHxHH)
#define OFF_W2  ((size_t)4*LL*HHxHH + (size_t)LL*HHxFF)

// ---------------- init kernels ----------------
#define NPAIRS ((size_t)LL*(4*HHxHH + 2*HHxFF)/2)
#define NCOPY4 ((size_t)MR*HH/4)

__global__ void initw_kernel(
    const float* __restrict__ wq, const float* __restrict__ wk,
    const float* __restrict__ wv, const float* __restrict__ wo,
    const float* __restrict__ w1, const float* __restrict__ w2,
    __half* __restrict__ dst)
{
    const size_t NP = (size_t)LL * HHxHH / 2;
    const size_t NF = (size_t)LL * HHxFF / 2;
    size_t i = (size_t)blockIdx.x * blockDim.x + threadIdx.x;
    if (i >= NPAIRS) return;
    const float* src; size_t off, dpi;
    if (i < 3 * NP) {                  // wq/wk/wv -> concatenated qkv layout
        size_t g = i / NP; off = i - g * NP;
        src = (g == 0) ? wq : (g == 1) ? wk : wv;
        size_t l  = off / (HHxHH / 2);
        size_t r  = off - l * (HHxHH / 2);
        size_t k  = r / (HH / 2);
        size_t nc = r - k * (HH / 2);
        dpi = l * ((size_t)HH * NQKV / 2) + k * (NQKV / 2) + g * (HH / 2) + nc;
    } else {
        dpi = i;
        if (i < 4 * NP) { src = wo; off = i - 3 * NP; }
        else {
            size_t j = i - 4 * NP;
            size_t g = j / NF; off = j - g * NF;
            src = g ? w2 : w1;
        }
    }
    float2 f = reinterpret_cast<const float2*>(src)[off];
    reinterpret_cast<__half2*>(dst)[dpi] = __floats2half2_rn(f.x, f.y);
}

__global__ void inith_kernel(const float* __restrict__ x, float* __restrict__ h) {
    size_t i = (size_t)blockIdx.x * blockDim.x + threadIdx.x;
    if (i < NCOPY4)
        reinterpret_cast<float4*>(h)[i] = reinterpret_cast<const float4*>(x)[i];
}

__global__ void initb_kernel(const float* __restrict__ bq, const float* __restrict__ bk,
                             const float* __restrict__ bv, float* __restrict__ dst) {
    int i = blockIdx.x * blockDim.x + threadIdx.x;
    if (i >= LL * NQKV) return;
    int l = i / NQKV, n = i - l * NQKV;
    float v = (n < HH) ? bq[l * HH + n]
            : (n < 2 * HH) ? bk[l * HH + n - HH]
            : bv[l * HH + n - 2 * HH];
    dst[i] = v;
}

// attn_bias fp32 -> fp16 (one pass; reused by all 4 layers)
__global__ void initab_kernel(const float* __restrict__ src, __half* __restrict__ dst) {
    size_t i = (size_t)blockIdx.x * blockDim.x + threadIdx.x;
    if (i < NBIAS / 2) {
        float2 f = reinterpret_cast<const float2*>(src)[i];
        reinterpret_cast<__half2*>(dst)[i] = __floats2half2_rn(f.x, f.y);
    }
}

// ---------------- LayerNorm ----------------
__global__ __launch_bounds__(256) void ln_kernel(
    const float* __restrict__ in, const float* __restrict__ g, const float* __restrict__ b,
    __half* __restrict__ outH, float* __restrict__ outF)
{
    const int row = blockIdx.x;
    const float* x = in + (size_t)row * HH;
    const int t = threadIdx.x;

    float v[3], s = 0.f, s2 = 0.f;
#pragma unroll
    for (int i = 0; i < 3; i++) {
        float xv = x[t + i * 256];
        v[i] = xv; s += xv; s2 += xv * xv;
    }
#pragma unroll
    for (int o = 16; o; o >>= 1) {
        s  += __shfl_xor_sync(0xffffffffu, s,  o);
        s2 += __shfl_xor_sync(0xffffffffu, s2, o);
    }
    __shared__ float r1[8], r2[8];
    __shared__ float mean_s, rstd_s;
    if ((t & 31) == 0) { r1[t >> 5] = s; r2[t >> 5] = s2; }
    __syncthreads();
    if (t == 0) {
        float ss = 0.f, ss2 = 0.f;
#pragma unroll
        for (int i = 0; i < 8; i++) { ss += r1[i]; ss2 += r2[i]; }
        float mean = ss * (1.f / HH);
        float var  = ss2 * (1.f / HH) - mean * mean;
        mean_s = mean;
        rstd_s = rsqrtf(var + LN_EPS);
    }
    __syncthreads();
    const float mean = mean_s, rstd = rstd_s;
#pragma unroll
    for (int i = 0; i < 3; i++) {
        int idx = t + i * 256;
        float o = (v[i] - mean) * rstd * g[idx] + b[idx];
        if (outH) outH[(size_t)row * HH + idx] = __float2half_rn(o);
        else      outF[(size_t)row * HH + idx] = o;
    }
}

// ---------------- asm helpers ----------------
__device__ __forceinline__ void cp16(void* smem, const void* gmem) {
    unsigned sa = (unsigned)__cvta_generic_to_shared(smem);
    asm volatile("cp.async.cg.shared.global [%0], [%1], 16;\n" :: "r"(sa), "l"(gmem));
}
__device__ __forceinline__ void cp_commit() { asm volatile("cp.async.commit_group;\n"); }
__device__ __forceinline__ unsigned smem_u32(const void* p) {
    return (unsigned)__cvta_generic_to_shared(p);
}
__device__ __forceinline__ uint32_t h2_as_u32(__half2 h) {
    return *reinterpret_cast<uint32_t*>(&h);
}
__device__ __forceinline__ void ldsm4(uint32_t& r0, uint32_t& r1, uint32_t& r2, uint32_t& r3,
                                      unsigned addr) {
    asm volatile("ldmatrix.sync.aligned.m8n8.x4.shared.b16 {%0,%1,%2,%3}, [%4];"
                 : "=r"(r0), "=r"(r1), "=r"(r2), "=r"(r3) : "r"(addr));
}
__device__ __forceinline__ void ldsm4t(uint32_t& r0, uint32_t& r1, uint32_t& r2, uint32_t& r3,
                                       unsigned addr) {
    asm volatile("ldmatrix.sync.aligned.m8n8.x4.trans.shared.b16 {%0,%1,%2,%3}, [%4];"
                 : "=r"(r0), "=r"(r1), "=r"(r2), "=r"(r3) : "r"(addr));
}
__device__ __forceinline__ void mma16816(float& d0, float& d1, float& d2, float& d3,
                                         uint32_t a0, uint32_t a1, uint32_t a2, uint32_t a3,
                                         uint32_t b0, uint32_t b1) {
    asm volatile(
        "mma.sync.aligned.m16n8k16.row.col.f32.f16.f16.f32 "
        "{%0,%1,%2,%3}, {%4,%5,%6,%7}, {%8,%9}, {%0,%1,%2,%3};"
        : "+f"(d0), "+f"(d1), "+f"(d2), "+f"(d3)
        : "r"(a0), "r"(a1), "r"(a2), "r"(a3), "r"(b0), "r"(b1));
}

// ---------------- flash attention: 1 CTA per (qtile=128, b*NH), 2 CTAs/SM ----------------
__global__ __launch_bounds__(256, 2) void flash_kernel(
    const __half* __restrict__ qg, const __half* __restrict__ kg,
    const __half* __restrict__ vg, const __half* __restrict__ biasg,
    __half* __restrict__ outH)
{
    __shared__ __align__(16) __half Qs[128 * 64];
    __shared__ __align__(16) __half Ks[2][64 * 64];
    __shared__ __align__(16) __half Vs[2][64 * 64];

    const int t = threadIdx.x, w = t >> 5, lane = t & 31;
    const int z = blockIdx.y;
    const int b = z / NH_, hh = z - b * NH_;
    const int q0 = blockIdx.x * 128;

    const __half* Qg = qg + (size_t)z * SS * DD + (size_t)q0 * DD;
    const __half* Kg = kg + (size_t)z * SS * DD;
    const __half* Vg = vg + (size_t)z * SS * DD;
    const __half* Bg = biasg + (size_t)z * SS * SS + (size_t)q0 * SS;

    const unsigned sQ = smem_u32(Qs);
    const unsigned sK[2] = { smem_u32(Ks[0]), smem_u32(Ks[1]) };
    const unsigned sV[2] = { smem_u32(Vs[0]), smem_u32(Vs[1]) };

    auto loadQ = [&]() {
#pragma unroll
        for (int j = 0; j < 4; j++) {
            int idx = t + j * 256;
            int r = idx >> 3, c = idx & 7;
            cp16((char*)Qs + r * 128 + ((c ^ (r & 7)) << 4), Qg + (size_t)r * DD + c * 8);
        }
    };
    auto loadKV = [&](int s, int chunk) {
        const __half* kc = Kg + (size_t)chunk * 64 * DD;
        const __half* vc = Vg + (size_t)chunk * 64 * DD;
#pragma unroll
        for (int j = 0; j < 2; j++) {
            int idx = t + j * 256;
            int r = idx >> 3, c = idx & 7;
            cp16((char*)Ks[s] + r * 128 + ((c ^ (r & 7)) << 4), kc + (size_t)r * DD + c * 8);
        }
#pragma unroll
        for (int j = 0; j < 2; j++) {
            int idx = t + j * 256;
            int r = idx >> 3, c = idx & 7;
            cp16((char*)Vs[s] + r * 128 + ((c ^ (r & 7)) << 4), vc + (size_t)r * DD + c * 8);
        }
    };

    loadQ(); loadKV(0, 0); cp_commit();
    loadKV(1, 1); cp_commit();

    float m0 = -1e30f, m1 = -1e30f, l0 = 0.f, l1 = 0.f;
    float o[8][4];
#pragma unroll
    for (int i = 0; i < 8; i++)
#pragma unroll
        for (int k = 0; k < 4; k++) o[i][k] = 0.f;

    asm volatile("cp.async.wait_group 1;\n");
    __syncthreads();
    uint32_t aq[4][4];
    {
        const int qrow = w * 16 + (lane & 15);
#pragma unroll
        for (int ks = 0; ks < 4; ks++) {
            int kch = ks * 2 + (lane >> 4);
            ldsm4(aq[ks][0], aq[ks][1], aq[ks][2], aq[ks][3],
                  sQ + qrow * 128 + ((kch ^ (qrow & 7)) << 4));
        }
    }

    const int r0g = w * 16 + (lane >> 2);
    const int cb2 = (lane & 3) * 2;

    for (int ch = 0; ch < 8; ch++) {
        if (ch > 0) {
            if (ch < 7) { asm volatile("cp.async.wait_group 1;\n"); }
            else        { asm volatile("cp.async.wait_group 0;\n"); }
            __syncthreads();
        }
        const int s = ch & 1;

        // ---- S accumulator initialized with bias (fp16 loads) ----
        float sc[8][4];
        {
            const __half* bp0 = Bg + (size_t)r0g * SS + ch * 64 + cb2;
            const __half* bp1 = bp0 + 8 * SS;
#pragma unroll
            for (int nj = 0; nj < 8; nj++) {
                float2 bv0 = __half22float2(*reinterpret_cast<const __half2*>(bp0 + nj * 8));
                float2 bv1 = __half22float2(*reinterpret_cast<const __half2*>(bp1 + nj * 8));
                sc[nj][0] = bv0.x; sc[nj][1] = bv0.y;
                sc[nj][2] = bv1.x; sc[nj][3] = bv1.y;
            }
        }

        // ---- S += Q @ K^T ----
#pragma unroll
        for (int ks = 0; ks < 4; ks++) {
#pragma unroll
            for (int ng = 0; ng < 4; ng++) {
                int nrow = ng * 16 + (lane & 15);
                int kch = ks * 2 + (lane >> 4);
                uint32_t r0, r1, r2, r3;
                ldsm4(r0, r1, r2, r3, sK[s] + nrow * 128 + ((kch ^ (nrow & 7)) << 4));
                mma16816(sc[ng*2][0], sc[ng*2][1], sc[ng*2][2], sc[ng*2][3],
                         aq[ks][0], aq[ks][1], aq[ks][2], aq[ks][3], r0, r2);
                mma16816(sc[ng*2+1][0], sc[ng*2+1][1], sc[ng*2+1][2], sc[ng*2+1][3],
                         aq[ks][0], aq[ks][1], aq[ks][2], aq[ks][3], r1, r3);
            }
        }

        // ---- online softmax ----
        float rm0 = -1e30f, rm1 = -1e30f;
#pragma unroll
        for (int nj = 0; nj < 8; nj++) {
            rm0 = fmaxf(rm0, fmaxf(sc[nj][0], sc[nj][1]));
            rm1 = fmaxf(rm1, fmaxf(sc[nj][2], sc[nj][3]));
        }
        rm0 = fmaxf(rm0, __shfl_xor_sync(0xffffffffu, rm0, 1));
        rm0 = fmaxf(rm0, __shfl_xor_sync(0xffffffffu, rm0, 2));
        rm1 = fmaxf(rm1, __shfl_xor_sync(0xffffffffu, rm1, 1));
        rm1 = fmaxf(rm1, __shfl_xor_sync(0xffffffffu, rm1, 2));

        float nm0 = fmaxf(m0, rm0), nm1 = fmaxf(m1, rm1);
        float al0 = __expf(m0 - nm0), al1 = __expf(m1 - nm1);
        m0 = nm0; m1 = nm1;

        uint32_t h0[8], h1[8];
        float rs0 = 0.f, rs1 = 0.f;
#pragma unroll
        for (int nj = 0; nj < 8; nj++) {
            float e0 = __expf(sc[nj][0] - nm0);
            float e1 = __expf(sc[nj][1] - nm0);
            float e2 = __expf(sc[nj][2] - nm1);
            float e3 = __expf(sc[nj][3] - nm1);
            rs0 += e0 + e1; rs1 += e2 + e3;
            h0[nj] = h2_as_u32(__floats2half2_rn(e0, e1));
            h1[nj] = h2_as_u32(__floats2half2_rn(e2, e3));
        }
        rs0 += __shfl_xor_sync(0xffffffffu, rs0, 1);
        rs0 += __shfl_xor_sync(0xffffffffu, rs0, 2);
        rs1 += __shfl_xor_sync(0xffffffffu, rs1, 1);
        rs1 += __shfl_xor_sync(0xffffffffu, rs1, 2);
        l0 = l0 * al0 + rs0;
        l1 = l1 * al1 + rs1;
#pragma unroll
        for (int i = 0; i < 8; i++) {
            o[i][0] *= al0; o[i][1] *= al0;
            o[i][2] *= al1; o[i][3] *= al1;
        }

        // ---- O += P @ V ----
#pragma unroll
        for (int j = 0; j < 4; j++) {
#pragma unroll
            for (int pr = 0; pr < 4; pr++) {
                int kk = j * 16 + (lane & 15);
                int nch = pr * 2 + (lane >> 4);
                uint32_t r0, r1, r2, r3;
                ldsm4t(r0, r1, r2, r3, sV[s] + kk * 128 + ((nch ^ (kk & 7)) << 4));
                mma16816(o[pr*2][0], o[pr*2][1], o[pr*2][2], o[pr*2][3],
                         h0[2*j], h1[2*j], h0[2*j+1], h1[2*j+1], r0, r1);
                mma16816(o[pr*2+1][0], o[pr*2+1][1], o[pr*2+1][2], o[pr*2+1][3],
                         h0[2*j], h1[2*j], h0[2*j+1], h1[2*j+1], r2, r3);
            }
        }
        __syncthreads();
        if (ch + 2 < 8) { loadKV(s, ch + 2); cp_commit(); }
        else if (ch < 7) { cp_commit(); }
    }

    // ---- epilogue ----
    const float inv0 = 1.f / l0, inv1 = 1.f / l1;
    const int row0 = q0 + r0g;
    const int col0 = hh * DD + cb2;
    __half* o0 = outH + ((size_t)(b * SS) + row0) * HH + col0;
    __half* o1 = o0 + 8 * HH;
#pragma unroll
    for (int pj = 0; pj < 8; pj++) {
        *reinterpret_cast<__half2*>(o0 + pj * 8) = __floats2half2_rn(o[pj][0] * inv0, o[pj][1] * inv0);
        *reinterpret_cast<__half2*>(o1 + pj * 8) = __floats2half2_rn(o[pj][2] * inv1, o[pj][3] * inv1);
    }
}

// ---------------- mma.sync GEMM: 128x128 tile, BK=32, 8 warps, 4-stage ----------------
// Epilogues: 6 QKV-fused scatter, 3 residual +=, 4 GELU.
#define MG_STAGES 4
#define MG_ASTG   8192
#define MG_BSTG   8192
#define MG_DSM    66560

template<int EPI>
__global__ __launch_bounds__(256, 2) void mgemm_kernel(
    const __half* __restrict__ Ag, const __half* __restrict__ Bg,
    const float* __restrict__ bias,
    float* __restrict__ outF, __half* __restrict__ outH,
    int K, int N, float oscale)
{
    extern __shared__ __align__(16) char dyn[];
    const unsigned sb = smem_u32(dyn);
    float* stg = reinterpret_cast<float*>(dyn);

    const int t = threadIdx.x, w = t >> 5, lane = t & 31;
    const int wm = w >> 2, wn = w & 3;
    const __half* A = Ag + (size_t)blockIdx.y * 128 * K;
    const int n0 = blockIdx.x * 128;

    float d[4][4][4];
#pragma unroll
    for (int i = 0; i < 4; i++)
#pragma unroll
        for (int j = 0; j < 4; j++)
#pragma unroll
            for (int k = 0; k < 4; k++) d[i][j][k] = 0.f;

    unsigned aoff[2][4], boff[2][2];
#pragma unroll
    for (int ks = 0; ks < 2; ks++) {
#pragma unroll
        for (int mi = 0; mi < 4; mi++) {
            int row = wm * 64 + mi * 16 + (lane & 15);
            int kch = ks * 2 + (lane >> 4);
            aoff[ks][mi] = (unsigned)(row * 64 + ((kch ^ ((row >> 1) & 3)) << 4));
        }
#pragma unroll
        for (int pj = 0; pj < 2; pj++) {
            int kk = ks * 16 + (lane & 15);
            int nch = wn * 4 + pj * 2 + (lane >> 4);
            boff[ks][pj] = (unsigned)(kk * 256 + ((nch ^ (kk & 7)) << 4));
        }
    }

    auto load_tiles = [&](int s, int k0) {
        char* as = dyn + s * MG_ASTG;
        char* bs = dyn + MG_STAGES * MG_ASTG + s * MG_BSTG;
#pragma unroll
        for (int i = 0; i < 2; i++) {
            int idx = t + i * 256;
            int r = idx >> 2, c = idx & 3;
            cp16(as + r * 64 + ((c ^ ((r >> 1) & 3)) << 4), A + (size_t)r * K + k0 + c * 8);
        }
#pragma unroll
        for (int i = 0; i < 2; i++) {
            int idx = t + i * 256;
            int k = idx >> 4, c = idx & 15;
            cp16(bs + k * 256 + ((c ^ (k & 7)) << 4), Bg + (size_t)(k0 + k) * N + n0 + c * 8);
        }
    };

    const int nk = K >> 5;
#pragma unroll
    for (int i = 0; i < MG_STAGES - 1; i++) {
        if (i < nk) load_tiles(i, i * 32);
        cp_commit();
    }

    for (int kt = 0; kt < nk; kt++) {
        asm volatile("cp.async.wait_group %0;\n" :: "n"(MG_STAGES - 2));
        __syncthreads();
        {
            int kn = kt + MG_STAGES - 1;
            if (kn < nk) load_tiles(kn & (MG_STAGES - 1), kn * 32);
            cp_commit();
        }
        const int s = kt & (MG_STAGES - 1);
        const unsigned abase = sb + s * MG_ASTG;
        const unsigned bbase = sb + MG_STAGES * MG_ASTG + s * MG_BSTG;

#pragma unroll
        for (int ks = 0; ks < 2; ks++) {
            uint32_t a[4][4], b[2][4];
#pragma unroll
            for (int mi = 0; mi < 4; mi++)
                ldsm4(a[mi][0], a[mi][1], a[mi][2], a[mi][3], abase + aoff[ks][mi]);
#pragma unroll
            for (int pj = 0; pj < 2; pj++)
                ldsm4t(b[pj][0], b[pj][1], b[pj][2], b[pj][3], bbase + boff[ks][pj]);
#pragma unroll
            for (int mi = 0; mi < 4; mi++)
#pragma unroll
                for (int nj = 0; nj < 4; nj++)
                    mma16816(d[mi][nj][0], d[mi][nj][1], d[mi][nj][2], d[mi][nj][3],
                             a[mi][0], a[mi][1], a[mi][2], a[mi][3],
                             b[nj >> 1][(nj & 1) * 2], b[nj >> 1][(nj & 1) * 2 + 1]);
        }
    }
    __syncthreads();

    // ---- staging (stride 129) ----
    const int qr = lane >> 2, qc = (lane & 3) * 2;
#pragma unroll
    for (int mi = 0; mi < 4; mi++) {
#pragma unroll
        for (int nj = 0; nj < 4; nj++) {
            int r0 = wm * 64 + mi * 16 + qr;
            int c0 = wn * 32 + nj * 8 + qc;
            stg[r0 * 129 + c0]           = d[mi][nj][0];
            stg[r0 * 129 + c0 + 1]       = d[mi][nj][1];
            stg[(r0 + 8) * 129 + c0]     = d[mi][nj][2];
            stg[(r0 + 8) * 129 + c0 + 1] = d[mi][nj][3];
        }
    }
    __syncthreads();

    const int gi0 = blockIdx.y * 128;
    const int gj0 = blockIdx.x * 128;

#pragma unroll
    for (int it = 0; it < 32; it++) {
        int idx = t + it * 256;
        int rr = idx >> 6;
        int c2 = (idx & 63) * 2;
        int gi = gi0 + rr, gj = gj0 + c2;
        float a0 = stg[rr * 129 + c2];
        float a1 = stg[rr * 129 + c2 + 1];

        if (EPI == 6) {
            int which = gj / HH;
            int col = gj - which * HH;
            float f = (which == 0) ? oscale : 1.f;
            float v0 = (a0 + bias[gj]) * f;
            float v1 = (a1 + bias[gj + 1]) * f;
            int bb = gi >> 9, ss2 = gi & 511, hhh = col >> 6, dd = col & 63;
            *reinterpret_cast<__half2*>(
                &outH[(size_t)which * QKV_STRIDE +
                      (((size_t)(bb * NH_ + hhh) * SS + ss2) << 6) + dd]) =
                __floats2half2_rn(v0, v1);
        } else if (EPI == 3) {
            float* dst = &outF[(size_t)gi * N + gj];
            float2 old = *reinterpret_cast<float2*>(dst);
            old.x += a0 + bias[gj];
            old.y += a1 + bias[gj + 1];
            *reinterpret_cast<float2*>(dst) = old;
        } else { // EPI == 4
            float x0 = a0 + bias[gj];
            float x1 = a1 + bias[gj + 1];
            float g0 = 0.5f * x0 * (1.f + erff(x0 * 0.70710678118654752f));
            float g1 = 0.5f * x1 * (1.f + erff(x1 * 0.70710678118654752f));
            *reinterpret_cast<__half2*>(&outH[(size_t)gi * N + gj]) =
                __floats2half2_rn(g0, g1);
        }
    }
}

// ---------------- host ----------------
extern "C" void kernel_launch(void* const* d_in, const int* in_sizes, int n_in,
                              void* d_out, int out_size)
{
    const float* x         = (const float*)d_in[0];
    const float* attn_bias = (const float*)d_in[1];
    const float* ln1_g = (const float*)d_in[2];
    const float* ln1_b = (const float*)d_in[3];
    const float* wq = (const float*)d_in[4];
    const float* bq = (const float*)d_in[5];
    const float* wk = (const float*)d_in[6];
    const float* bk = (const float*)d_in[7];
    const float* wv = (const float*)d_in[8];
    const float* bv = (const float*)d_in[9];
    const float* wo = (const float*)d_in[10];
    const float* bo = (const float*)d_in[11];
    const float* ln2_g = (const float*)d_in[12];
    const float* ln2_b = (const float*)d_in[13];
    const float* w1 = (const float*)d_in[14];
    const float* b1 = (const float*)d_in[15];
    const float* w2 = (const float*)d_in[16];
    const float* b2 = (const float*)d_in[17];
    const float* fln_g = (const float*)d_in[18];
    const float* fln_b = (const float*)d_in[19];
    float* out = (float*)d_out;

    void* pv_ = nullptr;
    cudaGetSymbolAddress(&pv_, g_h);      float*  p_h    = (float*)pv_;
    cudaGetSymbolAddress(&pv_, g_y);      __half* p_y    = (__half*)pv_;
    cudaGetSymbolAddress(&pv_, g_qkv);    __half* p_qkv  = (__half*)pv_;
    cudaGetSymbolAddress(&pv_, g_attn);   __half* p_attn = (__half*)pv_;
    cudaGetSymbolAddress(&pv_, g_ff);     __half* p_ff   = (__half*)pv_;
    cudaGetSymbolAddress(&pv_, g_bias16); __half* p_b16  = (__half*)pv_;
    cudaGetSymbolAddress(&pv_, g_w16);    __half* p_w16  = (__half*)pv_;
    cudaGetSymbolAddress(&pv_, g_bqkv);   float*  p_bqkv = (float*)pv_;

    __half* wqkv16 = p_w16 + OFF_QKV;
    __half* wo16   = p_w16 + OFF_WO;
    __half* w116   = p_w16 + OFF_W1;
    __half* w216   = p_w16 + OFF_W2;

    cudaFuncSetAttribute(mgemm_kernel<6>, cudaFuncAttributeMaxDynamicSharedMemorySize, MG_DSM);
    cudaFuncSetAttribute(mgemm_kernel<3>, cudaFuncAttributeMaxDynamicSharedMemorySize, MG_DSM);
    cudaFuncSetAttribute(mgemm_kernel<4>, cudaFuncAttributeMaxDynamicSharedMemorySize, MG_DSM);

    // init launches
    initw_kernel<<<(unsigned)((NPAIRS + 255) / 256), 256>>>(wq, wk, wv, wo, w1, w2, p_w16);
    inith_kernel<<<(unsigned)((NCOPY4 + 255) / 256), 256>>>(x, p_h);
    initb_kernel<<<(LL * NQKV + 255) / 256, 256>>>(bq, bk, bv, p_bqkv);
    initab_kernel<<<(unsigned)((NBIAS / 2 + 255) / 256), 256>>>(attn_bias, p_b16);

    const dim3 blk(256);
    const dim3 grid_qkv(NQKV / 128, MR / 128);          // 18 x 64
    const dim3 grid_proj(HH / 128, MR / 128);           // 6 x 64
    const dim3 grid_ff1(FF_ / 128, MR / 128);           // 24 x 64
    const dim3 grid_fa(SS / 128, BB * NH_);

    for (int l = 0; l < LL; l++) {
        ln_kernel<<<MR, blk>>>(p_h, ln1_g + l * HH, ln1_b + l * HH, p_y, nullptr);
        mgemm_kernel<6><<<grid_qkv, blk, MG_DSM>>>(p_y, wqkv16 + (size_t)l * HH * NQKV,
                                                   p_bqkv + (size_t)l * NQKV,
                                                   nullptr, p_qkv, HH, NQKV, SCALE_Q);
        flash_kernel<<<grid_fa, blk>>>(p_qkv, p_qkv + QKV_STRIDE, p_qkv + 2 * QKV_STRIDE,
                                       p_b16, p_attn);
        mgemm_kernel<3><<<grid_proj, blk, MG_DSM>>>(p_attn, wo16 + (size_t)l * HHxHH, bo + l * HH,
                                                    p_h, nullptr, HH, HH, 1.f);
        ln_kernel<<<MR, blk>>>(p_h, ln2_g + l * HH, ln2_b + l * HH, p_y, nullptr);
        mgemm_kernel<4><<<grid_ff1, blk, MG_DSM>>>(p_y, w116 + (size_t)l * HHxFF, b1 + l * FF_,
                                                   nullptr, p_ff, HH, FF_, 1.f);
        mgemm_kernel<3><<<grid_proj, blk, MG_DSM>>>(p_ff, w216 + (size_t)l * HHxFF, b2 + l * HH,
                                                    p_h, nullptr, FF_, HH, 1.f);
    }
    ln_kernel<<<MR, blk>>>(p_h, fln_g, fln_b, nullptr, out);
}

// round 13
// speedup vs baseline: 3.5090x; 1.0641x over previous
#include <cuda_runtime.h>
#include <cuda_fp16.h>
#include <cstdint>

// ---------------- problem constants ----------------
#define BB   16
#define SS   512
#define HH   768
#define NH_  12
#define DD   64
#define FF_  3072
#define LL   4
#define MR   (BB*SS)
#define SCALE_Q 0.125f
#define LN_EPS 1e-5f

#define HHxHH   (HH*HH)
#define HHxFF   (HH*FF_)
#define NQKV    (3*HH)                 // 2304
#define QKV_STRIDE ((size_t)MR*HH)
#define NBIAS   ((size_t)BB*NH_*SS*SS)

// ---------------- scratch ----------------
__device__ __align__(16) float  g_h[(size_t)MR*HH];
__device__ __align__(16) __half g_y[(size_t)MR*HH];
__device__ __align__(16) __half g_qkv[(size_t)3*MR*HH];      // q|k|v each [B,NH,S,D]
__device__ __align__(16) __half g_attn[(size_t)MR*HH];       // [B,S,H]
__device__ __align__(16) __half g_ff[(size_t)MR*FF_];
__device__ __align__(16) __half g_bias16[NBIAS];             // fp16 attn_bias
__device__ __align__(16) __half g_w16[(size_t)LL*(4*HHxHH + 2*HHxFF)];
__device__ __align__(16) float  g_bqkv[(size_t)LL*NQKV];

#define OFF_QKV ((size_t)0)
#define OFF_WO  ((size_t)3*LL*HHxHH)
#define OFF_W1  ((size_t)4*LL*HHxHH)
#define OFF_W2  ((size_t)4*LL*HHxHH + (size_t)LL*HHxFF)

// ---------------- init kernels ----------------
#define NPAIRS ((size_t)LL*(4*HHxHH + 2*HHxFF)/2)
#define NCOPY4 ((size_t)MR*HH/4)

__global__ void initw_kernel(
    const float* __restrict__ wq, const float* __restrict__ wk,
    const float* __restrict__ wv, const float* __restrict__ wo,
    const float* __restrict__ w1, const float* __restrict__ w2,
    __half* __restrict__ dst)
{
    const size_t NP = (size_t)LL * HHxHH / 2;
    const size_t NF = (size_t)LL * HHxFF / 2;
    size_t i = (size_t)blockIdx.x * blockDim.x + threadIdx.x;
    if (i >= NPAIRS) return;
    const float* src; size_t off, dpi;
    if (i < 3 * NP) {
        size_t g = i / NP; off = i - g * NP;
        src = (g == 0) ? wq : (g == 1) ? wk : wv;
        size_t l  = off / (HHxHH / 2);
        size_t r  = off - l * (HHxHH / 2);
        size_t k  = r / (HH / 2);
        size_t nc = r - k * (HH / 2);
        dpi = l * ((size_t)HH * NQKV / 2) + k * (NQKV / 2) + g * (HH / 2) + nc;
    } else {
        dpi = i;
        if (i < 4 * NP) { src = wo; off = i - 3 * NP; }
        else {
            size_t j = i - 4 * NP;
            size_t g = j / NF; off = j - g * NF;
            src = g ? w2 : w1;
        }
    }
    float2 f = reinterpret_cast<const float2*>(src)[off];
    reinterpret_cast<__half2*>(dst)[dpi] = __floats2half2_rn(f.x, f.y);
}

__global__ void inith_kernel(const float* __restrict__ x, float* __restrict__ h) {
    size_t i = (size_t)blockIdx.x * blockDim.x + threadIdx.x;
    if (i < NCOPY4)
        reinterpret_cast<float4*>(h)[i] = reinterpret_cast<const float4*>(x)[i];
}

__global__ void initb_kernel(const float* __restrict__ bq, const float* __restrict__ bk,
                             const float* __restrict__ bv, float* __restrict__ dst) {
    int i = blockIdx.x * blockDim.x + threadIdx.x;
    if (i >= LL * NQKV) return;
    int l = i / NQKV, n = i - l * NQKV;
    float v = (n < HH) ? bq[l * HH + n]
            : (n < 2 * HH) ? bk[l * HH + n - HH]
            : bv[l * HH + n - 2 * HH];
    dst[i] = v;
}

__global__ void initab_kernel(const float* __restrict__ src, __half* __restrict__ dst) {
    size_t i = (size_t)blockIdx.x * blockDim.x + threadIdx.x;
    if (i < NBIAS / 2) {
        float2 f = reinterpret_cast<const float2*>(src)[i];
        reinterpret_cast<__half2*>(dst)[i] = __floats2half2_rn(f.x, f.y);
    }
}

// ---------------- LayerNorm: warp-per-row, 8 rows/block, shfl-only ----------------
__global__ __launch_bounds__(256) void ln_kernel(
    const float* __restrict__ in, const float* __restrict__ g, const float* __restrict__ b,
    __half* __restrict__ outH, float* __restrict__ outF)
{
    const int w = threadIdx.x >> 5, lane = threadIdx.x & 31;
    const int row = blockIdx.x * 8 + w;
    const float* x = in + (size_t)row * HH;

    float4 v[6];
    float s = 0.f, s2 = 0.f;
#pragma unroll
    for (int i = 0; i < 6; i++) {
        v[i] = *reinterpret_cast<const float4*>(x + lane * 4 + i * 128);
        s  += v[i].x + v[i].y + v[i].z + v[i].w;
        s2 += v[i].x * v[i].x + v[i].y * v[i].y + v[i].z * v[i].z + v[i].w * v[i].w;
    }
#pragma unroll
    for (int o = 16; o; o >>= 1) {
        s  += __shfl_xor_sync(0xffffffffu, s,  o);
        s2 += __shfl_xor_sync(0xffffffffu, s2, o);
    }
    const float mean = s * (1.f / HH);
    const float rstd = rsqrtf(s2 * (1.f / HH) - mean * mean + LN_EPS);

#pragma unroll
    for (int i = 0; i < 6; i++) {
        const int c = lane * 4 + i * 128;
        float o0 = (v[i].x - mean) * rstd * g[c]     + b[c];
        float o1 = (v[i].y - mean) * rstd * g[c + 1] + b[c + 1];
        float o2 = (v[i].z - mean) * rstd * g[c + 2] + b[c + 2];
        float o3 = (v[i].w - mean) * rstd * g[c + 3] + b[c + 3];
        if (outH) {
            __half2 p0 = __floats2half2_rn(o0, o1);
            __half2 p1 = __floats2half2_rn(o2, o3);
            uint2 pk = { *reinterpret_cast<uint32_t*>(&p0), *reinterpret_cast<uint32_t*>(&p1) };
            *reinterpret_cast<uint2*>(outH + (size_t)row * HH + c) = pk;
        } else {
            float4 ov = { o0, o1, o2, o3 };
            *reinterpret_cast<float4*>(outF + (size_t)row * HH + c) = ov;
        }
    }
}

// ---------------- asm helpers ----------------
__device__ __forceinline__ void cp16(void* smem, const void* gmem) {
    unsigned sa = (unsigned)__cvta_generic_to_shared(smem);
    asm volatile("cp.async.cg.shared.global [%0], [%1], 16;\n" :: "r"(sa), "l"(gmem));
}
__device__ __forceinline__ void cp_commit() { asm volatile("cp.async.commit_group;\n"); }
__device__ __forceinline__ unsigned smem_u32(const void* p) {
    return (unsigned)__cvta_generic_to_shared(p);
}
__device__ __forceinline__ uint32_t h2_as_u32(__half2 h) {
    return *reinterpret_cast<uint32_t*>(&h);
}
__device__ __forceinline__ void ldsm4(uint32_t& r0, uint32_t& r1, uint32_t& r2, uint32_t& r3,
                                      unsigned addr) {
    asm volatile("ldmatrix.sync.aligned.m8n8.x4.shared.b16 {%0,%1,%2,%3}, [%4];"
                 : "=r"(r0), "=r"(r1), "=r"(r2), "=r"(r3) : "r"(addr));
}
__device__ __forceinline__ void ldsm4t(uint32_t& r0, uint32_t& r1, uint32_t& r2, uint32_t& r3,
                                       unsigned addr) {
    asm volatile("ldmatrix.sync.aligned.m8n8.x4.trans.shared.b16 {%0,%1,%2,%3}, [%4];"
                 : "=r"(r0), "=r"(r1), "=r"(r2), "=r"(r3) : "r"(addr));
}
__device__ __forceinline__ void mma16816(float& d0, float& d1, float& d2, float& d3,
                                         uint32_t a0, uint32_t a1, uint32_t a2, uint32_t a3,
                                         uint32_t b0, uint32_t b1) {
    asm volatile(
        "mma.sync.aligned.m16n8k16.row.col.f32.f16.f16.f32 "
        "{%0,%1,%2,%3}, {%4,%5,%6,%7}, {%8,%9}, {%0,%1,%2,%3};"
        : "+f"(d0), "+f"(d1), "+f"(d2), "+f"(d3)
        : "r"(a0), "r"(a1), "r"(a2), "r"(a3), "r"(b0), "r"(b1));
}

// ---------------- flash attention (unchanged from R12) ----------------
__global__ __launch_bounds__(256, 2) void flash_kernel(
    const __half* __restrict__ qg, const __half* __restrict__ kg,
    const __half* __restrict__ vg, const __half* __restrict__ biasg,
    __half* __restrict__ outH)
{
    __shared__ __align__(16) __half Qs[128 * 64];
    __shared__ __align__(16) __half Ks[2][64 * 64];
    __shared__ __align__(16) __half Vs[2][64 * 64];

    const int t = threadIdx.x, w = t >> 5, lane = t & 31;
    const int z = blockIdx.y;
    const int b = z / NH_, hh = z - b * NH_;
    const int q0 = blockIdx.x * 128;

    const __half* Qg = qg + (size_t)z * SS * DD + (size_t)q0 * DD;
    const __half* Kg = kg + (size_t)z * SS * DD;
    const __half* Vg = vg + (size_t)z * SS * DD;
    const __half* Bg = biasg + (size_t)z * SS * SS + (size_t)q0 * SS;

    const unsigned sQ = smem_u32(Qs);
    const unsigned sK[2] = { smem_u32(Ks[0]), smem_u32(Ks[1]) };
    const unsigned sV[2] = { smem_u32(Vs[0]), smem_u32(Vs[1]) };

    auto loadQ = [&]() {
#pragma unroll
        for (int j = 0; j < 4; j++) {
            int idx = t + j * 256;
            int r = idx >> 3, c = idx & 7;
            cp16((char*)Qs + r * 128 + ((c ^ (r & 7)) << 4), Qg + (size_t)r * DD + c * 8);
        }
    };
    auto loadKV = [&](int s, int chunk) {
        const __half* kc = Kg + (size_t)chunk * 64 * DD;
        const __half* vc = Vg + (size_t)chunk * 64 * DD;
#pragma unroll
        for (int j = 0; j < 2; j++) {
            int idx = t + j * 256;
            int r = idx >> 3, c = idx & 7;
            cp16((char*)Ks[s] + r * 128 + ((c ^ (r & 7)) << 4), kc + (size_t)r * DD + c * 8);
        }
#pragma unroll
        for (int j = 0; j < 2; j++) {
            int idx = t + j * 256;
            int r = idx >> 3, c = idx & 7;
            cp16((char*)Vs[s] + r * 128 + ((c ^ (r & 7)) << 4), vc + (size_t)r * DD + c * 8);
        }
    };

    loadQ(); loadKV(0, 0); cp_commit();
    loadKV(1, 1); cp_commit();

    float m0 = -1e30f, m1 = -1e30f, l0 = 0.f, l1 = 0.f;
    float o[8][4];
#pragma unroll
    for (int i = 0; i < 8; i++)
#pragma unroll
        for (int k = 0; k < 4; k++) o[i][k] = 0.f;

    asm volatile("cp.async.wait_group 1;\n");
    __syncthreads();
    uint32_t aq[4][4];
    {
        const int qrow = w * 16 + (lane & 15);
#pragma unroll
        for (int ks = 0; ks < 4; ks++) {
            int kch = ks * 2 + (lane >> 4);
            ldsm4(aq[ks][0], aq[ks][1], aq[ks][2], aq[ks][3],
                  sQ + qrow * 128 + ((kch ^ (qrow & 7)) << 4));
        }
    }

    const int r0g = w * 16 + (lane >> 2);
    const int cb2 = (lane & 3) * 2;

    for (int ch = 0; ch < 8; ch++) {
        if (ch > 0) {
            if (ch < 7) { asm volatile("cp.async.wait_group 1;\n"); }
            else        { asm volatile("cp.async.wait_group 0;\n"); }
            __syncthreads();
        }
        const int s = ch & 1;

        float sc[8][4];
        {
            const __half* bp0 = Bg + (size_t)r0g * SS + ch * 64 + cb2;
            const __half* bp1 = bp0 + 8 * SS;
#pragma unroll
            for (int nj = 0; nj < 8; nj++) {
                float2 bv0 = __half22float2(*reinterpret_cast<const __half2*>(bp0 + nj * 8));
                float2 bv1 = __half22float2(*reinterpret_cast<const __half2*>(bp1 + nj * 8));
                sc[nj][0] = bv0.x; sc[nj][1] = bv0.y;
                sc[nj][2] = bv1.x; sc[nj][3] = bv1.y;
            }
        }

#pragma unroll
        for (int ks = 0; ks < 4; ks++) {
#pragma unroll
            for (int ng = 0; ng < 4; ng++) {
                int nrow = ng * 16 + (lane & 15);
                int kch = ks * 2 + (lane >> 4);
                uint32_t r0, r1, r2, r3;
                ldsm4(r0, r1, r2, r3, sK[s] + nrow * 128 + ((kch ^ (nrow & 7)) << 4));
                mma16816(sc[ng*2][0], sc[ng*2][1], sc[ng*2][2], sc[ng*2][3],
                         aq[ks][0], aq[ks][1], aq[ks][2], aq[ks][3], r0, r2);
                mma16816(sc[ng*2+1][0], sc[ng*2+1][1], sc[ng*2+1][2], sc[ng*2+1][3],
                         aq[ks][0], aq[ks][1], aq[ks][2], aq[ks][3], r1, r3);
            }
        }

        float rm0 = -1e30f, rm1 = -1e30f;
#pragma unroll
        for (int nj = 0; nj < 8; nj++) {
            rm0 = fmaxf(rm0, fmaxf(sc[nj][0], sc[nj][1]));
            rm1 = fmaxf(rm1, fmaxf(sc[nj][2], sc[nj][3]));
        }
        rm0 = fmaxf(rm0, __shfl_xor_sync(0xffffffffu, rm0, 1));
        rm0 = fmaxf(rm0, __shfl_xor_sync(0xffffffffu, rm0, 2));
        rm1 = fmaxf(rm1, __shfl_xor_sync(0xffffffffu, rm1, 1));
        rm1 = fmaxf(rm1, __shfl_xor_sync(0xffffffffu, rm1, 2));

        float nm0 = fmaxf(m0, rm0), nm1 = fmaxf(m1, rm1);
        float al0 = __expf(m0 - nm0), al1 = __expf(m1 - nm1);
        m0 = nm0; m1 = nm1;

        uint32_t h0[8], h1[8];
        float rs0 = 0.f, rs1 = 0.f;
#pragma unroll
        for (int nj = 0; nj < 8; nj++) {
            float e0 = __expf(sc[nj][0] - nm0);
            float e1 = __expf(sc[nj][1] - nm0);
            float e2 = __expf(sc[nj][2] - nm1);
            float e3 = __expf(sc[nj][3] - nm1);
            rs0 += e0 + e1; rs1 += e2 + e3;
            h0[nj] = h2_as_u32(__floats2half2_rn(e0, e1));
            h1[nj] = h2_as_u32(__floats2half2_rn(e2, e3));
        }
        rs0 += __shfl_xor_sync(0xffffffffu, rs0, 1);
        rs0 += __shfl_xor_sync(0xffffffffu, rs0, 2);
        rs1 += __shfl_xor_sync(0xffffffffu, rs1, 1);
        rs1 += __shfl_xor_sync(0xffffffffu, rs1, 2);
        l0 = l0 * al0 + rs0;
        l1 = l1 * al1 + rs1;
#pragma unroll
        for (int i = 0; i < 8; i++) {
            o[i][0] *= al0; o[i][1] *= al0;
            o[i][2] *= al1; o[i][3] *= al1;
        }

#pragma unroll
        for (int j = 0; j < 4; j++) {
#pragma unroll
            for (int pr = 0; pr < 4; pr++) {
                int kk = j * 16 + (lane & 15);
                int nch = pr * 2 + (lane >> 4);
                uint32_t r0, r1, r2, r3;
                ldsm4t(r0, r1, r2, r3, sV[s] + kk * 128 + ((nch ^ (kk & 7)) << 4));
                mma16816(o[pr*2][0], o[pr*2][1], o[pr*2][2], o[pr*2][3],
                         h0[2*j], h1[2*j], h0[2*j+1], h1[2*j+1], r0, r1);
                mma16816(o[pr*2+1][0], o[pr*2+1][1], o[pr*2+1][2], o[pr*2+1][3],
                         h0[2*j], h1[2*j], h0[2*j+1], h1[2*j+1], r2, r3);
            }
        }
        __syncthreads();
        if (ch + 2 < 8) { loadKV(s, ch + 2); cp_commit(); }
        else if (ch < 7) { cp_commit(); }
    }

    const float inv0 = 1.f / l0, inv1 = 1.f / l1;
    const int row0 = q0 + r0g;
    const int col0 = hh * DD + cb2;
    __half* o0 = outH + ((size_t)(b * SS) + row0) * HH + col0;
    __half* o1 = o0 + 8 * HH;
#pragma unroll
    for (int pj = 0; pj < 8; pj++) {
        *reinterpret_cast<__half2*>(o0 + pj * 8) = __floats2half2_rn(o[pj][0] * inv0, o[pj][1] * inv0);
        *reinterpret_cast<__half2*>(o1 + pj * 8) = __floats2half2_rn(o[pj][2] * inv1, o[pj][3] * inv1);
    }
}

// ---------------- mma.sync GEMM: 128x128 tile, BK=64, 8 warps, 3-stage ----------------
// A stage: 128 rows x 128B (swizzle c^(r&7)); B stage: 64 rows x 256B (c^(k&7)).
// Epilogues: 6 QKV-fused scatter, 3 residual +=, 4 GELU.
#define MG_STAGES 3
#define MG_ASTG   16384
#define MG_BSTG   16384
#define MG_DSM    98304

template<int EPI>
__global__ __launch_bounds__(256, 2) void mgemm_kernel(
    const __half* __restrict__ Ag, const __half* __restrict__ Bg,
    const float* __restrict__ bias,
    float* __restrict__ outF, __half* __restrict__ outH,
    int K, int N, float oscale)
{
    extern __shared__ __align__(16) char dyn[];
    const unsigned sb = smem_u32(dyn);
    float* stg = reinterpret_cast<float*>(dyn);

    const int t = threadIdx.x, w = t >> 5, lane = t & 31;
    const int wm = w >> 2, wn = w & 3;
    const __half* A = Ag + (size_t)blockIdx.y * 128 * K;
    const int n0 = blockIdx.x * 128;

    float d[4][4][4];
#pragma unroll
    for (int i = 0; i < 4; i++)
#pragma unroll
        for (int j = 0; j < 4; j++)
#pragma unroll
            for (int k = 0; k < 4; k++) d[i][j][k] = 0.f;

    auto load_tiles = [&](int s, int k0) {
        char* as = dyn + s * MG_ASTG;
        char* bs = dyn + MG_STAGES * MG_ASTG + s * MG_BSTG;
#pragma unroll
        for (int i = 0; i < 4; i++) {           // A: 128 x 64 halves = 1024 chunks
            int idx = t + i * 256;
            int r = idx >> 3, c = idx & 7;
            cp16(as + r * 128 + ((c ^ (r & 7)) << 4), A + (size_t)r * K + k0 + c * 8);
        }
#pragma unroll
        for (int i = 0; i < 4; i++) {           // B: 64 x 128 halves = 1024 chunks
            int idx = t + i * 256;
            int k = idx >> 4, c = idx & 15;
            cp16(bs + k * 256 + ((c ^ (k & 7)) << 4), Bg + (size_t)(k0 + k) * N + n0 + c * 8);
        }
    };

    const int nk = K >> 6;
    load_tiles(0, 0); cp_commit();
    if (nk > 1) load_tiles(1, 64);
    cp_commit();

    int s = 0;
    for (int kt = 0; kt < nk; kt++) {
        asm volatile("cp.async.wait_group 1;\n");
        __syncthreads();
        {
            int kn = kt + 2;
            if (kn < nk) {
                int sn = s + 2; if (sn >= MG_STAGES) sn -= MG_STAGES;
                load_tiles(sn, kn * 64);
            }
            cp_commit();
        }
        const unsigned abase = sb + s * MG_ASTG;
        const unsigned bbase = sb + MG_STAGES * MG_ASTG + s * MG_BSTG;

#pragma unroll
        for (int ks = 0; ks < 4; ks++) {
            uint32_t a[4][4], b[2][4];
#pragma unroll
            for (int mi = 0; mi < 4; mi++) {
                int row = wm * 64 + mi * 16 + (lane & 15);
                int kch = ks * 2 + (lane >> 4);
                ldsm4(a[mi][0], a[mi][1], a[mi][2], a[mi][3],
                      abase + row * 128 + ((kch ^ (row & 7)) << 4));
            }
#pragma unroll
            for (int pj = 0; pj < 2; pj++) {
                int kk = ks * 16 + (lane & 15);
                int nch = wn * 4 + pj * 2 + (lane >> 4);
                ldsm4t(b[pj][0], b[pj][1], b[pj][2], b[pj][3],
                       bbase + kk * 256 + ((nch ^ (kk & 7)) << 4));
            }
#pragma unroll
            for (int mi = 0; mi < 4; mi++)
#pragma unroll
                for (int nj = 0; nj < 4; nj++)
                    mma16816(d[mi][nj][0], d[mi][nj][1], d[mi][nj][2], d[mi][nj][3],
                             a[mi][0], a[mi][1], a[mi][2], a[mi][3],
                             b[nj >> 1][(nj & 1) * 2], b[nj >> 1][(nj & 1) * 2 + 1]);
        }
        if (++s == MG_STAGES) s = 0;
    }
    __syncthreads();

    // ---- staging (stride 129) ----
    const int qr = lane >> 2, qc = (lane & 3) * 2;
#pragma unroll
    for (int mi = 0; mi < 4; mi++) {
#pragma unroll
        for (int nj = 0; nj < 4; nj++) {
            int r0 = wm * 64 + mi * 16 + qr;
            int c0 = wn * 32 + nj * 8 + qc;
            stg[r0 * 129 + c0]           = d[mi][nj][0];
            stg[r0 * 129 + c0 + 1]       = d[mi][nj][1];
            stg[(r0 + 8) * 129 + c0]     = d[mi][nj][2];
            stg[(r0 + 8) * 129 + c0 + 1] = d[mi][nj][3];
        }
    }
    __syncthreads();

    const int gi0 = blockIdx.y * 128;
    const int gj0 = blockIdx.x * 128;

#pragma unroll
    for (int it = 0; it < 32; it++) {
        int idx = t + it * 256;
        int rr = idx >> 6;
        int c2 = (idx & 63) * 2;
        int gi = gi0 + rr, gj = gj0 + c2;
        float a0 = stg[rr * 129 + c2];
        float a1 = stg[rr * 129 + c2 + 1];

        if (EPI == 6) {
            int which = gj / HH;
            int col = gj - which * HH;
            float f = (which == 0) ? oscale : 1.f;
            float v0 = (a0 + bias[gj]) * f;
            float v1 = (a1 + bias[gj + 1]) * f;
            int bb = gi >> 9, ss2 = gi & 511, hhh = col >> 6, dd = col & 63;
            *reinterpret_cast<__half2*>(
                &outH[(size_t)which * QKV_STRIDE +
                      (((size_t)(bb * NH_ + hhh) * SS + ss2) << 6) + dd]) =
                __floats2half2_rn(v0, v1);
        } else if (EPI == 3) {
            float* dst = &outF[(size_t)gi * N + gj];
            float2 old = *reinterpret_cast<float2*>(dst);
            old.x += a0 + bias[gj];
            old.y += a1 + bias[gj + 1];
            *reinterpret_cast<float2*>(dst) = old;
        } else { // EPI == 4
            float x0 = a0 + bias[gj];
            float x1 = a1 + bias[gj + 1];
            float g0 = 0.5f * x0 * (1.f + erff(x0 * 0.70710678118654752f));
            float g1 = 0.5f * x1 * (1.f + erff(x1 * 0.70710678118654752f));
            *reinterpret_cast<__half2*>(&outH[(size_t)gi * N + gj]) =
                __floats2half2_rn(g0, g1);
        }
    }
}

// ---------------- host ----------------
extern "C" void kernel_launch(void* const* d_in, const int* in_sizes, int n_in,
                              void* d_out, int out_size)
{
    const float* x         = (const float*)d_in[0];
    const float* attn_bias = (const float*)d_in[1];
    const float* ln1_g = (const float*)d_in[2];
    const float* ln1_b = (const float*)d_in[3];
    const float* wq = (const float*)d_in[4];
    const float* bq = (const float*)d_in[5];
    const float* wk = (const float*)d_in[6];
    const float* bk = (const float*)d_in[7];
    const float* wv = (const float*)d_in[8];
    const float* bv = (const float*)d_in[9];
    const float* wo = (const float*)d_in[10];
    const float* bo = (const float*)d_in[11];
    const float* ln2_g = (const float*)d_in[12];
    const float* ln2_b = (const float*)d_in[13];
    const float* w1 = (const float*)d_in[14];
    const float* b1 = (const float*)d_in[15];
    const float* w2 = (const float*)d_in[16];
    const float* b2 = (const float*)d_in[17];
    const float* fln_g = (const float*)d_in[18];
    const float* fln_b = (const float*)d_in[19];
    float* out = (float*)d_out;

    void* pv_ = nullptr;
    cudaGetSymbolAddress(&pv_, g_h);      float*  p_h    = (float*)pv_;
    cudaGetSymbolAddress(&pv_, g_y);      __half* p_y    = (__half*)pv_;
    cudaGetSymbolAddress(&pv_, g_qkv);    __half* p_qkv  = (__half*)pv_;
    cudaGetSymbolAddress(&pv_, g_attn);   __half* p_attn = (__half*)pv_;
    cudaGetSymbolAddress(&pv_, g_ff);     __half* p_ff   = (__half*)pv_;
    cudaGetSymbolAddress(&pv_, g_bias16); __half* p_b16  = (__half*)pv_;
    cudaGetSymbolAddress(&pv_, g_w16);    __half* p_w16  = (__half*)pv_;
    cudaGetSymbolAddress(&pv_, g_bqkv);   float*  p_bqkv = (float*)pv_;

    __half* wqkv16 = p_w16 + OFF_QKV;
    __half* wo16   = p_w16 + OFF_WO;
    __half* w116   = p_w16 + OFF_W1;
    __half* w216   = p_w16 + OFF_W2;

    cudaFuncSetAttribute(mgemm_kernel<6>, cudaFuncAttributeMaxDynamicSharedMemorySize, MG_DSM);
    cudaFuncSetAttribute(mgemm_kernel<3>, cudaFuncAttributeMaxDynamicSharedMemorySize, MG_DSM);
    cudaFuncSetAttribute(mgemm_kernel<4>, cudaFuncAttributeMaxDynamicSharedMemorySize, MG_DSM);

    // init launches
    initw_kernel<<<(unsigned)((NPAIRS + 255) / 256), 256>>>(wq, wk, wv, wo, w1, w2, p_w16);
    inith_kernel<<<(unsigned)((NCOPY4 + 255) / 256), 256>>>(x, p_h);
    initb_kernel<<<(LL * NQKV + 255) / 256, 256>>>(bq, bk, bv, p_bqkv);
    initab_kernel<<<(unsigned)((NBIAS / 2 + 255) / 256), 256>>>(attn_bias, p_b16);

    const dim3 blk(256);
    const dim3 grid_qkv(NQKV / 128, MR / 128);          // 18 x 64
    const dim3 grid_proj(HH / 128, MR / 128);           // 6 x 64
    const dim3 grid_ff1(FF_ / 128, MR / 128);           // 24 x 64
    const dim3 grid_fa(SS / 128, BB * NH_);
    const unsigned ln_blocks = MR / 8;                  // 1024

    for (int l = 0; l < LL; l++) {
        ln_kernel<<<ln_blocks, blk>>>(p_h, ln1_g + l * HH, ln1_b + l * HH, p_y, nullptr);
        mgemm_kernel<6><<<grid_qkv, blk, MG_DSM>>>(p_y, wqkv16 + (size_t)l * HH * NQKV,
                                                   p_bqkv + (size_t)l * NQKV,
                                                   nullptr, p_qkv, HH, NQKV, SCALE_Q);
        flash_kernel<<<grid_fa, blk>>>(p_qkv, p_qkv + QKV_STRIDE, p_qkv + 2 * QKV_STRIDE,
                                       p_b16, p_attn);
        mgemm_kernel<3><<<grid_proj, blk, MG_DSM>>>(p_attn, wo16 + (size_t)l * HHxHH, bo + l * HH,
                                                    p_h, nullptr, HH, HH, 1.f);
        ln_kernel<<<ln_blocks, blk>>>(p_h, ln2_g + l * HH, ln2_b + l * HH, p_y, nullptr);
        mgemm_kernel<4><<<grid_ff1, blk, MG_DSM>>>(p_y, w116 + (size_t)l * HHxFF, b1 + l * FF_,
                                                   nullptr, p_ff, HH, FF_, 1.f);
        mgemm_kernel<3><<<grid_proj, blk, MG_DSM>>>(p_ff, w216 + (size_t)l * HHxFF, b2 + l * HH,
                                                    p_h, nullptr, FF_, HH, 1.f);
    }
    ln_kernel<<<ln_blocks, blk>>>(p_h, fln_g, fln_b, nullptr, out);
}